// round 2
// baseline (speedup 1.0000x reference)
#include <cuda_runtime.h>
#include <cstdint>
#include <math.h>

#define S_LEN   2048
#define D_MODEL 1024
#define N_HEADS 16
#define D_K     64
#define IDX_D   256      // IDX_HEADS * IDX_DIM = 4*64
#define MAXB    2

// ---------------- scratch (static device globals; no allocation) ----------------
__device__ float    g_qkv [MAXB * (size_t)S_LEN * 3 * D_MODEL];   // [B,S,3,H,64]
__device__ float    g_iq  [MAXB * (size_t)S_LEN * IDX_D];
__device__ float    g_ik  [MAXB * (size_t)S_LEN * IDX_D];
__device__ unsigned g_mask[MAXB * (size_t)S_LEN * (S_LEN / 32)];  // allowed-key bitmap
__device__ float    g_attn[MAXB * (size_t)S_LEN * D_MODEL];       // [B,S,H*64]

// ---------------- SGEMM: C[M,N] = A[M,K] @ B[K,N], all row-major fp32 ----------
// 128x128 block tile, K-step 8, 256 threads, 8x8 register micro-tile,
// double-buffered shared. Requires M%128==0, N%128==0, K%8==0.
__global__ __launch_bounds__(256) void sgemm_nn(const float* __restrict__ A,
                                                const float* __restrict__ B,
                                                float* __restrict__ C,
                                                int M, int N, int K)
{
    __shared__ float As[2][8][128];   // transposed: As[k][m]
    __shared__ float Bs[2][8][128];   // Bs[k][n]

    const int tid = threadIdx.x;
    const int bx = blockIdx.x, by = blockIdx.y;
    const int tx = tid & 15, ty = tid >> 4;

    const int arow = tid >> 1, ak = (tid & 1) * 4;       // A: 128 rows x 8 k
    const int brow = tid >> 5, bcol = (tid & 31) * 4;    // B: 8 rows x 128 n

    const float* Ag = A + (size_t)(by * 128 + arow) * K + ak;
    const float* Bg = B + (size_t)brow * N + bx * 128 + bcol;

    float4 af = *(const float4*)Ag;
    float4 bf = *(const float4*)Bg;
    As[0][ak + 0][arow] = af.x;
    As[0][ak + 1][arow] = af.y;
    As[0][ak + 2][arow] = af.z;
    As[0][ak + 3][arow] = af.w;
    *(float4*)&Bs[0][brow][bcol] = bf;
    __syncthreads();

    float acc[8][8];
#pragma unroll
    for (int i = 0; i < 8; i++)
#pragma unroll
        for (int j = 0; j < 8; j++) acc[i][j] = 0.f;

    int buf = 0;
    for (int k0 = 8; k0 <= K; k0 += 8) {
        const bool next = (k0 < K);
        if (next) {
            af = *(const float4*)(Ag + k0);
            bf = *(const float4*)(Bg + (size_t)k0 * N);
        }
#pragma unroll
        for (int kk = 0; kk < 8; kk++) {
            float a[8], b[8];
            *(float4*)&a[0] = *(const float4*)&As[buf][kk][ty * 8];
            *(float4*)&a[4] = *(const float4*)&As[buf][kk][ty * 8 + 4];
            *(float4*)&b[0] = *(const float4*)&Bs[buf][kk][tx * 8];
            *(float4*)&b[4] = *(const float4*)&Bs[buf][kk][tx * 8 + 4];
#pragma unroll
            for (int i = 0; i < 8; i++)
#pragma unroll
                for (int j = 0; j < 8; j++)
                    acc[i][j] += a[i] * b[j];
        }
        if (next) {
            buf ^= 1;
            As[buf][ak + 0][arow] = af.x;
            As[buf][ak + 1][arow] = af.y;
            As[buf][ak + 2][arow] = af.z;
            As[buf][ak + 3][arow] = af.w;
            *(float4*)&Bs[buf][brow][bcol] = bf;
            __syncthreads();
        }
    }

#pragma unroll
    for (int i = 0; i < 8; i++) {
        float* Crow = C + (size_t)(by * 128 + ty * 8 + i) * N + bx * 128 + tx * 8;
        *(float4*)Crow       = make_float4(acc[i][0], acc[i][1], acc[i][2], acc[i][3]);
        *(float4*)(Crow + 4) = make_float4(acc[i][4], acc[i][5], acc[i][6], acc[i][7]);
    }
}

// ---------------- RoPE (in-place on Q and K slices of qkv) ----------------------
__global__ void rope_kernel(float* __restrict__ qkv, int BS)
{
    int idx = blockIdx.x * blockDim.x + threadIdx.x;   // BS * 2 * 16 * 32
    if (idx >= BS * 1024) return;
    int i   = idx & 31;          // pair / frequency index
    int h   = (idx >> 5) & 15;
    int qk  = (idx >> 9) & 1;    // 0 = Q, 1 = K
    int tok = idx >> 10;         // b*S + s
    int s   = tok & (S_LEN - 1);

    float ex   = (float)(2 * i) * (1.0f / 64.0f);
    float freq = powf(10000.0f, -ex);
    float ang  = (float)s * freq;
    float sn, cs;
    sincosf(ang, &sn, &cs);

    size_t base = (size_t)tok * 3072 + (size_t)qk * 1024 + h * 64 + 2 * i;
    float x1 = qkv[base], x2 = qkv[base + 1];
    qkv[base]     = x1 * cs - x2 * sn;
    qkv[base + 1] = x1 * sn + x2 * cs;
}

// ---------------- index scores + radix-select threshold + bitmask ---------------
// One block per (b, q) row. Scores for k<=q computed on the fly (256-dim dots),
// converted to order-preserving uint keys, 4-pass MSB radix select finds the
// top_k-th largest; bitmap bit set iff k<=q and key >= threshold.
__global__ __launch_bounds__(256) void topk_mask_kernel(const float* __restrict__ iq,
                                                        const float* __restrict__ ik,
                                                        const int* __restrict__ topk_ptr,
                                                        unsigned* __restrict__ mask)
{
    __shared__ float    iqs[IDX_D];
    __shared__ unsigned keys[S_LEN];
    __shared__ unsigned hist[256];
    __shared__ unsigned s_prefix;
    __shared__ int      s_kr;

    const int tid = threadIdx.x;
    const int b = blockIdx.x >> 11;
    const int q = blockIdx.x & (S_LEN - 1);

    iqs[tid] = iq[(size_t)(b * S_LEN + q) * IDX_D + tid];
    __syncthreads();

    const float4* iq4 = (const float4*)iqs;
    for (int k = tid; k < S_LEN; k += 256) {
        unsigned key = 0u;
        if (k <= q) {
            const float4* ikr = (const float4*)(ik + (size_t)(b * S_LEN + k) * IDX_D);
            float acc = 0.f;
#pragma unroll 8
            for (int i = 0; i < 64; i++) {
                float4 a = iq4[i];
                float4 c = ikr[i];
                acc += a.x * c.x + a.y * c.y + a.z * c.z + a.w * c.w;
            }
            unsigned u = __float_as_uint(acc);
            key = (u & 0x80000000u) ? ~u : (u | 0x80000000u);   // order-preserving
        }
        keys[k] = key;   // padding (k>q) = 0, below any finite score's key
    }
    __syncthreads();

    int topk = topk_ptr ? topk_ptr[0] : 512;
    if (topk > S_LEN) topk = S_LEN;
    const int nvalid = q + 1;

    unsigned threshold = 0u;
    if (nvalid > topk) {
        if (tid == 0) { s_prefix = 0u; s_kr = topk; }
        for (int pass = 0; pass < 4; pass++) {
            const int shift = 24 - pass * 8;
            __syncthreads();
            hist[tid] = 0u;
            __syncthreads();
            const unsigned pref = s_prefix;
            for (int k = tid; k < S_LEN; k += 256) {
                unsigned key = keys[k];
                bool match = (pass == 0) || ((key >> (shift + 8)) == (pref >> (shift + 8)));
                if (match) atomicAdd(&hist[(key >> shift) & 255u], 1u);
            }
            __syncthreads();
            if (tid == 0) {
                int kr = s_kr;
                unsigned p = s_prefix;
                for (int d = 255; d >= 0; d--) {
                    int c = (int)hist[d];
                    if (kr <= c) { s_prefix = p | ((unsigned)d << shift); break; }
                    kr -= c;
                }
                s_kr = kr;
            }
        }
        __syncthreads();
        threshold = s_prefix;
    }

    if (tid < S_LEN / 32) {
        unsigned w = 0u;
        const int kb = tid * 32;
#pragma unroll
        for (int bit = 0; bit < 32; bit++) {
            int k = kb + bit;
            if (k <= q && keys[k] >= threshold && keys[k] != 0u) w |= (1u << bit);
        }
        mask[(size_t)(b * S_LEN + q) * (S_LEN / 32) + tid] = w;
    }
}

// ---------------- masked flash attention -----------------------------------
// Block: 64 queries x 1 head. 256 threads: r = tid/4 (row), qd = tid%4 (quarter).
// Thread owns keys j = qd + 4*jj (jj=0..15) -> conflict-free float4 smem reads.
__global__ __launch_bounds__(256) void flash_kernel(const float* __restrict__ qkv,
                                                    const unsigned* __restrict__ mask,
                                                    float* __restrict__ attn)
{
    __shared__ float Qs [64][68];
    __shared__ float KVs[64][68];

    const int tid = threadIdx.x;
    const int qt = blockIdx.x, h = blockIdx.y, b = blockIdx.z;
    const int r = tid >> 2, qd = tid & 3;
    const int qglob = qt * 64 + r;

#pragma unroll
    for (int i = 0; i < 4; i++) {
        int lin = tid + i * 256;
        int row = lin >> 4, c4 = lin & 15;
        *(float4*)&Qs[row][c4 * 4] =
            *(const float4*)(qkv + (size_t)(b * S_LEN + qt * 64 + row) * 3072 + h * 64 + c4 * 4);
    }

    float m_run = -1e30f, l = 0.f;
    float4 acc[16];
#pragma unroll
    for (int i = 0; i < 16; i++) acc[i] = make_float4(0.f, 0.f, 0.f, 0.f);

    const unsigned* mrow = mask + (size_t)(b * S_LEN + qglob) * (S_LEN / 32);

    for (int kt = 0; kt <= qt; kt++) {
        __syncthreads();
        // load K tile
#pragma unroll
        for (int i = 0; i < 4; i++) {
            int lin = tid + i * 256;
            int row = lin >> 4, c4 = lin & 15;
            *(float4*)&KVs[row][c4 * 4] =
                *(const float4*)(qkv + (size_t)(b * S_LEN + kt * 64 + row) * 3072 + 1024 + h * 64 + c4 * 4);
        }
        __syncthreads();

        float s[16];
#pragma unroll
        for (int jj = 0; jj < 16; jj++) s[jj] = 0.f;
#pragma unroll
        for (int d4 = 0; d4 < 16; d4++) {
            float4 qv = *(const float4*)&Qs[r][d4 * 4];
#pragma unroll
            for (int jj = 0; jj < 16; jj++) {
                float4 kv = *(const float4*)&KVs[qd + jj * 4][d4 * 4];
                s[jj] += qv.x * kv.x + qv.y * kv.y + qv.z * kv.z + qv.w * kv.w;
            }
        }

        const unsigned mw0 = mrow[kt * 2];
        const unsigned mw1 = mrow[kt * 2 + 1];
        float mx = -1e30f;
#pragma unroll
        for (int jj = 0; jj < 16; jj++) {
            int j = qd + jj * 4;
            int kg = kt * 64 + j;
            unsigned bit = ((j < 32 ? mw0 : mw1) >> (j & 31)) & 1u;
            float sv = s[jj] * 0.125f;
            if (kg > qglob || !bit) sv = -1e30f;
            s[jj] = sv;
            mx = fmaxf(mx, sv);
        }
        mx = fmaxf(mx, __shfl_xor_sync(0xffffffffu, mx, 1));
        mx = fmaxf(mx, __shfl_xor_sync(0xffffffffu, mx, 2));
        float m_new = fmaxf(m_run, mx);
        float corr = __expf(m_run - m_new);
        float ls = 0.f;
#pragma unroll
        for (int jj = 0; jj < 16; jj++) {
            float p = __expf(s[jj] - m_new);
            s[jj] = p;
            ls += p;
        }
        ls += __shfl_xor_sync(0xffffffffu, ls, 1);
        ls += __shfl_xor_sync(0xffffffffu, ls, 2);
        l = l * corr + ls;
        m_run = m_new;
#pragma unroll
        for (int i = 0; i < 16; i++) {
            acc[i].x *= corr; acc[i].y *= corr; acc[i].z *= corr; acc[i].w *= corr;
        }

        __syncthreads();
        // load V tile (reuse KVs)
#pragma unroll
        for (int i = 0; i < 4; i++) {
            int lin = tid + i * 256;
            int row = lin >> 4, c4 = lin & 15;
            *(float4*)&KVs[row][c4 * 4] =
                *(const float4*)(qkv + (size_t)(b * S_LEN + kt * 64 + row) * 3072 + 2048 + h * 64 + c4 * 4);
        }
        __syncthreads();
#pragma unroll
        for (int jj = 0; jj < 16; jj++) {
            float p = s[jj];
            int j = qd + jj * 4;
#pragma unroll
            for (int d4 = 0; d4 < 16; d4++) {
                float4 v = *(const float4*)&KVs[j][d4 * 4];
                acc[d4].x += p * v.x; acc[d4].y += p * v.y;
                acc[d4].z += p * v.z; acc[d4].w += p * v.w;
            }
        }
    }

    // combine the 4 quarter-lane partials of each row
#pragma unroll
    for (int i = 0; i < 16; i++) {
        acc[i].x += __shfl_xor_sync(0xffffffffu, acc[i].x, 1);
        acc[i].y += __shfl_xor_sync(0xffffffffu, acc[i].y, 1);
        acc[i].z += __shfl_xor_sync(0xffffffffu, acc[i].z, 1);
        acc[i].w += __shfl_xor_sync(0xffffffffu, acc[i].w, 1);
        acc[i].x += __shfl_xor_sync(0xffffffffu, acc[i].x, 2);
        acc[i].y += __shfl_xor_sync(0xffffffffu, acc[i].y, 2);
        acc[i].z += __shfl_xor_sync(0xffffffffu, acc[i].z, 2);
        acc[i].w += __shfl_xor_sync(0xffffffffu, acc[i].w, 2);
    }

    float inv_l = 1.0f / l;
#pragma unroll
    for (int t = 0; t < 4; t++) {
        int d4 = qd * 4 + t;
        float4 o = acc[d4];
        o.x *= inv_l; o.y *= inv_l; o.z *= inv_l; o.w *= inv_l;
        *(float4*)(attn + (size_t)(b * S_LEN + qglob) * D_MODEL + h * 64 + d4 * 4) = o;
    }
}

// ---------------- launcher ------------------------------------------------------
extern "C" void kernel_launch(void* const* d_in, const int* in_sizes, int n_in,
                              void* d_out, int out_size)
{
    // Identify inputs by element count (robust to metadata ordering).
    const float* x    = nullptr;
    const float* Wqkv = nullptr;
    const float* Wo   = nullptr;
    const float* Wiq  = nullptr;
    const float* Wik  = nullptr;
    const int*   topk = nullptr;
    for (int i = 0; i < n_in; i++) {
        int sz = in_sizes[i];
        if      (sz == D_MODEL * 3 * D_MODEL)       Wqkv = (const float*)d_in[i];
        else if (sz == D_MODEL * D_MODEL)           Wo   = (const float*)d_in[i];
        else if (sz == D_MODEL * IDX_D) { if (!Wiq) Wiq  = (const float*)d_in[i];
                                          else      Wik  = (const float*)d_in[i]; }
        else if (sz <= 4)                           topk = (const int*)d_in[i];
        else                                        x    = (const float*)d_in[i];
    }

    const int BS = out_size / D_MODEL;      // B * S
    const int Bn = BS / S_LEN;

    float *qkv, *iq, *ik, *attn; unsigned* mask;
    cudaGetSymbolAddress((void**)&qkv,  g_qkv);
    cudaGetSymbolAddress((void**)&iq,   g_iq);
    cudaGetSymbolAddress((void**)&ik,   g_ik);
    cudaGetSymbolAddress((void**)&mask, g_mask);
    cudaGetSymbolAddress((void**)&attn, g_attn);

    dim3 blk(256);
    sgemm_nn<<<dim3(3 * D_MODEL / 128, BS / 128), blk>>>(x, Wqkv, qkv, BS, 3 * D_MODEL, D_MODEL);
    sgemm_nn<<<dim3(IDX_D / 128, BS / 128), blk>>>(x, Wiq, iq, BS, IDX_D, D_MODEL);
    sgemm_nn<<<dim3(IDX_D / 128, BS / 128), blk>>>(x, Wik, ik, BS, IDX_D, D_MODEL);

    rope_kernel<<<(BS * 1024 + 255) / 256, 256>>>(qkv, BS);

    topk_mask_kernel<<<BS, 256>>>(iq, ik, topk, mask);

    flash_kernel<<<dim3(S_LEN / 64, N_HEADS, Bn), 256>>>(qkv, mask, attn);

    sgemm_nn<<<dim3(D_MODEL / 128, BS / 128), blk>>>(attn, Wo, (float*)d_out, BS, D_MODEL, D_MODEL);
}

// round 4
// speedup vs baseline: 1.1227x; 1.1227x over previous
#include <cuda_runtime.h>
#include <cuda_bf16.h>
#include <cstdint>
#include <math.h>

#define S_LEN   2048
#define D_MODEL 1024
#define N_HEADS 16
#define IDX_D   256
#define MAXB    2
#define BS_MAX  (MAXB * S_LEN)

typedef __nv_bfloat16 bf16;

// ---------------- scratch (static device globals; no allocation) ----------------
__device__ float    g_qkv [(size_t)BS_MAX * 3 * D_MODEL];
__device__ float    g_iq  [(size_t)BS_MAX * IDX_D];
__device__ float    g_ik  [(size_t)BS_MAX * IDX_D];
__device__ float    g_attn[(size_t)BS_MAX * D_MODEL];
__device__ unsigned g_mask[(size_t)BS_MAX * (S_LEN / 32)];

__device__ bf16 g_x3   [(size_t)BS_MAX * 3 * D_MODEL];
__device__ bf16 g_attn3[(size_t)BS_MAX * 3 * D_MODEL];
__device__ bf16 g_wqkv3[(size_t)(3 * D_MODEL) * 3 * D_MODEL];  // [N=3072][3K=3072]
__device__ bf16 g_wo3  [(size_t)D_MODEL * 3 * D_MODEL];

// ---------------- bf16x3 split conversions --------------------------------------
// A pattern per element: (hi, lo, hi);  B pattern: (hi, hi, lo).
// Sum over tripled K = hi*hi + lo*hi + hi*lo ~= fp32 product (error ~2^-18).
__global__ void split_a(const float* __restrict__ s, bf16* __restrict__ d, int n)
{
    int i = blockIdx.x * blockDim.x + threadIdx.x;
    if (i >= n) return;
    float v = s[i];
    bf16 h = __float2bfloat16(v);
    bf16 l = __float2bfloat16(v - __bfloat162float(h));
    d[3 * i] = h; d[3 * i + 1] = l; d[3 * i + 2] = h;
}

// W [K,N] row-major -> out [N, 3K] bf16 with B-pattern (transpose + split).
__global__ void split_bT(const float* __restrict__ W, bf16* __restrict__ out,
                         int K, int N)
{
    __shared__ float t[32][33];
    int n0 = blockIdx.x * 32, k0 = blockIdx.y * 32;
    int tx = threadIdx.x, ty = threadIdx.y;   // block (32,8)
    for (int i = ty; i < 32; i += 8)
        t[i][tx] = W[(size_t)(k0 + i) * N + n0 + tx];
    __syncthreads();
    for (int r = ty; r < 32; r += 8) {
        float v = t[tx][r];
        bf16 h = __float2bfloat16(v);
        bf16 l = __float2bfloat16(v - __bfloat162float(h));
        size_t o = (size_t)(n0 + r) * (3 * K) + 3 * (size_t)(k0 + tx);
        out[o] = h; out[o + 1] = h; out[o + 2] = l;
    }
}

// ---------------- tensor-core NT GEMM: C[M,N] = A[M,K] * B[N,K]^T ---------------
#define BMg 128
#define BNg 128
#define BKg 32

__device__ __forceinline__ void ldsm_x4(uint32_t* r, uint32_t a) {
    asm volatile("ldmatrix.sync.aligned.m8n8.x4.shared.b16 {%0,%1,%2,%3}, [%4];"
                 : "=r"(r[0]), "=r"(r[1]), "=r"(r[2]), "=r"(r[3]) : "r"(a));
}
__device__ __forceinline__ void ldsm_x2(uint32_t* r, uint32_t a) {
    asm volatile("ldmatrix.sync.aligned.m8n8.x2.shared.b16 {%0,%1}, [%2];"
                 : "=r"(r[0]), "=r"(r[1]) : "r"(a));
}
__device__ __forceinline__ void mma16816(float* c, const uint32_t* a, const uint32_t* b) {
    asm volatile("mma.sync.aligned.m16n8k16.row.col.f32.bf16.bf16.f32 "
                 "{%0,%1,%2,%3},{%4,%5,%6,%7},{%8,%9},{%0,%1,%2,%3};"
                 : "+f"(c[0]), "+f"(c[1]), "+f"(c[2]), "+f"(c[3])
                 : "r"(a[0]), "r"(a[1]), "r"(a[2]), "r"(a[3]), "r"(b[0]), "r"(b[1]));
}
#define CP16(sa, ga) asm volatile("cp.async.cg.shared.global [%0], [%1], 16;\n" :: "r"(sa), "l"(ga))
#define CPCOMMIT()   asm volatile("cp.async.commit_group;\n" ::: "memory")
#define CPWAIT0()    asm volatile("cp.async.wait_group 0;\n" ::: "memory")

__global__ __launch_bounds__(256) void mma_gemm(
    const bf16* __restrict__ A, const bf16* __restrict__ B, float* __restrict__ C,
    int M, int N, int K)
{
    const int bx = blockIdx.x, by = blockIdx.y;

    __shared__ bf16 As[2][BMg][40];
    __shared__ bf16 Bs[2][BNg][40];

    const int tid  = threadIdx.x;
    const int warp = tid >> 5, lane = tid & 31;
    const int wm = warp & 1, wn = warp >> 1;

    const uint32_t sA = (uint32_t)__cvta_generic_to_shared(&As[0][0][0]);
    const uint32_t sB = (uint32_t)__cvta_generic_to_shared(&Bs[0][0][0]);
    const uint32_t BUFB = BMg * 40 * 2;

    const int ldrow = tid >> 2;
    const int ldch  = (tid & 3) * 8;

    float acc[4][4][4];
#pragma unroll
    for (int i = 0; i < 4; i++)
#pragma unroll
        for (int j = 0; j < 4; j++)
#pragma unroll
            for (int t = 0; t < 4; t++) acc[i][j][t] = 0.f;

#pragma unroll
    for (int h = 0; h < 2; h++) {
        int row = ldrow + h * 64;
        CP16(sA + (uint32_t)(row * 40 + ldch) * 2,
             A + (size_t)(by * BMg + row) * K + ldch);
        CP16(sB + (uint32_t)(row * 40 + ldch) * 2,
             B + (size_t)(bx * BNg + row) * K + ldch);
    }
    CPCOMMIT();
    CPWAIT0();
    __syncthreads();

    const int KT = K / BKg;
    int buf = 0;
    for (int kt = 0; kt < KT; kt++) {
        if (kt + 1 < KT) {
            int k0 = (kt + 1) * BKg;
#pragma unroll
            for (int h = 0; h < 2; h++) {
                int row = ldrow + h * 64;
                CP16(sA + (buf ^ 1) * BUFB + (uint32_t)(row * 40 + ldch) * 2,
                     A + (size_t)(by * BMg + row) * K + k0 + ldch);
                CP16(sB + (buf ^ 1) * BUFB + (uint32_t)(row * 40 + ldch) * 2,
                     B + (size_t)(bx * BNg + row) * K + k0 + ldch);
            }
            CPCOMMIT();
        }

#pragma unroll
        for (int ks = 0; ks < BKg; ks += 16) {
            uint32_t af[4][4], bfr[4][2];
            const int arow = wm * 64 + (lane & 15);
            const int acol = ks + ((lane >> 4) << 3);
#pragma unroll
            for (int mt = 0; mt < 4; mt++)
                ldsm_x4(af[mt], sA + buf * BUFB +
                        (uint32_t)((arow + mt * 16) * 40 + acol) * 2);
            const int brow = wn * 32 + (lane & 7);
            const int bcol = ks + (((lane >> 3) & 1) << 3);
#pragma unroll
            for (int nt = 0; nt < 4; nt++)
                ldsm_x2(bfr[nt], sB + buf * BUFB +
                        (uint32_t)((brow + nt * 8) * 40 + bcol) * 2);
#pragma unroll
            for (int mt = 0; mt < 4; mt++)
#pragma unroll
                for (int nt = 0; nt < 4; nt++)
                    mma16816(acc[mt][nt], af[mt], bfr[nt]);
        }

        if (kt + 1 < KT) {
            CPWAIT0();
            __syncthreads();
            buf ^= 1;
        }
    }

#pragma unroll
    for (int mt = 0; mt < 4; mt++) {
#pragma unroll
        for (int nt = 0; nt < 4; nt++) {
            int row = by * BMg + wm * 64 + mt * 16 + (lane >> 2);
            int col = bx * BNg + wn * 32 + nt * 8 + (lane & 3) * 2;
            float2 v0 = make_float2(acc[mt][nt][0], acc[mt][nt][1]);
            float2 v1 = make_float2(acc[mt][nt][2], acc[mt][nt][3]);
            *(float2*)&C[(size_t)row * N + col]       = v0;
            *(float2*)&C[(size_t)(row + 8) * N + col] = v1;
        }
    }
}

// ---------------- fp32 SGEMM (exact; used for the selection path) ---------------
__global__ __launch_bounds__(256) void sgemm_nn(const float* __restrict__ A,
                                                const float* __restrict__ B,
                                                float* __restrict__ C,
                                                int M, int N, int K)
{
    __shared__ float As[2][8][128];
    __shared__ float Bs[2][8][128];

    const int tid = threadIdx.x;
    const int bx = blockIdx.x, by = blockIdx.y;
    const int tx = tid & 15, ty = tid >> 4;

    const int arow = tid >> 1, ak = (tid & 1) * 4;
    const int brow = tid >> 5, bcol = (tid & 31) * 4;

    const float* Ag = A + (size_t)(by * 128 + arow) * K + ak;
    const float* Bg = B + (size_t)brow * N + bx * 128 + bcol;

    float4 af = *(const float4*)Ag;
    float4 bf = *(const float4*)Bg;
    As[0][ak + 0][arow] = af.x;
    As[0][ak + 1][arow] = af.y;
    As[0][ak + 2][arow] = af.z;
    As[0][ak + 3][arow] = af.w;
    *(float4*)&Bs[0][brow][bcol] = bf;
    __syncthreads();

    float acc[8][8];
#pragma unroll
    for (int i = 0; i < 8; i++)
#pragma unroll
        for (int j = 0; j < 8; j++) acc[i][j] = 0.f;

    int buf = 0;
    for (int k0 = 8; k0 <= K; k0 += 8) {
        const bool next = (k0 < K);
        if (next) {
            af = *(const float4*)(Ag + k0);
            bf = *(const float4*)(Bg + (size_t)k0 * N);
        }
#pragma unroll
        for (int kk = 0; kk < 8; kk++) {
            float a[8], b[8];
            *(float4*)&a[0] = *(const float4*)&As[buf][kk][ty * 8];
            *(float4*)&a[4] = *(const float4*)&As[buf][kk][ty * 8 + 4];
            *(float4*)&b[0] = *(const float4*)&Bs[buf][kk][tx * 8];
            *(float4*)&b[4] = *(const float4*)&Bs[buf][kk][tx * 8 + 4];
#pragma unroll
            for (int i = 0; i < 8; i++)
#pragma unroll
                for (int j = 0; j < 8; j++)
                    acc[i][j] += a[i] * b[j];
        }
        if (next) {
            buf ^= 1;
            As[buf][ak + 0][arow] = af.x;
            As[buf][ak + 1][arow] = af.y;
            As[buf][ak + 2][arow] = af.z;
            As[buf][ak + 3][arow] = af.w;
            *(float4*)&Bs[buf][brow][bcol] = bf;
            __syncthreads();
        }
    }

#pragma unroll
    for (int i = 0; i < 8; i++) {
        float* Crow = C + (size_t)(by * 128 + ty * 8 + i) * N + bx * 128 + tx * 8;
        *(float4*)Crow       = make_float4(acc[i][0], acc[i][1], acc[i][2], acc[i][3]);
        *(float4*)(Crow + 4) = make_float4(acc[i][4], acc[i][5], acc[i][6], acc[i][7]);
    }
}

// ---------------- RoPE (in-place on Q and K slices of qkv) ----------------------
__global__ void rope_kernel(float* __restrict__ qkv, int BS)
{
    int idx = blockIdx.x * blockDim.x + threadIdx.x;
    if (idx >= BS * 1024) return;
    int i   = idx & 31;
    int h   = (idx >> 5) & 15;
    int qk  = (idx >> 9) & 1;
    int tok = idx >> 10;
    int s   = tok & (S_LEN - 1);

    float ex   = (float)(2 * i) * (1.0f / 64.0f);
    float freq = powf(10000.0f, -ex);
    float ang  = (float)s * freq;
    float sn, cs;
    sincosf(ang, &sn, &cs);

    size_t base = (size_t)tok * 3072 + (size_t)qk * 1024 + h * 64 + 2 * i;
    float x1 = qkv[base], x2 = qkv[base + 1];
    qkv[base]     = x1 * cs - x2 * sn;
    qkv[base + 1] = x1 * sn + x2 * cs;
}

// ---------------- exact index scores + radix-select threshold + bitmask ---------
__global__ __launch_bounds__(256) void topk_mask_kernel(const float* __restrict__ iq,
                                                        const float* __restrict__ ik,
                                                        const int* __restrict__ topk_ptr,
                                                        unsigned* __restrict__ mask)
{
    __shared__ float    iqs[IDX_D];
    __shared__ unsigned keys[S_LEN];
    __shared__ unsigned hist[256];
    __shared__ unsigned s_prefix;
    __shared__ int      s_kr;

    const int tid = threadIdx.x;
    const int b = blockIdx.x >> 11;
    const int q = blockIdx.x & (S_LEN - 1);

    iqs[tid] = iq[(size_t)(b * S_LEN + q) * IDX_D + tid];
    __syncthreads();

    const float4* iq4 = (const float4*)iqs;
    for (int k = tid; k < S_LEN; k += 256) {
        unsigned key = 0u;
        if (k <= q) {
            const float4* ikr = (const float4*)(ik + (size_t)(b * S_LEN + k) * IDX_D);
            float acc = 0.f;
#pragma unroll 8
            for (int i = 0; i < 64; i++) {
                float4 a = iq4[i];
                float4 c = ikr[i];
                acc += a.x * c.x + a.y * c.y + a.z * c.z + a.w * c.w;
            }
            unsigned u = __float_as_uint(acc);
            key = (u & 0x80000000u) ? ~u : (u | 0x80000000u);
        }
        keys[k] = key;
    }
    __syncthreads();

    int topk = topk_ptr ? topk_ptr[0] : 512;
    if (topk > S_LEN) topk = S_LEN;
    const int nvalid = q + 1;

    unsigned threshold = 0u;
    if (nvalid > topk) {
        if (tid == 0) { s_prefix = 0u; s_kr = topk; }
        for (int pass = 0; pass < 4; pass++) {
            const int shift = 24 - pass * 8;
            __syncthreads();
            hist[tid] = 0u;
            __syncthreads();
            const unsigned pref = s_prefix;
            for (int k = tid; k < S_LEN; k += 256) {
                unsigned key = keys[k];
                bool match = (pass == 0) || ((key >> (shift + 8)) == (pref >> (shift + 8)));
                if (match) atomicAdd(&hist[(key >> shift) & 255u], 1u);
            }
            __syncthreads();
            if (tid == 0) {
                int kr = s_kr;
                unsigned p = s_prefix;
                for (int d = 255; d >= 0; d--) {
                    int c = (int)hist[d];
                    if (kr <= c) { s_prefix = p | ((unsigned)d << shift); break; }
                    kr -= c;
                }
                s_kr = kr;
            }
        }
        __syncthreads();
        threshold = s_prefix;
    }

    if (tid < S_LEN / 32) {
        unsigned w = 0u;
        const int kb = tid * 32;
#pragma unroll
        for (int bit = 0; bit < 32; bit++) {
            int k = kb + bit;
            if (k <= q && keys[k] >= threshold && keys[k] != 0u) w |= (1u << bit);
        }
        mask[(size_t)(b * S_LEN + q) * (S_LEN / 32) + tid] = w;
    }
}

// ---------------- masked flash attention (fp32, verified) -----------------------
__global__ __launch_bounds__(256) void flash_kernel(const float* __restrict__ qkv,
                                                    const unsigned* __restrict__ mask,
                                                    float* __restrict__ attn)
{
    __shared__ float Qs [64][68];
    __shared__ float KVs[64][68];

    const int tid = threadIdx.x;
    const int qt = blockIdx.x, h = blockIdx.y, b = blockIdx.z;
    const int r = tid >> 2, qd = tid & 3;
    const int qglob = qt * 64 + r;

#pragma unroll
    for (int i = 0; i < 4; i++) {
        int lin = tid + i * 256;
        int row = lin >> 4, c4 = lin & 15;
        *(float4*)&Qs[row][c4 * 4] =
            *(const float4*)(qkv + (size_t)(b * S_LEN + qt * 64 + row) * 3072 + h * 64 + c4 * 4);
    }

    float m_run = -1e30f, l = 0.f;
    float4 acc[16];
#pragma unroll
    for (int i = 0; i < 16; i++) acc[i] = make_float4(0.f, 0.f, 0.f, 0.f);

    const unsigned* mrow = mask + (size_t)(b * S_LEN + qglob) * (S_LEN / 32);

    for (int kt = 0; kt <= qt; kt++) {
        __syncthreads();
#pragma unroll
        for (int i = 0; i < 4; i++) {
            int lin = tid + i * 256;
            int row = lin >> 4, c4 = lin & 15;
            *(float4*)&KVs[row][c4 * 4] =
                *(const float4*)(qkv + (size_t)(b * S_LEN + kt * 64 + row) * 3072 + 1024 + h * 64 + c4 * 4);
        }
        __syncthreads();

        float s[16];
#pragma unroll
        for (int jj = 0; jj < 16; jj++) s[jj] = 0.f;
#pragma unroll
        for (int d4 = 0; d4 < 16; d4++) {
            float4 qv = *(const float4*)&Qs[r][d4 * 4];
#pragma unroll
            for (int jj = 0; jj < 16; jj++) {
                float4 kv = *(const float4*)&KVs[qd + jj * 4][d4 * 4];
                s[jj] += qv.x * kv.x + qv.y * kv.y + qv.z * kv.z + qv.w * kv.w;
            }
        }

        const unsigned mw0 = mrow[kt * 2];
        const unsigned mw1 = mrow[kt * 2 + 1];
        float mx = -1e30f;
#pragma unroll
        for (int jj = 0; jj < 16; jj++) {
            int j = qd + jj * 4;
            int kg = kt * 64 + j;
            unsigned bit = ((j < 32 ? mw0 : mw1) >> (j & 31)) & 1u;
            float sv = s[jj] * 0.125f;
            if (kg > qglob || !bit) sv = -1e30f;
            s[jj] = sv;
            mx = fmaxf(mx, sv);
        }
        mx = fmaxf(mx, __shfl_xor_sync(0xffffffffu, mx, 1));
        mx = fmaxf(mx, __shfl_xor_sync(0xffffffffu, mx, 2));
        float m_new = fmaxf(m_run, mx);
        float corr = __expf(m_run - m_new);
        float ls = 0.f;
#pragma unroll
        for (int jj = 0; jj < 16; jj++) {
            float p = __expf(s[jj] - m_new);
            s[jj] = p;
            ls += p;
        }
        ls += __shfl_xor_sync(0xffffffffu, ls, 1);
        ls += __shfl_xor_sync(0xffffffffu, ls, 2);
        l = l * corr + ls;
        m_run = m_new;
#pragma unroll
        for (int i = 0; i < 16; i++) {
            acc[i].x *= corr; acc[i].y *= corr; acc[i].z *= corr; acc[i].w *= corr;
        }

        __syncthreads();
#pragma unroll
        for (int i = 0; i < 4; i++) {
            int lin = tid + i * 256;
            int row = lin >> 4, c4 = lin & 15;
            *(float4*)&KVs[row][c4 * 4] =
                *(const float4*)(qkv + (size_t)(b * S_LEN + kt * 64 + row) * 3072 + 2048 + h * 64 + c4 * 4);
        }
        __syncthreads();
#pragma unroll
        for (int jj = 0; jj < 16; jj++) {
            float p = s[jj];
            int j = qd + jj * 4;
#pragma unroll
            for (int d4 = 0; d4 < 16; d4++) {
                float4 v = *(const float4*)&KVs[j][d4 * 4];
                acc[d4].x += p * v.x; acc[d4].y += p * v.y;
                acc[d4].z += p * v.z; acc[d4].w += p * v.w;
            }
        }
    }

#pragma unroll
    for (int i = 0; i < 16; i++) {
        acc[i].x += __shfl_xor_sync(0xffffffffu, acc[i].x, 1);
        acc[i].y += __shfl_xor_sync(0xffffffffu, acc[i].y, 1);
        acc[i].z += __shfl_xor_sync(0xffffffffu, acc[i].z, 1);
        acc[i].w += __shfl_xor_sync(0xffffffffu, acc[i].w, 1);
        acc[i].x += __shfl_xor_sync(0xffffffffu, acc[i].x, 2);
        acc[i].y += __shfl_xor_sync(0xffffffffu, acc[i].y, 2);
        acc[i].z += __shfl_xor_sync(0xffffffffu, acc[i].z, 2);
        acc[i].w += __shfl_xor_sync(0xffffffffu, acc[i].w, 2);
    }

    float inv_l = 1.0f / l;
#pragma unroll
    for (int t = 0; t < 4; t++) {
        int d4 = qd * 4 + t;
        float4 o = acc[d4];
        o.x *= inv_l; o.y *= inv_l; o.z *= inv_l; o.w *= inv_l;
        *(float4*)(attn + (size_t)(b * S_LEN + qglob) * D_MODEL + h * 64 + d4 * 4) = o;
    }
}

// ---------------- launcher ------------------------------------------------------
extern "C" void kernel_launch(void* const* d_in, const int* in_sizes, int n_in,
                              void* d_out, int out_size)
{
    const float* x    = nullptr;
    const float* Wqkv = nullptr;
    const float* Wo   = nullptr;
    const float* Wiq  = nullptr;
    const float* Wik  = nullptr;
    const int*   topk = nullptr;
    for (int i = 0; i < n_in; i++) {
        int sz = in_sizes[i];
        if      (sz == D_MODEL * 3 * D_MODEL)       Wqkv = (const float*)d_in[i];
        else if (sz == D_MODEL * D_MODEL)           Wo   = (const float*)d_in[i];
        else if (sz == D_MODEL * IDX_D) { if (!Wiq) Wiq  = (const float*)d_in[i];
                                          else      Wik  = (const float*)d_in[i]; }
        else if (sz <= 4)                           topk = (const int*)d_in[i];
        else                                        x    = (const float*)d_in[i];
    }

    const int BS = out_size / D_MODEL;
    const int Bn = BS / S_LEN;

    float *qkv, *iq, *ik, *attn; unsigned* mask;
    bf16 *x3, *attn3, *wqkv3, *wo3;
    cudaGetSymbolAddress((void**)&qkv,   g_qkv);
    cudaGetSymbolAddress((void**)&iq,    g_iq);
    cudaGetSymbolAddress((void**)&ik,    g_ik);
    cudaGetSymbolAddress((void**)&attn,  g_attn);
    cudaGetSymbolAddress((void**)&mask,  g_mask);
    cudaGetSymbolAddress((void**)&x3,    g_x3);
    cudaGetSymbolAddress((void**)&attn3, g_attn3);
    cudaGetSymbolAddress((void**)&wqkv3, g_wqkv3);
    cudaGetSymbolAddress((void**)&wo3,   g_wo3);

    const int K3 = 3 * D_MODEL;

    // splits for the tensor-core path (QKV and W_o only)
    split_a<<<(BS * D_MODEL + 255) / 256, 256>>>(x, x3, BS * D_MODEL);
    {
        dim3 blk(32, 8);
        split_bT<<<dim3(3 * D_MODEL / 32, D_MODEL / 32), blk>>>(Wqkv, wqkv3, D_MODEL, 3 * D_MODEL);
        split_bT<<<dim3(D_MODEL / 32, D_MODEL / 32), blk>>>(Wo, wo3, D_MODEL, D_MODEL);
    }

    // QKV projection on tensor cores (smooth path)
    mma_gemm<<<dim3(3 * D_MODEL / BNg, BS / BMg), 256>>>(x3, wqkv3, qkv, BS, 3 * D_MODEL, K3);

    // selection path: exact fp32 projections
    sgemm_nn<<<dim3(IDX_D / 128, BS / 128), 256>>>(x, Wiq, iq, BS, IDX_D, D_MODEL);
    sgemm_nn<<<dim3(IDX_D / 128, BS / 128), 256>>>(x, Wik, ik, BS, IDX_D, D_MODEL);

    rope_kernel<<<(BS * 1024 + 255) / 256, 256>>>(qkv, BS);

    // exact fp32 scores + radix select (matches reference selection)
    topk_mask_kernel<<<BS, 256>>>(iq, ik, topk, mask);

    flash_kernel<<<dim3(S_LEN / 64, N_HEADS, Bn), 256>>>(qkv, mask, attn);

    // output projection on tensor cores (smooth path)
    split_a<<<(BS * D_MODEL + 255) / 256, 256>>>(attn, attn3, BS * D_MODEL);
    mma_gemm<<<dim3(D_MODEL / BNg, BS / BMg), 256>>>(attn3, wo3, (float*)d_out, BS, D_MODEL, K3);
}

// round 7
// speedup vs baseline: 1.5333x; 1.3657x over previous
#include <cuda_runtime.h>
#include <cuda_bf16.h>
#include <cstdint>
#include <math.h>

#define S_LEN   2048
#define D_MODEL 1024
#define N_HEADS 16
#define IDX_D   256
#define MAXB    2
#define BS_MAX  (MAXB * S_LEN)

typedef __nv_bfloat16 bf16;

// ---------------- scratch (static device globals; no allocation) ----------------
__device__ float    g_qkv [(size_t)BS_MAX * 3 * D_MODEL];
__device__ float    g_iq  [(size_t)BS_MAX * IDX_D];
__device__ float    g_ik  [(size_t)BS_MAX * IDX_D];
__device__ float    g_attn[(size_t)BS_MAX * D_MODEL];
__device__ unsigned g_mask[(size_t)BS_MAX * (S_LEN / 32)];

__device__ __align__(16) bf16 g_x3   [(size_t)BS_MAX * 3 * D_MODEL];
__device__ __align__(16) bf16 g_attn3[(size_t)BS_MAX * 3 * D_MODEL];
__device__ __align__(16) bf16 g_wqkv3[(size_t)(3 * D_MODEL) * 3 * D_MODEL];
__device__ __align__(16) bf16 g_wo3  [(size_t)D_MODEL * 3 * D_MODEL];

// flash operands (x3)
__device__ __align__(16) bf16 g_q3 [(size_t)MAXB * N_HEADS * S_LEN * 192];
__device__ __align__(16) bf16 g_k3 [(size_t)MAXB * N_HEADS * S_LEN * 192];
__device__ __align__(16) bf16 g_vt3[(size_t)MAXB * N_HEADS * 64 * 3 * S_LEN];

// ---------------- bf16x3 split conversions --------------------------------------
// A pattern (h,l,h); B pattern (h,h,l): sum over tripled K = hh + lh + hl.
__global__ void split_a(const float* __restrict__ s, bf16* __restrict__ d, int n)
{
    int i = blockIdx.x * blockDim.x + threadIdx.x;
    if (i >= n) return;
    float v = s[i];
    bf16 h = __float2bfloat16(v);
    bf16 l = __float2bfloat16(v - __bfloat162float(h));
    d[3 * i] = h; d[3 * i + 1] = l; d[3 * i + 2] = h;
}

// W [K,N] row-major -> out [N, 3K] bf16 with B-pattern (transpose + split).
__global__ void split_bT(const float* __restrict__ W, bf16* __restrict__ out,
                         int K, int N)
{
    __shared__ float t[32][33];
    int n0 = blockIdx.x * 32, k0 = blockIdx.y * 32;
    int tx = threadIdx.x, ty = threadIdx.y;   // block (32,8)
    for (int i = ty; i < 32; i += 8)
        t[i][tx] = W[(size_t)(k0 + i) * N + n0 + tx];
    __syncthreads();
    for (int r = ty; r < 32; r += 8) {
        float v = t[tx][r];
        bf16 h = __float2bfloat16(v);
        bf16 l = __float2bfloat16(v - __bfloat162float(h));
        size_t o = (size_t)(n0 + r) * (3 * K) + 3 * (size_t)(k0 + tx);
        out[o] = h; out[o + 1] = h; out[o + 2] = l;
    }
}

// ---------------- tensor-core NT GEMM: C[M,N] = A[M,K] * B[N,K]^T ---------------
#define BMg 128
#define BNg 128
#define BKg 32

__device__ __forceinline__ void ldsm_x4(uint32_t* r, uint32_t a) {
    asm volatile("ldmatrix.sync.aligned.m8n8.x4.shared.b16 {%0,%1,%2,%3}, [%4];"
                 : "=r"(r[0]), "=r"(r[1]), "=r"(r[2]), "=r"(r[3]) : "r"(a));
}
__device__ __forceinline__ void ldsm_x2(uint32_t* r, uint32_t a) {
    asm volatile("ldmatrix.sync.aligned.m8n8.x2.shared.b16 {%0,%1}, [%2];"
                 : "=r"(r[0]), "=r"(r[1]) : "r"(a));
}
__device__ __forceinline__ void mma16816(float* c, const uint32_t* a, const uint32_t* b) {
    asm volatile("mma.sync.aligned.m16n8k16.row.col.f32.bf16.bf16.f32 "
                 "{%0,%1,%2,%3},{%4,%5,%6,%7},{%8,%9},{%0,%1,%2,%3};"
                 : "+f"(c[0]), "+f"(c[1]), "+f"(c[2]), "+f"(c[3])
                 : "r"(a[0]), "r"(a[1]), "r"(a[2]), "r"(a[3]), "r"(b[0]), "r"(b[1]));
}
#define CP16(sa, ga) asm volatile("cp.async.cg.shared.global [%0], [%1], 16;\n" :: "r"(sa), "l"(ga))
#define CPCOMMIT()   asm volatile("cp.async.commit_group;\n" ::: "memory")
#define CPWAIT0()    asm volatile("cp.async.wait_group 0;\n" ::: "memory")

__global__ __launch_bounds__(256) void mma_gemm(
    const bf16* __restrict__ A, const bf16* __restrict__ B, float* __restrict__ C,
    int M, int N, int K)
{
    const int bx = blockIdx.x, by = blockIdx.y;

    __shared__ bf16 As[2][BMg][40];
    __shared__ bf16 Bs[2][BNg][40];

    const int tid  = threadIdx.x;
    const int warp = tid >> 5, lane = tid & 31;
    const int wm = warp & 1, wn = warp >> 1;

    const uint32_t sA = (uint32_t)__cvta_generic_to_shared(&As[0][0][0]);
    const uint32_t sB = (uint32_t)__cvta_generic_to_shared(&Bs[0][0][0]);
    const uint32_t BUFB = BMg * 40 * 2;

    const int ldrow = tid >> 2;
    const int ldch  = (tid & 3) * 8;

    float acc[4][4][4];
#pragma unroll
    for (int i = 0; i < 4; i++)
#pragma unroll
        for (int j = 0; j < 4; j++)
#pragma unroll
            for (int t = 0; t < 4; t++) acc[i][j][t] = 0.f;

#pragma unroll
    for (int h = 0; h < 2; h++) {
        int row = ldrow + h * 64;
        CP16(sA + (uint32_t)(row * 40 + ldch) * 2,
             A + (size_t)(by * BMg + row) * K + ldch);
        CP16(sB + (uint32_t)(row * 40 + ldch) * 2,
             B + (size_t)(bx * BNg + row) * K + ldch);
    }
    CPCOMMIT();
    CPWAIT0();
    __syncthreads();

    const int KT = K / BKg;
    int buf = 0;
    for (int kt = 0; kt < KT; kt++) {
        if (kt + 1 < KT) {
            int k0 = (kt + 1) * BKg;
#pragma unroll
            for (int h = 0; h < 2; h++) {
                int row = ldrow + h * 64;
                CP16(sA + (buf ^ 1) * BUFB + (uint32_t)(row * 40 + ldch) * 2,
                     A + (size_t)(by * BMg + row) * K + k0 + ldch);
                CP16(sB + (buf ^ 1) * BUFB + (uint32_t)(row * 40 + ldch) * 2,
                     B + (size_t)(bx * BNg + row) * K + k0 + ldch);
            }
            CPCOMMIT();
        }

#pragma unroll
        for (int ks = 0; ks < BKg; ks += 16) {
            uint32_t af[4][4], bfr[4][2];
            const int arow = wm * 64 + (lane & 15);
            const int acol = ks + ((lane >> 4) << 3);
#pragma unroll
            for (int mt = 0; mt < 4; mt++)
                ldsm_x4(af[mt], sA + buf * BUFB +
                        (uint32_t)((arow + mt * 16) * 40 + acol) * 2);
            const int brow = wn * 32 + (lane & 7);
            const int bcol = ks + (((lane >> 3) & 1) << 3);
#pragma unroll
            for (int nt = 0; nt < 4; nt++)
                ldsm_x2(bfr[nt], sB + buf * BUFB +
                        (uint32_t)((brow + nt * 8) * 40 + bcol) * 2);
#pragma unroll
            for (int mt = 0; mt < 4; mt++)
#pragma unroll
                for (int nt = 0; nt < 4; nt++)
                    mma16816(acc[mt][nt], af[mt], bfr[nt]);
        }

        if (kt + 1 < KT) {
            CPWAIT0();
            __syncthreads();
            buf ^= 1;
        }
    }

#pragma unroll
    for (int mt = 0; mt < 4; mt++) {
#pragma unroll
        for (int nt = 0; nt < 4; nt++) {
            int row = by * BMg + wm * 64 + mt * 16 + (lane >> 2);
            int col = bx * BNg + wn * 32 + nt * 8 + (lane & 3) * 2;
            float2 v0 = make_float2(acc[mt][nt][0], acc[mt][nt][1]);
            float2 v1 = make_float2(acc[mt][nt][2], acc[mt][nt][3]);
            *(float2*)&C[(size_t)row * N + col]       = v0;
            *(float2*)&C[(size_t)(row + 8) * N + col] = v1;
        }
    }
}

// ---------------- fp32 SGEMM (exact; selection path) ----------------------------
__global__ __launch_bounds__(256) void sgemm_nn(const float* __restrict__ A,
                                                const float* __restrict__ B,
                                                float* __restrict__ C,
                                                int M, int N, int K)
{
    __shared__ float As[2][8][128];
    __shared__ float Bs[2][8][128];

    const int tid = threadIdx.x;
    const int bx = blockIdx.x, by = blockIdx.y;
    const int tx = tid & 15, ty = tid >> 4;

    const int arow = tid >> 1, ak = (tid & 1) * 4;
    const int brow = tid >> 5, bcol = (tid & 31) * 4;

    const float* Ag = A + (size_t)(by * 128 + arow) * K + ak;
    const float* Bg = B + (size_t)brow * N + bx * 128 + bcol;

    float4 af = *(const float4*)Ag;
    float4 bf = *(const float4*)Bg;
    As[0][ak + 0][arow] = af.x;
    As[0][ak + 1][arow] = af.y;
    As[0][ak + 2][arow] = af.z;
    As[0][ak + 3][arow] = af.w;
    *(float4*)&Bs[0][brow][bcol] = bf;
    __syncthreads();

    float acc[8][8];
#pragma unroll
    for (int i = 0; i < 8; i++)
#pragma unroll
        for (int j = 0; j < 8; j++) acc[i][j] = 0.f;

    int buf = 0;
    for (int k0 = 8; k0 <= K; k0 += 8) {
        const bool next = (k0 < K);
        if (next) {
            af = *(const float4*)(Ag + k0);
            bf = *(const float4*)(Bg + (size_t)k0 * N);
        }
#pragma unroll
        for (int kk = 0; kk < 8; kk++) {
            float a[8], b[8];
            *(float4*)&a[0] = *(const float4*)&As[buf][kk][ty * 8];
            *(float4*)&a[4] = *(const float4*)&As[buf][kk][ty * 8 + 4];
            *(float4*)&b[0] = *(const float4*)&Bs[buf][kk][tx * 8];
            *(float4*)&b[4] = *(const float4*)&Bs[buf][kk][tx * 8 + 4];
#pragma unroll
            for (int i = 0; i < 8; i++)
#pragma unroll
                for (int j = 0; j < 8; j++)
                    acc[i][j] += a[i] * b[j];
        }
        if (next) {
            buf ^= 1;
            As[buf][ak + 0][arow] = af.x;
            As[buf][ak + 1][arow] = af.y;
            As[buf][ak + 2][arow] = af.z;
            As[buf][ak + 3][arow] = af.w;
            *(float4*)&Bs[buf][brow][bcol] = bf;
            __syncthreads();
        }
    }

#pragma unroll
    for (int i = 0; i < 8; i++) {
        float* Crow = C + (size_t)(by * 128 + ty * 8 + i) * N + bx * 128 + tx * 8;
        *(float4*)Crow       = make_float4(acc[i][0], acc[i][1], acc[i][2], acc[i][3]);
        *(float4*)(Crow + 4) = make_float4(acc[i][4], acc[i][5], acc[i][6], acc[i][7]);
    }
}

// ---------------- RoPE ----------------------------------------------------------
__global__ void rope_kernel(float* __restrict__ qkv, int BS)
{
    int idx = blockIdx.x * blockDim.x + threadIdx.x;
    if (idx >= BS * 1024) return;
    int i   = idx & 31;
    int h   = (idx >> 5) & 15;
    int qk  = (idx >> 9) & 1;
    int tok = idx >> 10;
    int s   = tok & (S_LEN - 1);

    float ex   = (float)(2 * i) * (1.0f / 64.0f);
    float freq = powf(10000.0f, -ex);
    float ang  = (float)s * freq;
    float sn, cs;
    sincosf(ang, &sn, &cs);

    size_t base = (size_t)tok * 3072 + (size_t)qk * 1024 + h * 64 + 2 * i;
    float x1 = qkv[base], x2 = qkv[base + 1];
    qkv[base]     = x1 * cs - x2 * sn;
    qkv[base + 1] = x1 * sn + x2 * cs;
}

// ---------------- exact index scores + radix-select threshold + bitmask ---------
__global__ __launch_bounds__(256) void topk_mask_kernel(const float* __restrict__ iq,
                                                        const float* __restrict__ ik,
                                                        const int* __restrict__ topk_ptr,
                                                        unsigned* __restrict__ mask)
{
    __shared__ float    iqs[IDX_D];
    __shared__ unsigned keys[S_LEN];
    __shared__ unsigned hist[256];
    __shared__ unsigned s_prefix;
    __shared__ int      s_kr;

    const int tid = threadIdx.x;
    const int b = blockIdx.x >> 11;
    const int q = blockIdx.x & (S_LEN - 1);

    iqs[tid] = iq[(size_t)(b * S_LEN + q) * IDX_D + tid];
    __syncthreads();

    const float4* iq4 = (const float4*)iqs;
    for (int k = tid; k < S_LEN; k += 256) {
        unsigned key = 0u;
        if (k <= q) {
            const float4* ikr = (const float4*)(ik + (size_t)(b * S_LEN + k) * IDX_D);
            float acc = 0.f;
#pragma unroll 8
            for (int i = 0; i < 64; i++) {
                float4 a = iq4[i];
                float4 c = ikr[i];
                acc += a.x * c.x + a.y * c.y + a.z * c.z + a.w * c.w;
            }
            unsigned u = __float_as_uint(acc);
            key = (u & 0x80000000u) ? ~u : (u | 0x80000000u);
        }
        keys[k] = key;
    }
    __syncthreads();

    int topk = topk_ptr ? topk_ptr[0] : 512;
    if (topk > S_LEN) topk = S_LEN;
    const int nvalid = q + 1;

    unsigned threshold = 0u;
    if (nvalid > topk) {
        if (tid == 0) { s_prefix = 0u; s_kr = topk; }
        for (int pass = 0; pass < 4; pass++) {
            const int shift = 24 - pass * 8;
            __syncthreads();
            hist[tid] = 0u;
            __syncthreads();
            const unsigned pref = s_prefix;
            for (int k = tid; k < S_LEN; k += 256) {
                unsigned key = keys[k];
                bool match = (pass == 0) || ((key >> (shift + 8)) == (pref >> (shift + 8)));
                if (match) atomicAdd(&hist[(key >> shift) & 255u], 1u);
            }
            __syncthreads();
            if (tid == 0) {
                int kr = s_kr;
                unsigned p = s_prefix;
                for (int d = 255; d >= 0; d--) {
                    int c = (int)hist[d];
                    if (kr <= c) { s_prefix = p | ((unsigned)d << shift); break; }
                    kr -= c;
                }
                s_kr = kr;
            }
        }
        __syncthreads();
        threshold = s_prefix;
    }

    if (tid < S_LEN / 32) {
        unsigned w = 0u;
        const int kb = tid * 32;
#pragma unroll
        for (int bit = 0; bit < 32; bit++) {
            int k = kb + bit;
            if (k <= q && keys[k] >= threshold && keys[k] != 0u) w |= (1u << bit);
        }
        mask[(size_t)(b * S_LEN + q) * (S_LEN / 32) + tid] = w;
    }
}

// ---------------- flash operand prep: split Q/K (x3), V transposed (x3) ---------
__global__ void prep_flash(const float* __restrict__ qkv,
                           bf16* __restrict__ q3, bf16* __restrict__ k3,
                           bf16* __restrict__ vt3, int BS)
{
    int idx = blockIdx.x * blockDim.x + threadIdx.x;
    if (idx >= BS * 1024) return;
    int d = idx & 63;
    int h = (idx >> 6) & 15;
    int tok = idx >> 10;
    int b = tok >> 11;
    int s = tok & (S_LEN - 1);

    size_t base = (size_t)tok * 3072 + h * 64 + d;
    float q = qkv[base];
    float k = qkv[base + 1024];
    float v = qkv[base + 2048];
    size_t bh = (size_t)b * N_HEADS + h;

    {
        bf16 hh = __float2bfloat16(q);
        bf16 ll = __float2bfloat16(q - __bfloat162float(hh));
        size_t o = (bh * S_LEN + s) * 192 + 3 * (size_t)d;
        q3[o] = hh; q3[o + 1] = ll; q3[o + 2] = hh;
    }
    {
        bf16 hh = __float2bfloat16(k);
        bf16 ll = __float2bfloat16(k - __bfloat162float(hh));
        size_t o = (bh * S_LEN + s) * 192 + 3 * (size_t)d;
        k3[o] = hh; k3[o + 1] = hh; k3[o + 2] = ll;
    }
    {
        bf16 hh = __float2bfloat16(v);
        bf16 ll = __float2bfloat16(v - __bfloat162float(hh));
        size_t o = (bh * 64 + d) * (size_t)(3 * S_LEN) + 3 * (size_t)s;
        vt3[o] = hh; vt3[o + 1] = hh; vt3[o + 2] = ll;
    }
}

// ---------------- tensor-core masked flash attention (x3 operands) --------------
#define FSTR 200   // smem row stride in bf16 (400B rows: conflict-free ldsm)

__global__ __launch_bounds__(128) void flash_mma(
    const bf16* __restrict__ q3, const bf16* __restrict__ k3,
    const bf16* __restrict__ vt3, const unsigned* __restrict__ mask,
    float* __restrict__ attn)
{
    extern __shared__ __align__(16) bf16 sm[];
    const int tid  = threadIdx.x;
    const int warp = tid >> 5, lane = tid & 31;
    const int qt = blockIdx.x, h = blockIdx.y, b = blockIdx.z;

    const uint32_t sQ = (uint32_t)__cvta_generic_to_shared(sm);
    const uint32_t sK = sQ + 64 * FSTR * 2;
    const uint32_t sV = sQ + 2 * 64 * FSTR * 2;
    const uint32_t sP = sQ + 3 * 64 * FSTR * 2;
    bf16* Psp = sm + 3 * 64 * FSTR;

    const size_t bh = (size_t)b * N_HEADS + h;
    const bf16* q3g  = q3  + (bh * S_LEN + (size_t)qt * 64) * 192;
    const bf16* k3g  = k3  + bh * S_LEN * 192;
    const bf16* vt3g = vt3 + bh * 64 * (size_t)(3 * S_LEN);

    for (int c = tid; c < 1536; c += 128) {
        int row = c / 24, k16 = c % 24;
        CP16(sQ + row * 400 + k16 * 16, q3g + (size_t)row * 192 + k16 * 8);
    }
    CPCOMMIT();

    float O[8][4];
#pragma unroll
    for (int i = 0; i < 8; i++)
#pragma unroll
        for (int j = 0; j < 4; j++) O[i][j] = 0.f;
    float m0 = -1e30f, m1 = -1e30f, l0 = 0.f, l1 = 0.f;

    const int r0 = warp * 16 + (lane >> 2);
    const int q0 = qt * 64 + r0, q1 = q0 + 8;
    const unsigned* mrow0 = mask + ((size_t)b * S_LEN + q0) * 64;
    const unsigned* mrow1 = mask + ((size_t)b * S_LEN + q1) * 64;

    const uint32_t aoff = (uint32_t)((warp * 16 + (lane & 15)) * 400 + ((lane >> 4) << 3) * 2);
    const int browo = (lane & 7) + ((lane >> 4) << 3);
    const uint32_t bcol = (uint32_t)((((lane >> 3) & 1) << 3) * 2);

    for (int kt = 0; kt <= qt; kt++) {
        for (int c = tid; c < 3072; c += 128) {
            if (c < 1536) {
                int row = c / 24, k16 = c % 24;
                CP16(sK + row * 400 + k16 * 16,
                     k3g + ((size_t)kt * 64 + row) * 192 + k16 * 8);
            } else {
                int cc = c - 1536;
                int drow = cc / 24, k16 = cc % 24;
                CP16(sV + drow * 400 + k16 * 16,
                     vt3g + (size_t)drow * (3 * S_LEN) + (size_t)kt * 192 + k16 * 8);
            }
        }
        CPCOMMIT();
        CPWAIT0();
        __syncthreads();

        float S_[8][4];
#pragma unroll
        for (int i = 0; i < 8; i++)
#pragma unroll
            for (int j = 0; j < 4; j++) S_[i][j] = 0.f;

#pragma unroll
        for (int ks = 0; ks < 12; ks++) {
            uint32_t a[4];
            ldsm_x4(a, sQ + aoff + ks * 32);
#pragma unroll
            for (int nt2 = 0; nt2 < 4; nt2++) {
                uint32_t bb[4];
                ldsm_x4(bb, sK + (uint32_t)((nt2 * 16 + browo) * 400) + bcol + ks * 32);
                mma16816(S_[nt2 * 2],     a, bb);
                mma16816(S_[nt2 * 2 + 1], a, bb + 2);
            }
        }

        const unsigned mw00 = mrow0[kt * 2], mw01 = mrow0[kt * 2 + 1];
        const unsigned mw10 = mrow1[kt * 2], mw11 = mrow1[kt * 2 + 1];
        float mx0 = -1e30f, mx1 = -1e30f;
#pragma unroll
        for (int nf = 0; nf < 8; nf++) {
            int c = nf * 8 + 2 * (lane & 3);
#pragma unroll
            for (int e = 0; e < 2; e++) {
                int cc = c + e;
                unsigned w0 = (cc < 32 ? mw00 : mw01) >> (cc & 31);
                unsigned w1 = (cc < 32 ? mw10 : mw11) >> (cc & 31);
                float v0 = (w0 & 1u) ? S_[nf][e] * 0.125f     : -1e30f;
                float v1 = (w1 & 1u) ? S_[nf][e + 2] * 0.125f : -1e30f;
                S_[nf][e] = v0; S_[nf][e + 2] = v1;
                mx0 = fmaxf(mx0, v0); mx1 = fmaxf(mx1, v1);
            }
        }
        mx0 = fmaxf(mx0, __shfl_xor_sync(0xffffffffu, mx0, 1));
        mx0 = fmaxf(mx0, __shfl_xor_sync(0xffffffffu, mx0, 2));
        mx1 = fmaxf(mx1, __shfl_xor_sync(0xffffffffu, mx1, 1));
        mx1 = fmaxf(mx1, __shfl_xor_sync(0xffffffffu, mx1, 2));
        float mn0 = fmaxf(m0, mx0), mn1 = fmaxf(m1, mx1);
        float c0 = __expf(m0 - mn0), c1 = __expf(m1 - mn1);
        float ls0 = 0.f, ls1 = 0.f;
#pragma unroll
        for (int nf = 0; nf < 8; nf++) {
#pragma unroll
            for (int e = 0; e < 2; e++) {
                // guard: masked lanes (-1e30) must yield p = 0 even when the
                // running max is also -1e30 (all-masked tile), not exp(0)=1.
                float p0 = (S_[nf][e]     > -1e29f) ? __expf(S_[nf][e]     - mn0) : 0.f;
                float p1 = (S_[nf][e + 2] > -1e29f) ? __expf(S_[nf][e + 2] - mn1) : 0.f;
                S_[nf][e] = p0; S_[nf][e + 2] = p1;
                ls0 += p0; ls1 += p1;
            }
        }
        ls0 += __shfl_xor_sync(0xffffffffu, ls0, 1);
        ls0 += __shfl_xor_sync(0xffffffffu, ls0, 2);
        ls1 += __shfl_xor_sync(0xffffffffu, ls1, 1);
        ls1 += __shfl_xor_sync(0xffffffffu, ls1, 2);
        l0 = l0 * c0 + ls0; l1 = l1 * c1 + ls1;
        m0 = mn0; m1 = mn1;
#pragma unroll
        for (int nf = 0; nf < 8; nf++) {
            O[nf][0] *= c0; O[nf][1] *= c0;
            O[nf][2] *= c1; O[nf][3] *= c1;
        }

#pragma unroll
        for (int nf = 0; nf < 8; nf++) {
            int c = nf * 8 + 2 * (lane & 3);
#pragma unroll
            for (int e = 0; e < 2; e++) {
                float p = S_[nf][e];
                bf16 hh = __float2bfloat16(p);
                bf16 ll = __float2bfloat16(p - __bfloat162float(hh));
                int o = r0 * FSTR + 3 * (c + e);
                Psp[o] = hh; Psp[o + 1] = ll; Psp[o + 2] = hh;

                p = S_[nf][e + 2];
                hh = __float2bfloat16(p);
                ll = __float2bfloat16(p - __bfloat162float(hh));
                o = (r0 + 8) * FSTR + 3 * (c + e);
                Psp[o] = hh; Psp[o + 1] = ll; Psp[o + 2] = hh;
            }
        }
        __syncwarp();

#pragma unroll
        for (int ks = 0; ks < 12; ks++) {
            uint32_t a[4];
            ldsm_x4(a, sP + aoff + ks * 32);
#pragma unroll
            for (int nt2 = 0; nt2 < 4; nt2++) {
                uint32_t bb[4];
                ldsm_x4(bb, sV + (uint32_t)((nt2 * 16 + browo) * 400) + bcol + ks * 32);
                mma16816(O[nt2 * 2],     a, bb);
                mma16816(O[nt2 * 2 + 1], a, bb + 2);
            }
        }
        __syncthreads();
    }

    float inv0 = 1.0f / l0, inv1 = 1.0f / l1;
    float* out0 = attn + ((size_t)b * S_LEN + q0) * D_MODEL + h * 64;
    float* out1 = attn + ((size_t)b * S_LEN + q1) * D_MODEL + h * 64;
#pragma unroll
    for (int nf = 0; nf < 8; nf++) {
        int c = nf * 8 + 2 * (lane & 3);
        *(float2*)(out0 + c) = make_float2(O[nf][0] * inv0, O[nf][1] * inv0);
        *(float2*)(out1 + c) = make_float2(O[nf][2] * inv1, O[nf][3] * inv1);
    }
}

// ---------------- launcher ------------------------------------------------------
extern "C" void kernel_launch(void* const* d_in, const int* in_sizes, int n_in,
                              void* d_out, int out_size)
{
    const float* x    = nullptr;
    const float* Wqkv = nullptr;
    const float* Wo   = nullptr;
    const float* Wiq  = nullptr;
    const float* Wik  = nullptr;
    const int*   topk = nullptr;
    for (int i = 0; i < n_in; i++) {
        int sz = in_sizes[i];
        if      (sz == D_MODEL * 3 * D_MODEL)       Wqkv = (const float*)d_in[i];
        else if (sz == D_MODEL * D_MODEL)           Wo   = (const float*)d_in[i];
        else if (sz == D_MODEL * IDX_D) { if (!Wiq) Wiq  = (const float*)d_in[i];
                                          else      Wik  = (const float*)d_in[i]; }
        else if (sz <= 4)                           topk = (const int*)d_in[i];
        else                                        x    = (const float*)d_in[i];
    }

    const int BS = out_size / D_MODEL;
    const int Bn = BS / S_LEN;

    float *qkv, *iq, *ik, *attn; unsigned* mask;
    bf16 *x3, *attn3, *wqkv3, *wo3, *q3, *k3, *vt3;
    cudaGetSymbolAddress((void**)&qkv,   g_qkv);
    cudaGetSymbolAddress((void**)&iq,    g_iq);
    cudaGetSymbolAddress((void**)&ik,    g_ik);
    cudaGetSymbolAddress((void**)&attn,  g_attn);
    cudaGetSymbolAddress((void**)&mask,  g_mask);
    cudaGetSymbolAddress((void**)&x3,    g_x3);
    cudaGetSymbolAddress((void**)&attn3, g_attn3);
    cudaGetSymbolAddress((void**)&wqkv3, g_wqkv3);
    cudaGetSymbolAddress((void**)&wo3,   g_wo3);
    cudaGetSymbolAddress((void**)&q3,    g_q3);
    cudaGetSymbolAddress((void**)&k3,    g_k3);
    cudaGetSymbolAddress((void**)&vt3,   g_vt3);

    const int K3 = 3 * D_MODEL;

    // splits for the tensor-core path (QKV and W_o)
    split_a<<<(BS * D_MODEL + 255) / 256, 256>>>(x, x3, BS * D_MODEL);
    {
        dim3 blk(32, 8);
        split_bT<<<dim3(3 * D_MODEL / 32, D_MODEL / 32), blk>>>(Wqkv, wqkv3, D_MODEL, 3 * D_MODEL);
        split_bT<<<dim3(D_MODEL / 32, D_MODEL / 32), blk>>>(Wo, wo3, D_MODEL, D_MODEL);
    }

    // QKV projection on tensor cores
    mma_gemm<<<dim3(3 * D_MODEL / BNg, BS / BMg), 256>>>(x3, wqkv3, qkv, BS, 3 * D_MODEL, K3);

    // selection path: exact fp32 projections + exact scalar top-k (known good)
    sgemm_nn<<<dim3(IDX_D / 128, BS / 128), 256>>>(x, Wiq, iq, BS, IDX_D, D_MODEL);
    sgemm_nn<<<dim3(IDX_D / 128, BS / 128), 256>>>(x, Wik, ik, BS, IDX_D, D_MODEL);

    rope_kernel<<<(BS * 1024 + 255) / 256, 256>>>(qkv, BS);

    topk_mask_kernel<<<BS, 256>>>(iq, ik, topk, mask);

    // tensor-core flash (x3 operands)
    prep_flash<<<(BS * 1024 + 255) / 256, 256>>>(qkv, q3, k3, vt3, BS);
    cudaFuncSetAttribute(flash_mma, cudaFuncAttributeMaxDynamicSharedMemorySize,
                         4 * 64 * FSTR * 2);
    flash_mma<<<dim3(S_LEN / 64, N_HEADS, Bn), 128, 4 * 64 * FSTR * 2>>>(
        q3, k3, vt3, mask, attn);

    // output projection on tensor cores
    split_a<<<(BS * D_MODEL + 255) / 256, 256>>>(attn, attn3, BS * D_MODEL);
    mma_gemm<<<dim3(D_MODEL / BNg, BS / BMg), 256>>>(attn3, wo3, (float*)d_out, BS, D_MODEL, K3);
}

// round 8
// speedup vs baseline: 2.4327x; 1.5866x over previous
#include <cuda_runtime.h>
#include <cuda_bf16.h>
#include <cstdint>
#include <math.h>

#define S_LEN   2048
#define D_MODEL 1024
#define N_HEADS 16
#define IDX_D   256
#define MAXB    2
#define BS_MAX  (MAXB * S_LEN)

typedef __nv_bfloat16 bf16;

// ---------------- scratch (static device globals; no allocation) ----------------
__device__ float    g_qkv [(size_t)BS_MAX * 3 * D_MODEL];
__device__ float    g_iq  [(size_t)BS_MAX * IDX_D];
__device__ float    g_ik  [(size_t)BS_MAX * IDX_D];
__device__ float    g_attn[(size_t)BS_MAX * D_MODEL];
__device__ unsigned g_mask[(size_t)BS_MAX * (S_LEN / 32)];

__device__ __align__(16) bf16 g_x3   [(size_t)BS_MAX * 3 * D_MODEL];
__device__ __align__(16) bf16 g_attn3[(size_t)BS_MAX * 3 * D_MODEL];
__device__ __align__(16) bf16 g_wqkv3[(size_t)(3 * D_MODEL) * 3 * D_MODEL];
__device__ __align__(16) bf16 g_wo3  [(size_t)D_MODEL * 3 * D_MODEL];

// flash operands (x3)
__device__ __align__(16) bf16 g_q3 [(size_t)MAXB * N_HEADS * S_LEN * 192];
__device__ __align__(16) bf16 g_k3 [(size_t)MAXB * N_HEADS * S_LEN * 192];
__device__ __align__(16) bf16 g_vt3[(size_t)MAXB * N_HEADS * 64 * 3 * S_LEN];

// ---------------- bf16x3 split conversions --------------------------------------
__global__ void split_a(const float* __restrict__ s, bf16* __restrict__ d, int n)
{
    int i = blockIdx.x * blockDim.x + threadIdx.x;
    if (i >= n) return;
    float v = s[i];
    bf16 h = __float2bfloat16(v);
    bf16 l = __float2bfloat16(v - __bfloat162float(h));
    d[3 * i] = h; d[3 * i + 1] = l; d[3 * i + 2] = h;
}

__global__ void split_bT(const float* __restrict__ W, bf16* __restrict__ out,
                         int K, int N)
{
    __shared__ float t[32][33];
    int n0 = blockIdx.x * 32, k0 = blockIdx.y * 32;
    int tx = threadIdx.x, ty = threadIdx.y;   // block (32,8)
    for (int i = ty; i < 32; i += 8)
        t[i][tx] = W[(size_t)(k0 + i) * N + n0 + tx];
    __syncthreads();
    for (int r = ty; r < 32; r += 8) {
        float v = t[tx][r];
        bf16 h = __float2bfloat16(v);
        bf16 l = __float2bfloat16(v - __bfloat162float(h));
        size_t o = (size_t)(n0 + r) * (3 * K) + 3 * (size_t)(k0 + tx);
        out[o] = h; out[o + 1] = h; out[o + 2] = l;
    }
}

// ---------------- tensor-core NT GEMM (unchanged, validated) --------------------
#define BMg 128
#define BNg 128
#define BKg 32

__device__ __forceinline__ void ldsm_x4(uint32_t* r, uint32_t a) {
    asm volatile("ldmatrix.sync.aligned.m8n8.x4.shared.b16 {%0,%1,%2,%3}, [%4];"
                 : "=r"(r[0]), "=r"(r[1]), "=r"(r[2]), "=r"(r[3]) : "r"(a));
}
__device__ __forceinline__ void ldsm_x2(uint32_t* r, uint32_t a) {
    asm volatile("ldmatrix.sync.aligned.m8n8.x2.shared.b16 {%0,%1}, [%2];"
                 : "=r"(r[0]), "=r"(r[1]) : "r"(a));
}
__device__ __forceinline__ void mma16816(float* c, const uint32_t* a, const uint32_t* b) {
    asm volatile("mma.sync.aligned.m16n8k16.row.col.f32.bf16.bf16.f32 "
                 "{%0,%1,%2,%3},{%4,%5,%6,%7},{%8,%9},{%0,%1,%2,%3};"
                 : "+f"(c[0]), "+f"(c[1]), "+f"(c[2]), "+f"(c[3])
                 : "r"(a[0]), "r"(a[1]), "r"(a[2]), "r"(a[3]), "r"(b[0]), "r"(b[1]));
}
#define CP16(sa, ga) asm volatile("cp.async.cg.shared.global [%0], [%1], 16;\n" :: "r"(sa), "l"(ga))
#define CPCOMMIT()   asm volatile("cp.async.commit_group;\n" ::: "memory")
#define CPWAIT0()    asm volatile("cp.async.wait_group 0;\n" ::: "memory")
#define CPWAIT1()    asm volatile("cp.async.wait_group 1;\n" ::: "memory")

__global__ __launch_bounds__(256) void mma_gemm(
    const bf16* __restrict__ A, const bf16* __restrict__ B, float* __restrict__ C,
    int M, int N, int K)
{
    const int bx = blockIdx.x, by = blockIdx.y;

    __shared__ bf16 As[2][BMg][40];
    __shared__ bf16 Bs[2][BNg][40];

    const int tid  = threadIdx.x;
    const int warp = tid >> 5, lane = tid & 31;
    const int wm = warp & 1, wn = warp >> 1;

    const uint32_t sA = (uint32_t)__cvta_generic_to_shared(&As[0][0][0]);
    const uint32_t sB = (uint32_t)__cvta_generic_to_shared(&Bs[0][0][0]);
    const uint32_t BUFB = BMg * 40 * 2;

    const int ldrow = tid >> 2;
    const int ldch  = (tid & 3) * 8;

    float acc[4][4][4];
#pragma unroll
    for (int i = 0; i < 4; i++)
#pragma unroll
        for (int j = 0; j < 4; j++)
#pragma unroll
            for (int t = 0; t < 4; t++) acc[i][j][t] = 0.f;

#pragma unroll
    for (int h = 0; h < 2; h++) {
        int row = ldrow + h * 64;
        CP16(sA + (uint32_t)(row * 40 + ldch) * 2,
             A + (size_t)(by * BMg + row) * K + ldch);
        CP16(sB + (uint32_t)(row * 40 + ldch) * 2,
             B + (size_t)(bx * BNg + row) * K + ldch);
    }
    CPCOMMIT();
    CPWAIT0();
    __syncthreads();

    const int KT = K / BKg;
    int buf = 0;
    for (int kt = 0; kt < KT; kt++) {
        if (kt + 1 < KT) {
            int k0 = (kt + 1) * BKg;
#pragma unroll
            for (int h = 0; h < 2; h++) {
                int row = ldrow + h * 64;
                CP16(sA + (buf ^ 1) * BUFB + (uint32_t)(row * 40 + ldch) * 2,
                     A + (size_t)(by * BMg + row) * K + k0 + ldch);
                CP16(sB + (buf ^ 1) * BUFB + (uint32_t)(row * 40 + ldch) * 2,
                     B + (size_t)(bx * BNg + row) * K + k0 + ldch);
            }
            CPCOMMIT();
        }

#pragma unroll
        for (int ks = 0; ks < BKg; ks += 16) {
            uint32_t af[4][4], bfr[4][2];
            const int arow = wm * 64 + (lane & 15);
            const int acol = ks + ((lane >> 4) << 3);
#pragma unroll
            for (int mt = 0; mt < 4; mt++)
                ldsm_x4(af[mt], sA + buf * BUFB +
                        (uint32_t)((arow + mt * 16) * 40 + acol) * 2);
            const int brow = wn * 32 + (lane & 7);
            const int bcol = ks + (((lane >> 3) & 1) << 3);
#pragma unroll
            for (int nt = 0; nt < 4; nt++)
                ldsm_x2(bfr[nt], sB + buf * BUFB +
                        (uint32_t)((brow + nt * 8) * 40 + bcol) * 2);
#pragma unroll
            for (int mt = 0; mt < 4; mt++)
#pragma unroll
                for (int nt = 0; nt < 4; nt++)
                    mma16816(acc[mt][nt], af[mt], bfr[nt]);
        }

        if (kt + 1 < KT) {
            CPWAIT0();
            __syncthreads();
            buf ^= 1;
        }
    }

#pragma unroll
    for (int mt = 0; mt < 4; mt++) {
#pragma unroll
        for (int nt = 0; nt < 4; nt++) {
            int row = by * BMg + wm * 64 + mt * 16 + (lane >> 2);
            int col = bx * BNg + wn * 32 + nt * 8 + (lane & 3) * 2;
            float2 v0 = make_float2(acc[mt][nt][0], acc[mt][nt][1]);
            float2 v1 = make_float2(acc[mt][nt][2], acc[mt][nt][3]);
            *(float2*)&C[(size_t)row * N + col]       = v0;
            *(float2*)&C[(size_t)(row + 8) * N + col] = v1;
        }
    }
}

// ---------------- fp32 SGEMM, dual-output (selection path) ----------------------
// blockIdx.z selects (B1,C1) or (B2,C2). Math identical to validated sgemm_nn.
__global__ __launch_bounds__(256) void sgemm_nn2(const float* __restrict__ A,
                                                 const float* __restrict__ B1,
                                                 float* __restrict__ C1,
                                                 const float* __restrict__ B2,
                                                 float* __restrict__ C2,
                                                 int M, int N, int K)
{
    const float* B = blockIdx.z ? B2 : B1;
    float*       C = blockIdx.z ? C2 : C1;

    __shared__ float As[2][8][128];
    __shared__ float Bs[2][8][128];

    const int tid = threadIdx.x;
    const int bx = blockIdx.x, by = blockIdx.y;
    const int tx = tid & 15, ty = tid >> 4;

    const int arow = tid >> 1, ak = (tid & 1) * 4;
    const int brow = tid >> 5, bcol = (tid & 31) * 4;

    const float* Ag = A + (size_t)(by * 128 + arow) * K + ak;
    const float* Bg = B + (size_t)brow * N + bx * 128 + bcol;

    float4 af = *(const float4*)Ag;
    float4 bf = *(const float4*)Bg;
    As[0][ak + 0][arow] = af.x;
    As[0][ak + 1][arow] = af.y;
    As[0][ak + 2][arow] = af.z;
    As[0][ak + 3][arow] = af.w;
    *(float4*)&Bs[0][brow][bcol] = bf;
    __syncthreads();

    float acc[8][8];
#pragma unroll
    for (int i = 0; i < 8; i++)
#pragma unroll
        for (int j = 0; j < 8; j++) acc[i][j] = 0.f;

    int buf = 0;
    for (int k0 = 8; k0 <= K; k0 += 8) {
        const bool next = (k0 < K);
        if (next) {
            af = *(const float4*)(Ag + k0);
            bf = *(const float4*)(Bg + (size_t)k0 * N);
        }
#pragma unroll
        for (int kk = 0; kk < 8; kk++) {
            float a[8], b[8];
            *(float4*)&a[0] = *(const float4*)&As[buf][kk][ty * 8];
            *(float4*)&a[4] = *(const float4*)&As[buf][kk][ty * 8 + 4];
            *(float4*)&b[0] = *(const float4*)&Bs[buf][kk][tx * 8];
            *(float4*)&b[4] = *(const float4*)&Bs[buf][kk][tx * 8 + 4];
#pragma unroll
            for (int i = 0; i < 8; i++)
#pragma unroll
                for (int j = 0; j < 8; j++)
                    acc[i][j] += a[i] * b[j];
        }
        if (next) {
            buf ^= 1;
            As[buf][ak + 0][arow] = af.x;
            As[buf][ak + 1][arow] = af.y;
            As[buf][ak + 2][arow] = af.z;
            As[buf][ak + 3][arow] = af.w;
            *(float4*)&Bs[buf][brow][bcol] = bf;
            __syncthreads();
        }
    }

#pragma unroll
    for (int i = 0; i < 8; i++) {
        float* Crow = C + (size_t)(by * 128 + ty * 8 + i) * N + bx * 128 + tx * 8;
        *(float4*)Crow       = make_float4(acc[i][0], acc[i][1], acc[i][2], acc[i][3]);
        *(float4*)(Crow + 4) = make_float4(acc[i][4], acc[i][5], acc[i][6], acc[i][7]);
    }
}

// ---------------- RoPE ----------------------------------------------------------
__global__ void rope_kernel(float* __restrict__ qkv, int BS)
{
    int idx = blockIdx.x * blockDim.x + threadIdx.x;
    if (idx >= BS * 1024) return;
    int i   = idx & 31;
    int h   = (idx >> 5) & 15;
    int qk  = (idx >> 9) & 1;
    int tok = idx >> 10;
    int s   = tok & (S_LEN - 1);

    float ex   = (float)(2 * i) * (1.0f / 64.0f);
    float freq = powf(10000.0f, -ex);
    float ang  = (float)s * freq;
    float sn, cs;
    sincosf(ang, &sn, &cs);

    size_t base = (size_t)tok * 3072 + (size_t)qk * 1024 + h * 64 + 2 * i;
    float x1 = qkv[base], x2 = qkv[base + 1];
    qkv[base]     = x1 * cs - x2 * sn;
    qkv[base + 1] = x1 * sn + x2 * cs;
}

// ---------------- top-k: 8 query rows per block ---------------------------------
// Per-row dot uses the IDENTICAL float4 expression as the validated kernel;
// ik rows are streamed once per 8 rows instead of once per row (L2 traffic /8).
__global__ __launch_bounds__(256) void topk8_kernel(const float* __restrict__ iq,
                                                    const float* __restrict__ ik,
                                                    const int* __restrict__ topk_ptr,
                                                    unsigned* __restrict__ mask)
{
    extern __shared__ __align__(16) unsigned dsm[];
    float*    iqs  = (float*)dsm;             // 8 * 256 floats
    unsigned* keys = dsm + 8 * 256;           // 8 * 2048
    unsigned* hist = keys + 8 * 2048;         // 256
    __shared__ unsigned s_prefix;
    __shared__ int      s_kr;
    __shared__ unsigned s_thr[8];

    const int tid = threadIdx.x;
    const int gid = blockIdx.x;               // BS/8 blocks
    const int b = (gid * 8) >> 11;
    const int qbase = (gid * 8) & (S_LEN - 1);
    const int qmax = qbase + 7;

    // load 8 iq rows
    for (int i = tid; i < 8 * IDX_D; i += 256) {
        int r = i >> 8, c = i & 255;
        iqs[i] = iq[(size_t)(b * S_LEN + qbase + r) * IDX_D + c];
    }
    __syncthreads();

    // scores for all 8 rows, one ik stream
    for (int k = tid; k < S_LEN; k += 256) {
        if (k <= qmax) {
            const float4* ikr = (const float4*)(ik + (size_t)(b * S_LEN + k) * IDX_D);
            float acc[8];
#pragma unroll
            for (int r = 0; r < 8; r++) acc[r] = 0.f;
#pragma unroll 4
            for (int i = 0; i < 64; i++) {
                float4 c = ikr[i];
#pragma unroll
                for (int r = 0; r < 8; r++) {
                    float4 a = ((const float4*)(iqs + r * 256))[i];
                    acc[r] += a.x * c.x + a.y * c.y + a.z * c.z + a.w * c.w;
                }
            }
#pragma unroll
            for (int r = 0; r < 8; r++) {
                unsigned key = 0u;
                if (k <= qbase + r) {
                    unsigned u = __float_as_uint(acc[r]);
                    key = (u & 0x80000000u) ? ~u : (u | 0x80000000u);
                }
                keys[r * S_LEN + k] = key;
            }
        } else {
#pragma unroll
            for (int r = 0; r < 8; r++) keys[r * S_LEN + k] = 0u;
        }
    }
    __syncthreads();

    int topk = topk_ptr ? topk_ptr[0] : 512;
    if (topk > S_LEN) topk = S_LEN;

    // radix select per row (identical algorithm to validated kernel)
    for (int r = 0; r < 8; r++) {
        const int q = qbase + r;
        const unsigned* kr = keys + r * S_LEN;
        if (q + 1 > topk) {
            if (tid == 0) { s_prefix = 0u; s_kr = topk; }
            for (int pass = 0; pass < 4; pass++) {
                const int shift = 24 - pass * 8;
                __syncthreads();
                hist[tid] = 0u;
                __syncthreads();
                const unsigned pref = s_prefix;
                for (int k = tid; k < S_LEN; k += 256) {
                    unsigned key = kr[k];
                    bool match = (pass == 0) || ((key >> (shift + 8)) == (pref >> (shift + 8)));
                    if (match) atomicAdd(&hist[(key >> shift) & 255u], 1u);
                }
                __syncthreads();
                if (tid == 0) {
                    int kk = s_kr;
                    unsigned p = s_prefix;
                    for (int d = 255; d >= 0; d--) {
                        int c = (int)hist[d];
                        if (kk <= c) { s_prefix = p | ((unsigned)d << shift); break; }
                        kk -= c;
                    }
                    s_kr = kk;
                }
            }
            __syncthreads();
            if (tid == 0) s_thr[r] = s_prefix;
        } else {
            if (tid == 0) s_thr[r] = 0u;
        }
        __syncthreads();
    }

    // emit mask words for all 8 rows
    for (int w = tid; w < 8 * 64; w += 256) {
        int r = w >> 6, wi = w & 63;
        int q = qbase + r;
        unsigned thr = s_thr[r];
        const unsigned* kr = keys + r * S_LEN;
        unsigned word = 0u;
        int kb = wi * 32;
#pragma unroll
        for (int bit = 0; bit < 32; bit++) {
            int k = kb + bit;
            unsigned key = kr[k];
            if (k <= q && key >= thr && key != 0u) word |= (1u << bit);
        }
        mask[(size_t)(b * S_LEN + q) * 64 + wi] = word;
    }
}

// ---------------- flash operand prep (unchanged) --------------------------------
__global__ void prep_flash(const float* __restrict__ qkv,
                           bf16* __restrict__ q3, bf16* __restrict__ k3,
                           bf16* __restrict__ vt3, int BS)
{
    int idx = blockIdx.x * blockDim.x + threadIdx.x;
    if (idx >= BS * 1024) return;
    int d = idx & 63;
    int h = (idx >> 6) & 15;
    int tok = idx >> 10;
    int b = tok >> 11;
    int s = tok & (S_LEN - 1);

    size_t base = (size_t)tok * 3072 + h * 64 + d;
    float q = qkv[base];
    float k = qkv[base + 1024];
    float v = qkv[base + 2048];
    size_t bh = (size_t)b * N_HEADS + h;

    {
        bf16 hh = __float2bfloat16(q);
        bf16 ll = __float2bfloat16(q - __bfloat162float(hh));
        size_t o = (bh * S_LEN + s) * 192 + 3 * (size_t)d;
        q3[o] = hh; q3[o + 1] = ll; q3[o + 2] = hh;
    }
    {
        bf16 hh = __float2bfloat16(k);
        bf16 ll = __float2bfloat16(k - __bfloat162float(hh));
        size_t o = (bh * S_LEN + s) * 192 + 3 * (size_t)d;
        k3[o] = hh; k3[o + 1] = hh; k3[o + 2] = ll;
    }
    {
        bf16 hh = __float2bfloat16(v);
        bf16 ll = __float2bfloat16(v - __bfloat162float(hh));
        size_t o = (bh * 64 + d) * (size_t)(3 * S_LEN) + 3 * (size_t)s;
        vt3[o] = hh; vt3[o + 1] = hh; vt3[o + 2] = ll;
    }
}

// ---------------- tensor-core masked flash v2 ------------------------------------
// 128 q-rows x 1 head per block, 256 threads (8 warps, warp w owns rows 16w..).
// Double-buffered K/V tiles (cp.async wait_group 1 keeps one tile in flight).
#define FSTR  200                  // bf16 per smem row (400B, conflict-free ldsm)
#define FSTR2 400                  // bytes per row
#define OQ    0
#define OK0   (128 * FSTR)
#define OK1   (OK0 + 64 * FSTR)
#define OV0   (OK1 + 64 * FSTR)
#define OV1   (OV0 + 64 * FSTR)
#define OP    (OV1 + 64 * FSTR)
#define FSMEM ((OP + 128 * FSTR) * 2)   // 204800 bytes

__global__ __launch_bounds__(256) void flash_mma2(
    const bf16* __restrict__ q3, const bf16* __restrict__ k3,
    const bf16* __restrict__ vt3, const unsigned* __restrict__ mask,
    float* __restrict__ attn)
{
    extern __shared__ __align__(16) bf16 sm[];
    const int tid  = threadIdx.x;
    const int warp = tid >> 5, lane = tid & 31;
    const int qt = gridDim.x - 1 - blockIdx.x;   // largest-work-first
    const int h = blockIdx.y, b = blockIdx.z;

    const uint32_t sbase = (uint32_t)__cvta_generic_to_shared(sm);
    const uint32_t sQ = sbase + OQ * 2;
    const uint32_t sP = sbase + OP * 2;
    bf16* Psp = sm + OP;

    const size_t bh = (size_t)b * N_HEADS + h;
    const bf16* q3g  = q3  + (bh * S_LEN + (size_t)qt * 128) * 192;
    const bf16* k3g  = k3  + bh * S_LEN * 192;
    const bf16* vt3g = vt3 + bh * 64 * (size_t)(3 * S_LEN);

    // Q tile: 128 rows x 24 16B-chunks  (group 0)
    for (int c = tid; c < 3072; c += 256) {
        int row = c / 24, k16 = c % 24;
        CP16(sQ + row * FSTR2 + k16 * 16, q3g + (size_t)row * 192 + k16 * 8);
    }
    CPCOMMIT();

    const int ktmax = 2 * qt + 1;

    // K/V tile 0 into buffer 0  (group 1)
    for (int c = tid; c < 3072; c += 256) {
        if (c < 1536) {
            int row = c / 24, k16 = c % 24;
            CP16(sbase + OK0 * 2 + row * FSTR2 + k16 * 16,
                 k3g + (size_t)row * 192 + k16 * 8);
        } else {
            int cc = c - 1536;
            int drow = cc / 24, k16 = cc % 24;
            CP16(sbase + OV0 * 2 + drow * FSTR2 + k16 * 16,
                 vt3g + (size_t)drow * (3 * S_LEN) + k16 * 8);
        }
    }
    CPCOMMIT();

    float O[8][4];
#pragma unroll
    for (int i = 0; i < 8; i++)
#pragma unroll
        for (int j = 0; j < 4; j++) O[i][j] = 0.f;
    float m0 = -1e30f, m1 = -1e30f, l0 = 0.f, l1 = 0.f;

    const int r0 = warp * 16 + (lane >> 2);
    const int q0 = qt * 128 + r0, q1 = q0 + 8;
    const unsigned* mrow0 = mask + ((size_t)b * S_LEN + q0) * 64;
    const unsigned* mrow1 = mask + ((size_t)b * S_LEN + q1) * 64;

    const uint32_t aoff = (uint32_t)((warp * 16 + (lane & 15)) * FSTR2 + ((lane >> 4) << 3) * 2);
    const int browo = (lane & 7) + ((lane >> 4) << 3);
    const uint32_t bcol = (uint32_t)((((lane >> 3) & 1) << 3) * 2);

    for (int kt = 0; kt <= ktmax; kt++) {
        const int buf = kt & 1;
        if (kt < ktmax) {
            // prefetch tile kt+1 into buf^1 (safe: end-of-iter sync passed)
            const uint32_t dK = sbase + (buf ? OK0 : OK1) * 2;
            const uint32_t dV = sbase + (buf ? OV0 : OV1) * 2;
            const size_t kro = (size_t)(kt + 1) * 64;
            for (int c = tid; c < 3072; c += 256) {
                if (c < 1536) {
                    int row = c / 24, k16 = c % 24;
                    CP16(dK + row * FSTR2 + k16 * 16,
                         k3g + (kro + row) * 192 + k16 * 8);
                } else {
                    int cc = c - 1536;
                    int drow = cc / 24, k16 = cc % 24;
                    CP16(dV + drow * FSTR2 + k16 * 16,
                         vt3g + (size_t)drow * (3 * S_LEN) + (kt + 1) * 192 + k16 * 8);
                }
            }
            CPCOMMIT();
            CPWAIT1();
        } else {
            CPWAIT0();
        }
        __syncthreads();

        const uint32_t sKb = sbase + (buf ? OK1 : OK0) * 2;
        const uint32_t sVb = sbase + (buf ? OV1 : OV0) * 2;

        // S = Q K^T
        float S_[8][4];
#pragma unroll
        for (int i = 0; i < 8; i++)
#pragma unroll
            for (int j = 0; j < 4; j++) S_[i][j] = 0.f;

#pragma unroll
        for (int ks = 0; ks < 12; ks++) {
            uint32_t a[4];
            ldsm_x4(a, sQ + aoff + ks * 32);
#pragma unroll
            for (int nt2 = 0; nt2 < 4; nt2++) {
                uint32_t bb[4];
                ldsm_x4(bb, sKb + (uint32_t)((nt2 * 16 + browo) * FSTR2) + bcol + ks * 32);
                mma16816(S_[nt2 * 2],     a, bb);
                mma16816(S_[nt2 * 2 + 1], a, bb + 2);
            }
        }

        // mask + online softmax
        const unsigned mw00 = mrow0[kt * 2], mw01 = mrow0[kt * 2 + 1];
        const unsigned mw10 = mrow1[kt * 2], mw11 = mrow1[kt * 2 + 1];
        float mx0 = -1e30f, mx1 = -1e30f;
#pragma unroll
        for (int nf = 0; nf < 8; nf++) {
            int c = nf * 8 + 2 * (lane & 3);
#pragma unroll
            for (int e = 0; e < 2; e++) {
                int cc = c + e;
                unsigned w0 = (cc < 32 ? mw00 : mw01) >> (cc & 31);
                unsigned w1 = (cc < 32 ? mw10 : mw11) >> (cc & 31);
                float v0 = (w0 & 1u) ? S_[nf][e] * 0.125f     : -1e30f;
                float v1 = (w1 & 1u) ? S_[nf][e + 2] * 0.125f : -1e30f;
                S_[nf][e] = v0; S_[nf][e + 2] = v1;
                mx0 = fmaxf(mx0, v0); mx1 = fmaxf(mx1, v1);
            }
        }
        mx0 = fmaxf(mx0, __shfl_xor_sync(0xffffffffu, mx0, 1));
        mx0 = fmaxf(mx0, __shfl_xor_sync(0xffffffffu, mx0, 2));
        mx1 = fmaxf(mx1, __shfl_xor_sync(0xffffffffu, mx1, 1));
        mx1 = fmaxf(mx1, __shfl_xor_sync(0xffffffffu, mx1, 2));
        float mn0 = fmaxf(m0, mx0), mn1 = fmaxf(m1, mx1);
        float c0 = __expf(m0 - mn0), c1 = __expf(m1 - mn1);
        float ls0 = 0.f, ls1 = 0.f;
#pragma unroll
        for (int nf = 0; nf < 8; nf++) {
#pragma unroll
            for (int e = 0; e < 2; e++) {
                float p0 = (S_[nf][e]     > -1e29f) ? __expf(S_[nf][e]     - mn0) : 0.f;
                float p1 = (S_[nf][e + 2] > -1e29f) ? __expf(S_[nf][e + 2] - mn1) : 0.f;
                S_[nf][e] = p0; S_[nf][e + 2] = p1;
                ls0 += p0; ls1 += p1;
            }
        }
        ls0 += __shfl_xor_sync(0xffffffffu, ls0, 1);
        ls0 += __shfl_xor_sync(0xffffffffu, ls0, 2);
        ls1 += __shfl_xor_sync(0xffffffffu, ls1, 1);
        ls1 += __shfl_xor_sync(0xffffffffu, ls1, 2);
        l0 = l0 * c0 + ls0; l1 = l1 * c1 + ls1;
        m0 = mn0; m1 = mn1;
#pragma unroll
        for (int nf = 0; nf < 8; nf++) {
            O[nf][0] *= c0; O[nf][1] *= c0;
            O[nf][2] *= c1; O[nf][3] *= c1;
        }

        // P -> smem, A3 pattern (h,l,h); warp-private rows
#pragma unroll
        for (int nf = 0; nf < 8; nf++) {
            int c = nf * 8 + 2 * (lane & 3);
#pragma unroll
            for (int e = 0; e < 2; e++) {
                float p = S_[nf][e];
                bf16 hh = __float2bfloat16(p);
                bf16 ll = __float2bfloat16(p - __bfloat162float(hh));
                int o = r0 * FSTR + 3 * (c + e);
                Psp[o] = hh; Psp[o + 1] = ll; Psp[o + 2] = hh;

                p = S_[nf][e + 2];
                hh = __float2bfloat16(p);
                ll = __float2bfloat16(p - __bfloat162float(hh));
                o = (r0 + 8) * FSTR + 3 * (c + e);
                Psp[o] = hh; Psp[o + 1] = ll; Psp[o + 2] = hh;
            }
        }
        __syncwarp();

        // O += P V
#pragma unroll
        for (int ks = 0; ks < 12; ks++) {
            uint32_t a[4];
            ldsm_x4(a, sP + aoff + ks * 32);
#pragma unroll
            for (int nt2 = 0; nt2 < 4; nt2++) {
                uint32_t bb[4];
                ldsm_x4(bb, sVb + (uint32_t)((nt2 * 16 + browo) * FSTR2) + bcol + ks * 32);
                mma16816(O[nt2 * 2],     a, bb);
                mma16816(O[nt2 * 2 + 1], a, bb + 2);
            }
        }
        __syncthreads();   // all warps done reading K/V/P before next prefetch
    }

    float inv0 = 1.0f / l0, inv1 = 1.0f / l1;
    float* out0 = attn + ((size_t)b * S_LEN + q0) * D_MODEL + h * 64;
    float* out1 = attn + ((size_t)b * S_LEN + q1) * D_MODEL + h * 64;
#pragma unroll
    for (int nf = 0; nf < 8; nf++) {
        int c = nf * 8 + 2 * (lane & 3);
        *(float2*)(out0 + c) = make_float2(O[nf][0] * inv0, O[nf][1] * inv0);
        *(float2*)(out1 + c) = make_float2(O[nf][2] * inv1, O[nf][3] * inv1);
    }
}

// ---------------- launcher ------------------------------------------------------
extern "C" void kernel_launch(void* const* d_in, const int* in_sizes, int n_in,
                              void* d_out, int out_size)
{
    const float* x    = nullptr;
    const float* Wqkv = nullptr;
    const float* Wo   = nullptr;
    const float* Wiq  = nullptr;
    const float* Wik  = nullptr;
    const int*   topk = nullptr;
    for (int i = 0; i < n_in; i++) {
        int sz = in_sizes[i];
        if      (sz == D_MODEL * 3 * D_MODEL)       Wqkv = (const float*)d_in[i];
        else if (sz == D_MODEL * D_MODEL)           Wo   = (const float*)d_in[i];
        else if (sz == D_MODEL * IDX_D) { if (!Wiq) Wiq  = (const float*)d_in[i];
                                          else      Wik  = (const float*)d_in[i]; }
        else if (sz <= 4)                           topk = (const int*)d_in[i];
        else                                        x    = (const float*)d_in[i];
    }

    const int BS = out_size / D_MODEL;
    const int Bn = BS / S_LEN;

    float *qkv, *iq, *ik, *attn; unsigned* mask;
    bf16 *x3, *attn3, *wqkv3, *wo3, *q3, *k3, *vt3;
    cudaGetSymbolAddress((void**)&qkv,   g_qkv);
    cudaGetSymbolAddress((void**)&iq,    g_iq);
    cudaGetSymbolAddress((void**)&ik,    g_ik);
    cudaGetSymbolAddress((void**)&attn,  g_attn);
    cudaGetSymbolAddress((void**)&mask,  g_mask);
    cudaGetSymbolAddress((void**)&x3,    g_x3);
    cudaGetSymbolAddress((void**)&attn3, g_attn3);
    cudaGetSymbolAddress((void**)&wqkv3, g_wqkv3);
    cudaGetSymbolAddress((void**)&wo3,   g_wo3);
    cudaGetSymbolAddress((void**)&q3,    g_q3);
    cudaGetSymbolAddress((void**)&k3,    g_k3);
    cudaGetSymbolAddress((void**)&vt3,   g_vt3);

    const int K3 = 3 * D_MODEL;

    // splits for the tensor-core path
    split_a<<<(BS * D_MODEL + 255) / 256, 256>>>(x, x3, BS * D_MODEL);
    {
        dim3 blk(32, 8);
        split_bT<<<dim3(3 * D_MODEL / 32, D_MODEL / 32), blk>>>(Wqkv, wqkv3, D_MODEL, 3 * D_MODEL);
        split_bT<<<dim3(D_MODEL / 32, D_MODEL / 32), blk>>>(Wo, wo3, D_MODEL, D_MODEL);
    }

    // QKV projection on tensor cores
    mma_gemm<<<dim3(3 * D_MODEL / BNg, BS / BMg), 256>>>(x3, wqkv3, qkv, BS, 3 * D_MODEL, K3);

    // selection path: exact fp32 projections (iq + ik fused into one launch)
    sgemm_nn2<<<dim3(IDX_D / 128, BS / 128, 2), 256>>>(x, Wiq, iq, Wik, ik, BS, IDX_D, D_MODEL);

    rope_kernel<<<(BS * 1024 + 255) / 256, 256>>>(qkv, BS);

    // exact scalar top-k, 8 rows per block
    cudaFuncSetAttribute(topk8_kernel, cudaFuncAttributeMaxDynamicSharedMemorySize,
                         (8 * 256 + 8 * 2048 + 256) * 4);
    topk8_kernel<<<BS / 8, 256, (8 * 256 + 8 * 2048 + 256) * 4>>>(iq, ik, topk, mask);

    // tensor-core flash v2
    prep_flash<<<(BS * 1024 + 255) / 256, 256>>>(qkv, q3, k3, vt3, BS);
    cudaFuncSetAttribute(flash_mma2, cudaFuncAttributeMaxDynamicSharedMemorySize, FSMEM);
    flash_mma2<<<dim3(S_LEN / 128, N_HEADS, Bn), 256, FSMEM>>>(q3, k3, vt3, mask, attn);

    // output projection on tensor cores
    split_a<<<(BS * D_MODEL + 255) / 256, 256>>>(attn, attn3, BS * D_MODEL);
    mma_gemm<<<dim3(D_MODEL / BNg, BS / BMg), 256>>>(attn3, wo3, (float*)d_out, BS, D_MODEL, K3);
}

// round 9
// speedup vs baseline: 2.5173x; 1.0348x over previous
#include <cuda_runtime.h>
#include <cuda_bf16.h>
#include <cstdint>
#include <math.h>

#define S_LEN   2048
#define D_MODEL 1024
#define N_HEADS 16
#define IDX_D   256
#define MAXB    2
#define BS_MAX  (MAXB * S_LEN)

typedef __nv_bfloat16 bf16;

// ---------------- scratch (static device globals; no allocation) ----------------
__device__ float    g_qkv [(size_t)BS_MAX * 3 * D_MODEL];
__device__ float    g_iq  [(size_t)BS_MAX * IDX_D];
__device__ float    g_ik  [(size_t)BS_MAX * IDX_D];
__device__ float    g_attn[(size_t)BS_MAX * D_MODEL];
__device__ unsigned g_mask[(size_t)BS_MAX * (S_LEN / 32)];

__device__ __align__(16) bf16 g_x3   [(size_t)BS_MAX * 3 * D_MODEL];
__device__ __align__(16) bf16 g_attn3[(size_t)BS_MAX * 3 * D_MODEL];
__device__ __align__(16) bf16 g_wqkv3[(size_t)(3 * D_MODEL) * 3 * D_MODEL];
__device__ __align__(16) bf16 g_wo3  [(size_t)D_MODEL * 3 * D_MODEL];

// flash operands (x3)
__device__ __align__(16) bf16 g_q3 [(size_t)MAXB * N_HEADS * S_LEN * 192];
__device__ __align__(16) bf16 g_k3 [(size_t)MAXB * N_HEADS * S_LEN * 192];
__device__ __align__(16) bf16 g_vt3[(size_t)MAXB * N_HEADS * 64 * 3 * S_LEN];

// ---------------- bf16x3 split conversions --------------------------------------
__global__ void split_a(const float* __restrict__ s, bf16* __restrict__ d, int n)
{
    int i = blockIdx.x * blockDim.x + threadIdx.x;
    if (i >= n) return;
    float v = s[i];
    bf16 h = __float2bfloat16(v);
    bf16 l = __float2bfloat16(v - __bfloat162float(h));
    d[3 * i] = h; d[3 * i + 1] = l; d[3 * i + 2] = h;
}

__global__ void split_bT(const float* __restrict__ W, bf16* __restrict__ out,
                         int K, int N)
{
    __shared__ float t[32][33];
    int n0 = blockIdx.x * 32, k0 = blockIdx.y * 32;
    int tx = threadIdx.x, ty = threadIdx.y;   // block (32,8)
    for (int i = ty; i < 32; i += 8)
        t[i][tx] = W[(size_t)(k0 + i) * N + n0 + tx];
    __syncthreads();
    for (int r = ty; r < 32; r += 8) {
        float v = t[tx][r];
        bf16 h = __float2bfloat16(v);
        bf16 l = __float2bfloat16(v - __bfloat162float(h));
        size_t o = (size_t)(n0 + r) * (3 * K) + 3 * (size_t)(k0 + tx);
        out[o] = h; out[o + 1] = h; out[o + 2] = l;
    }
}

// ---------------- tensor-core NT GEMM (unchanged, validated) --------------------
#define BMg 128
#define BNg 128
#define BKg 32

__device__ __forceinline__ void ldsm_x4(uint32_t* r, uint32_t a) {
    asm volatile("ldmatrix.sync.aligned.m8n8.x4.shared.b16 {%0,%1,%2,%3}, [%4];"
                 : "=r"(r[0]), "=r"(r[1]), "=r"(r[2]), "=r"(r[3]) : "r"(a));
}
__device__ __forceinline__ void ldsm_x2(uint32_t* r, uint32_t a) {
    asm volatile("ldmatrix.sync.aligned.m8n8.x2.shared.b16 {%0,%1}, [%2];"
                 : "=r"(r[0]), "=r"(r[1]) : "r"(a));
}
__device__ __forceinline__ void mma16816(float* c, const uint32_t* a, const uint32_t* b) {
    asm volatile("mma.sync.aligned.m16n8k16.row.col.f32.bf16.bf16.f32 "
                 "{%0,%1,%2,%3},{%4,%5,%6,%7},{%8,%9},{%0,%1,%2,%3};"
                 : "+f"(c[0]), "+f"(c[1]), "+f"(c[2]), "+f"(c[3])
                 : "r"(a[0]), "r"(a[1]), "r"(a[2]), "r"(a[3]), "r"(b[0]), "r"(b[1]));
}
#define CP16(sa, ga) asm volatile("cp.async.cg.shared.global [%0], [%1], 16;\n" :: "r"(sa), "l"(ga))
#define CPCOMMIT()   asm volatile("cp.async.commit_group;\n" ::: "memory")
#define CPWAIT0()    asm volatile("cp.async.wait_group 0;\n" ::: "memory")
#define CPWAIT1()    asm volatile("cp.async.wait_group 1;\n" ::: "memory")

__global__ __launch_bounds__(256) void mma_gemm(
    const bf16* __restrict__ A, const bf16* __restrict__ B, float* __restrict__ C,
    int M, int N, int K)
{
    const int bx = blockIdx.x, by = blockIdx.y;

    __shared__ bf16 As[2][BMg][40];
    __shared__ bf16 Bs[2][BNg][40];

    const int tid  = threadIdx.x;
    const int warp = tid >> 5, lane = tid & 31;
    const int wm = warp & 1, wn = warp >> 1;

    const uint32_t sA = (uint32_t)__cvta_generic_to_shared(&As[0][0][0]);
    const uint32_t sB = (uint32_t)__cvta_generic_to_shared(&Bs[0][0][0]);
    const uint32_t BUFB = BMg * 40 * 2;

    const int ldrow = tid >> 2;
    const int ldch  = (tid & 3) * 8;

    float acc[4][4][4];
#pragma unroll
    for (int i = 0; i < 4; i++)
#pragma unroll
        for (int j = 0; j < 4; j++)
#pragma unroll
            for (int t = 0; t < 4; t++) acc[i][j][t] = 0.f;

#pragma unroll
    for (int h = 0; h < 2; h++) {
        int row = ldrow + h * 64;
        CP16(sA + (uint32_t)(row * 40 + ldch) * 2,
             A + (size_t)(by * BMg + row) * K + ldch);
        CP16(sB + (uint32_t)(row * 40 + ldch) * 2,
             B + (size_t)(bx * BNg + row) * K + ldch);
    }
    CPCOMMIT();
    CPWAIT0();
    __syncthreads();

    const int KT = K / BKg;
    int buf = 0;
    for (int kt = 0; kt < KT; kt++) {
        if (kt + 1 < KT) {
            int k0 = (kt + 1) * BKg;
#pragma unroll
            for (int h = 0; h < 2; h++) {
                int row = ldrow + h * 64;
                CP16(sA + (buf ^ 1) * BUFB + (uint32_t)(row * 40 + ldch) * 2,
                     A + (size_t)(by * BMg + row) * K + k0 + ldch);
                CP16(sB + (buf ^ 1) * BUFB + (uint32_t)(row * 40 + ldch) * 2,
                     B + (size_t)(bx * BNg + row) * K + k0 + ldch);
            }
            CPCOMMIT();
        }

#pragma unroll
        for (int ks = 0; ks < BKg; ks += 16) {
            uint32_t af[4][4], bfr[4][2];
            const int arow = wm * 64 + (lane & 15);
            const int acol = ks + ((lane >> 4) << 3);
#pragma unroll
            for (int mt = 0; mt < 4; mt++)
                ldsm_x4(af[mt], sA + buf * BUFB +
                        (uint32_t)((arow + mt * 16) * 40 + acol) * 2);
            const int brow = wn * 32 + (lane & 7);
            const int bcol = ks + (((lane >> 3) & 1) << 3);
#pragma unroll
            for (int nt = 0; nt < 4; nt++)
                ldsm_x2(bfr[nt], sB + buf * BUFB +
                        (uint32_t)((brow + nt * 8) * 40 + bcol) * 2);
#pragma unroll
            for (int mt = 0; mt < 4; mt++)
#pragma unroll
                for (int nt = 0; nt < 4; nt++)
                    mma16816(acc[mt][nt], af[mt], bfr[nt]);
        }

        if (kt + 1 < KT) {
            CPWAIT0();
            __syncthreads();
            buf ^= 1;
        }
    }

#pragma unroll
    for (int mt = 0; mt < 4; mt++) {
#pragma unroll
        for (int nt = 0; nt < 4; nt++) {
            int row = by * BMg + wm * 64 + mt * 16 + (lane >> 2);
            int col = bx * BNg + wn * 32 + nt * 8 + (lane & 3) * 2;
            float2 v0 = make_float2(acc[mt][nt][0], acc[mt][nt][1]);
            float2 v1 = make_float2(acc[mt][nt][2], acc[mt][nt][3]);
            *(float2*)&C[(size_t)row * N + col]       = v0;
            *(float2*)&C[(size_t)(row + 8) * N + col] = v1;
        }
    }
}

// ---------------- fp32 SGEMM, dual-output (selection path, validated) -----------
__global__ __launch_bounds__(256) void sgemm_nn2(const float* __restrict__ A,
                                                 const float* __restrict__ B1,
                                                 float* __restrict__ C1,
                                                 const float* __restrict__ B2,
                                                 float* __restrict__ C2,
                                                 int M, int N, int K)
{
    const float* B = blockIdx.z ? B2 : B1;
    float*       C = blockIdx.z ? C2 : C1;

    __shared__ float As[2][8][128];
    __shared__ float Bs[2][8][128];

    const int tid = threadIdx.x;
    const int bx = blockIdx.x, by = blockIdx.y;
    const int tx = tid & 15, ty = tid >> 4;

    const int arow = tid >> 1, ak = (tid & 1) * 4;
    const int brow = tid >> 5, bcol = (tid & 31) * 4;

    const float* Ag = A + (size_t)(by * 128 + arow) * K + ak;
    const float* Bg = B + (size_t)brow * N + bx * 128 + bcol;

    float4 af = *(const float4*)Ag;
    float4 bf = *(const float4*)Bg;
    As[0][ak + 0][arow] = af.x;
    As[0][ak + 1][arow] = af.y;
    As[0][ak + 2][arow] = af.z;
    As[0][ak + 3][arow] = af.w;
    *(float4*)&Bs[0][brow][bcol] = bf;
    __syncthreads();

    float acc[8][8];
#pragma unroll
    for (int i = 0; i < 8; i++)
#pragma unroll
        for (int j = 0; j < 8; j++) acc[i][j] = 0.f;

    int buf = 0;
    for (int k0 = 8; k0 <= K; k0 += 8) {
        const bool next = (k0 < K);
        if (next) {
            af = *(const float4*)(Ag + k0);
            bf = *(const float4*)(Bg + (size_t)k0 * N);
        }
#pragma unroll
        for (int kk = 0; kk < 8; kk++) {
            float a[8], b[8];
            *(float4*)&a[0] = *(const float4*)&As[buf][kk][ty * 8];
            *(float4*)&a[4] = *(const float4*)&As[buf][kk][ty * 8 + 4];
            *(float4*)&b[0] = *(const float4*)&Bs[buf][kk][tx * 8];
            *(float4*)&b[4] = *(const float4*)&Bs[buf][kk][tx * 8 + 4];
#pragma unroll
            for (int i = 0; i < 8; i++)
#pragma unroll
                for (int j = 0; j < 8; j++)
                    acc[i][j] += a[i] * b[j];
        }
        if (next) {
            buf ^= 1;
            As[buf][ak + 0][arow] = af.x;
            As[buf][ak + 1][arow] = af.y;
            As[buf][ak + 2][arow] = af.z;
            As[buf][ak + 3][arow] = af.w;
            *(float4*)&Bs[buf][brow][bcol] = bf;
            __syncthreads();
        }
    }

#pragma unroll
    for (int i = 0; i < 8; i++) {
        float* Crow = C + (size_t)(by * 128 + ty * 8 + i) * N + bx * 128 + tx * 8;
        *(float4*)Crow       = make_float4(acc[i][0], acc[i][1], acc[i][2], acc[i][3]);
        *(float4*)(Crow + 4) = make_float4(acc[i][4], acc[i][5], acc[i][6], acc[i][7]);
    }
}

// ---------------- RoPE ----------------------------------------------------------
__global__ void rope_kernel(float* __restrict__ qkv, int BS)
{
    int idx = blockIdx.x * blockDim.x + threadIdx.x;
    if (idx >= BS * 1024) return;
    int i   = idx & 31;
    int h   = (idx >> 5) & 15;
    int qk  = (idx >> 9) & 1;
    int tok = idx >> 10;
    int s   = tok & (S_LEN - 1);

    float ex   = (float)(2 * i) * (1.0f / 64.0f);
    float freq = powf(10000.0f, -ex);
    float ang  = (float)s * freq;
    float sn, cs;
    sincosf(ang, &sn, &cs);

    size_t base = (size_t)tok * 3072 + (size_t)qk * 1024 + h * 64 + 2 * i;
    float x1 = qkv[base], x2 = qkv[base + 1];
    qkv[base]     = x1 * cs - x2 * sn;
    qkv[base + 1] = x1 * sn + x2 * cs;
}

// ---------------- top-k: 8 query rows per block (validated) ---------------------
__global__ __launch_bounds__(256) void topk8_kernel(const float* __restrict__ iq,
                                                    const float* __restrict__ ik,
                                                    const int* __restrict__ topk_ptr,
                                                    unsigned* __restrict__ mask)
{
    extern __shared__ __align__(16) unsigned dsm[];
    float*    iqs  = (float*)dsm;             // 8 * 256 floats
    unsigned* keys = dsm + 8 * 256;           // 8 * 2048
    unsigned* hist = keys + 8 * 2048;         // 256
    __shared__ unsigned s_prefix;
    __shared__ int      s_kr;
    __shared__ unsigned s_thr[8];

    const int tid = threadIdx.x;
    const int gid = blockIdx.x;
    const int b = (gid * 8) >> 11;
    const int qbase = (gid * 8) & (S_LEN - 1);
    const int qmax = qbase + 7;

    for (int i = tid; i < 8 * IDX_D; i += 256) {
        int r = i >> 8, c = i & 255;
        iqs[i] = iq[(size_t)(b * S_LEN + qbase + r) * IDX_D + c];
    }
    __syncthreads();

    for (int k = tid; k < S_LEN; k += 256) {
        if (k <= qmax) {
            const float4* ikr = (const float4*)(ik + (size_t)(b * S_LEN + k) * IDX_D);
            float acc[8];
#pragma unroll
            for (int r = 0; r < 8; r++) acc[r] = 0.f;
#pragma unroll 4
            for (int i = 0; i < 64; i++) {
                float4 c = ikr[i];
#pragma unroll
                for (int r = 0; r < 8; r++) {
                    float4 a = ((const float4*)(iqs + r * 256))[i];
                    acc[r] += a.x * c.x + a.y * c.y + a.z * c.z + a.w * c.w;
                }
            }
#pragma unroll
            for (int r = 0; r < 8; r++) {
                unsigned key = 0u;
                if (k <= qbase + r) {
                    unsigned u = __float_as_uint(acc[r]);
                    key = (u & 0x80000000u) ? ~u : (u | 0x80000000u);
                }
                keys[r * S_LEN + k] = key;
            }
        } else {
#pragma unroll
            for (int r = 0; r < 8; r++) keys[r * S_LEN + k] = 0u;
        }
    }
    __syncthreads();

    int topk = topk_ptr ? topk_ptr[0] : 512;
    if (topk > S_LEN) topk = S_LEN;

    for (int r = 0; r < 8; r++) {
        const int q = qbase + r;
        const unsigned* kr = keys + r * S_LEN;
        if (q + 1 > topk) {
            if (tid == 0) { s_prefix = 0u; s_kr = topk; }
            for (int pass = 0; pass < 4; pass++) {
                const int shift = 24 - pass * 8;
                __syncthreads();
                hist[tid] = 0u;
                __syncthreads();
                const unsigned pref = s_prefix;
                for (int k = tid; k < S_LEN; k += 256) {
                    unsigned key = kr[k];
                    bool match = (pass == 0) || ((key >> (shift + 8)) == (pref >> (shift + 8)));
                    if (match) atomicAdd(&hist[(key >> shift) & 255u], 1u);
                }
                __syncthreads();
                if (tid == 0) {
                    int kk = s_kr;
                    unsigned p = s_prefix;
                    for (int d = 255; d >= 0; d--) {
                        int c = (int)hist[d];
                        if (kk <= c) { s_prefix = p | ((unsigned)d << shift); break; }
                        kk -= c;
                    }
                    s_kr = kk;
                }
            }
            __syncthreads();
            if (tid == 0) s_thr[r] = s_prefix;
        } else {
            if (tid == 0) s_thr[r] = 0u;
        }
        __syncthreads();
    }

    for (int w = tid; w < 8 * 64; w += 256) {
        int r = w >> 6, wi = w & 63;
        int q = qbase + r;
        unsigned thr = s_thr[r];
        const unsigned* kr = keys + r * S_LEN;
        unsigned word = 0u;
        int kb = wi * 32;
#pragma unroll
        for (int bit = 0; bit < 32; bit++) {
            int k = kb + bit;
            unsigned key = kr[k];
            if (k <= q && key >= thr && key != 0u) word |= (1u << bit);
        }
        mask[(size_t)(b * S_LEN + q) * 64 + wi] = word;
    }
}

// ---------------- flash operand prep (unchanged) --------------------------------
__global__ void prep_flash(const float* __restrict__ qkv,
                           bf16* __restrict__ q3, bf16* __restrict__ k3,
                           bf16* __restrict__ vt3, int BS)
{
    int idx = blockIdx.x * blockDim.x + threadIdx.x;
    if (idx >= BS * 1024) return;
    int d = idx & 63;
    int h = (idx >> 6) & 15;
    int tok = idx >> 10;
    int b = tok >> 11;
    int s = tok & (S_LEN - 1);

    size_t base = (size_t)tok * 3072 + h * 64 + d;
    float q = qkv[base];
    float k = qkv[base + 1024];
    float v = qkv[base + 2048];
    size_t bh = (size_t)b * N_HEADS + h;

    {
        bf16 hh = __float2bfloat16(q);
        bf16 ll = __float2bfloat16(q - __bfloat162float(hh));
        size_t o = (bh * S_LEN + s) * 192 + 3 * (size_t)d;
        q3[o] = hh; q3[o + 1] = ll; q3[o + 2] = hh;
    }
    {
        bf16 hh = __float2bfloat16(k);
        bf16 ll = __float2bfloat16(k - __bfloat162float(hh));
        size_t o = (bh * S_LEN + s) * 192 + 3 * (size_t)d;
        k3[o] = hh; k3[o + 1] = hh; k3[o + 2] = ll;
    }
    {
        bf16 hh = __float2bfloat16(v);
        bf16 ll = __float2bfloat16(v - __bfloat162float(hh));
        size_t o = (bh * 64 + d) * (size_t)(3 * S_LEN) + 3 * (size_t)s;
        vt3[o] = hh; vt3[o + 1] = hh; vt3[o + 2] = ll;
    }
}

// ---------------- tensor-core masked flash v2 (unchanged, validated) -------------
#define FSTR  200
#define FSTR2 400
#define OQ    0
#define OK0   (128 * FSTR)
#define OK1   (OK0 + 64 * FSTR)
#define OV0   (OK1 + 64 * FSTR)
#define OV1   (OV0 + 64 * FSTR)
#define OP    (OV1 + 64 * FSTR)
#define FSMEM ((OP + 128 * FSTR) * 2)   // 204800 bytes

__global__ __launch_bounds__(256) void flash_mma2(
    const bf16* __restrict__ q3, const bf16* __restrict__ k3,
    const bf16* __restrict__ vt3, const unsigned* __restrict__ mask,
    float* __restrict__ attn)
{
    extern __shared__ __align__(16) bf16 sm[];
    const int tid  = threadIdx.x;
    const int warp = tid >> 5, lane = tid & 31;
    const int qt = gridDim.x - 1 - blockIdx.x;
    const int h = blockIdx.y, b = blockIdx.z;

    const uint32_t sbase = (uint32_t)__cvta_generic_to_shared(sm);
    const uint32_t sQ = sbase + OQ * 2;
    const uint32_t sP = sbase + OP * 2;
    bf16* Psp = sm + OP;

    const size_t bh = (size_t)b * N_HEADS + h;
    const bf16* q3g  = q3  + (bh * S_LEN + (size_t)qt * 128) * 192;
    const bf16* k3g  = k3  + bh * S_LEN * 192;
    const bf16* vt3g = vt3 + bh * 64 * (size_t)(3 * S_LEN);

    for (int c = tid; c < 3072; c += 256) {
        int row = c / 24, k16 = c % 24;
        CP16(sQ + row * FSTR2 + k16 * 16, q3g + (size_t)row * 192 + k16 * 8);
    }
    CPCOMMIT();

    const int ktmax = 2 * qt + 1;

    for (int c = tid; c < 3072; c += 256) {
        if (c < 1536) {
            int row = c / 24, k16 = c % 24;
            CP16(sbase + OK0 * 2 + row * FSTR2 + k16 * 16,
                 k3g + (size_t)row * 192 + k16 * 8);
        } else {
            int cc = c - 1536;
            int drow = cc / 24, k16 = cc % 24;
            CP16(sbase + OV0 * 2 + drow * FSTR2 + k16 * 16,
                 vt3g + (size_t)drow * (3 * S_LEN) + k16 * 8);
        }
    }
    CPCOMMIT();

    float O[8][4];
#pragma unroll
    for (int i = 0; i < 8; i++)
#pragma unroll
        for (int j = 0; j < 4; j++) O[i][j] = 0.f;
    float m0 = -1e30f, m1 = -1e30f, l0 = 0.f, l1 = 0.f;

    const int r0 = warp * 16 + (lane >> 2);
    const int q0 = qt * 128 + r0, q1 = q0 + 8;
    const unsigned* mrow0 = mask + ((size_t)b * S_LEN + q0) * 64;
    const unsigned* mrow1 = mask + ((size_t)b * S_LEN + q1) * 64;

    const uint32_t aoff = (uint32_t)((warp * 16 + (lane & 15)) * FSTR2 + ((lane >> 4) << 3) * 2);
    const int browo = (lane & 7) + ((lane >> 4) << 3);
    const uint32_t bcol = (uint32_t)((((lane >> 3) & 1) << 3) * 2);

    for (int kt = 0; kt <= ktmax; kt++) {
        const int buf = kt & 1;
        if (kt < ktmax) {
            const uint32_t dK = sbase + (buf ? OK0 : OK1) * 2;
            const uint32_t dV = sbase + (buf ? OV0 : OV1) * 2;
            const size_t kro = (size_t)(kt + 1) * 64;
            for (int c = tid; c < 3072; c += 256) {
                if (c < 1536) {
                    int row = c / 24, k16 = c % 24;
                    CP16(dK + row * FSTR2 + k16 * 16,
                         k3g + (kro + row) * 192 + k16 * 8);
                } else {
                    int cc = c - 1536;
                    int drow = cc / 24, k16 = cc % 24;
                    CP16(dV + drow * FSTR2 + k16 * 16,
                         vt3g + (size_t)drow * (3 * S_LEN) + (kt + 1) * 192 + k16 * 8);
                }
            }
            CPCOMMIT();
            CPWAIT1();
        } else {
            CPWAIT0();
        }
        __syncthreads();

        const uint32_t sKb = sbase + (buf ? OK1 : OK0) * 2;
        const uint32_t sVb = sbase + (buf ? OV1 : OV0) * 2;

        float S_[8][4];
#pragma unroll
        for (int i = 0; i < 8; i++)
#pragma unroll
            for (int j = 0; j < 4; j++) S_[i][j] = 0.f;

#pragma unroll
        for (int ks = 0; ks < 12; ks++) {
            uint32_t a[4];
            ldsm_x4(a, sQ + aoff + ks * 32);
#pragma unroll
            for (int nt2 = 0; nt2 < 4; nt2++) {
                uint32_t bb[4];
                ldsm_x4(bb, sKb + (uint32_t)((nt2 * 16 + browo) * FSTR2) + bcol + ks * 32);
                mma16816(S_[nt2 * 2],     a, bb);
                mma16816(S_[nt2 * 2 + 1], a, bb + 2);
            }
        }

        const unsigned mw00 = mrow0[kt * 2], mw01 = mrow0[kt * 2 + 1];
        const unsigned mw10 = mrow1[kt * 2], mw11 = mrow1[kt * 2 + 1];
        float mx0 = -1e30f, mx1 = -1e30f;
#pragma unroll
        for (int nf = 0; nf < 8; nf++) {
            int c = nf * 8 + 2 * (lane & 3);
#pragma unroll
            for (int e = 0; e < 2; e++) {
                int cc = c + e;
                unsigned w0 = (cc < 32 ? mw00 : mw01) >> (cc & 31);
                unsigned w1 = (cc < 32 ? mw10 : mw11) >> (cc & 31);
                float v0 = (w0 & 1u) ? S_[nf][e] * 0.125f     : -1e30f;
                float v1 = (w1 & 1u) ? S_[nf][e + 2] * 0.125f : -1e30f;
                S_[nf][e] = v0; S_[nf][e + 2] = v1;
                mx0 = fmaxf(mx0, v0); mx1 = fmaxf(mx1, v1);
            }
        }
        mx0 = fmaxf(mx0, __shfl_xor_sync(0xffffffffu, mx0, 1));
        mx0 = fmaxf(mx0, __shfl_xor_sync(0xffffffffu, mx0, 2));
        mx1 = fmaxf(mx1, __shfl_xor_sync(0xffffffffu, mx1, 1));
        mx1 = fmaxf(mx1, __shfl_xor_sync(0xffffffffu, mx1, 2));
        float mn0 = fmaxf(m0, mx0), mn1 = fmaxf(m1, mx1);
        float c0 = __expf(m0 - mn0), c1 = __expf(m1 - mn1);
        float ls0 = 0.f, ls1 = 0.f;
#pragma unroll
        for (int nf = 0; nf < 8; nf++) {
#pragma unroll
            for (int e = 0; e < 2; e++) {
                float p0 = (S_[nf][e]     > -1e29f) ? __expf(S_[nf][e]     - mn0) : 0.f;
                float p1 = (S_[nf][e + 2] > -1e29f) ? __expf(S_[nf][e + 2] - mn1) : 0.f;
                S_[nf][e] = p0; S_[nf][e + 2] = p1;
                ls0 += p0; ls1 += p1;
            }
        }
        ls0 += __shfl_xor_sync(0xffffffffu, ls0, 1);
        ls0 += __shfl_xor_sync(0xffffffffu, ls0, 2);
        ls1 += __shfl_xor_sync(0xffffffffu, ls1, 1);
        ls1 += __shfl_xor_sync(0xffffffffu, ls1, 2);
        l0 = l0 * c0 + ls0; l1 = l1 * c1 + ls1;
        m0 = mn0; m1 = mn1;
#pragma unroll
        for (int nf = 0; nf < 8; nf++) {
            O[nf][0] *= c0; O[nf][1] *= c0;
            O[nf][2] *= c1; O[nf][3] *= c1;
        }

#pragma unroll
        for (int nf = 0; nf < 8; nf++) {
            int c = nf * 8 + 2 * (lane & 3);
#pragma unroll
            for (int e = 0; e < 2; e++) {
                float p = S_[nf][e];
                bf16 hh = __float2bfloat16(p);
                bf16 ll = __float2bfloat16(p - __bfloat162float(hh));
                int o = r0 * FSTR + 3 * (c + e);
                Psp[o] = hh; Psp[o + 1] = ll; Psp[o + 2] = hh;

                p = S_[nf][e + 2];
                hh = __float2bfloat16(p);
                ll = __float2bfloat16(p - __bfloat162float(hh));
                o = (r0 + 8) * FSTR + 3 * (c + e);
                Psp[o] = hh; Psp[o + 1] = ll; Psp[o + 2] = hh;
            }
        }
        __syncwarp();

#pragma unroll
        for (int ks = 0; ks < 12; ks++) {
            uint32_t a[4];
            ldsm_x4(a, sP + aoff + ks * 32);
#pragma unroll
            for (int nt2 = 0; nt2 < 4; nt2++) {
                uint32_t bb[4];
                ldsm_x4(bb, sVb + (uint32_t)((nt2 * 16 + browo) * FSTR2) + bcol + ks * 32);
                mma16816(O[nt2 * 2],     a, bb);
                mma16816(O[nt2 * 2 + 1], a, bb + 2);
            }
        }
        __syncthreads();
    }

    float inv0 = 1.0f / l0, inv1 = 1.0f / l1;
    float* out0 = attn + ((size_t)b * S_LEN + q0) * D_MODEL + h * 64;
    float* out1 = attn + ((size_t)b * S_LEN + q1) * D_MODEL + h * 64;
#pragma unroll
    for (int nf = 0; nf < 8; nf++) {
        int c = nf * 8 + 2 * (lane & 3);
        *(float2*)(out0 + c) = make_float2(O[nf][0] * inv0, O[nf][1] * inv0);
        *(float2*)(out1 + c) = make_float2(O[nf][2] * inv1, O[nf][3] * inv1);
    }
}

// ---------------- launcher with fork/join stream overlap -------------------------
extern "C" void kernel_launch(void* const* d_in, const int* in_sizes, int n_in,
                              void* d_out, int out_size)
{
    // Lazily create the selection stream + events. The harness's first call is
    // the uncaptured correctness run, so creation happens outside graph capture;
    // afterwards these persist and only event-record/wait nodes enter the graph.
    static cudaStream_t s_sel = nullptr;
    static cudaEvent_t  ev_fork = nullptr, ev_join = nullptr;
    if (!s_sel) {
        cudaStreamCreateWithFlags(&s_sel, cudaStreamNonBlocking);
        cudaEventCreateWithFlags(&ev_fork, cudaEventDisableTiming);
        cudaEventCreateWithFlags(&ev_join, cudaEventDisableTiming);
    }

    const float* x    = nullptr;
    const float* Wqkv = nullptr;
    const float* Wo   = nullptr;
    const float* Wiq  = nullptr;
    const float* Wik  = nullptr;
    const int*   topk = nullptr;
    for (int i = 0; i < n_in; i++) {
        int sz = in_sizes[i];
        if      (sz == D_MODEL * 3 * D_MODEL)       Wqkv = (const float*)d_in[i];
        else if (sz == D_MODEL * D_MODEL)           Wo   = (const float*)d_in[i];
        else if (sz == D_MODEL * IDX_D) { if (!Wiq) Wiq  = (const float*)d_in[i];
                                          else      Wik  = (const float*)d_in[i]; }
        else if (sz <= 4)                           topk = (const int*)d_in[i];
        else                                        x    = (const float*)d_in[i];
    }

    const int BS = out_size / D_MODEL;
    const int Bn = BS / S_LEN;

    float *qkv, *iq, *ik, *attn; unsigned* mask;
    bf16 *x3, *attn3, *wqkv3, *wo3, *q3, *k3, *vt3;
    cudaGetSymbolAddress((void**)&qkv,   g_qkv);
    cudaGetSymbolAddress((void**)&iq,    g_iq);
    cudaGetSymbolAddress((void**)&ik,    g_ik);
    cudaGetSymbolAddress((void**)&attn,  g_attn);
    cudaGetSymbolAddress((void**)&mask,  g_mask);
    cudaGetSymbolAddress((void**)&x3,    g_x3);
    cudaGetSymbolAddress((void**)&attn3, g_attn3);
    cudaGetSymbolAddress((void**)&wqkv3, g_wqkv3);
    cudaGetSymbolAddress((void**)&wo3,   g_wo3);
    cudaGetSymbolAddress((void**)&q3,    g_q3);
    cudaGetSymbolAddress((void**)&k3,    g_k3);
    cudaGetSymbolAddress((void**)&vt3,   g_vt3);

    const int K3 = 3 * D_MODEL;

    cudaFuncSetAttribute(topk8_kernel, cudaFuncAttributeMaxDynamicSharedMemorySize,
                         (8 * 256 + 8 * 2048 + 256) * 4);
    cudaFuncSetAttribute(flash_mma2, cudaFuncAttributeMaxDynamicSharedMemorySize, FSMEM);

    // ---- fork: selection chain on s_sel (reads only x / Wiq / Wik / topk) ----
    cudaEventRecord(ev_fork, 0);
    cudaStreamWaitEvent(s_sel, ev_fork, 0);
    sgemm_nn2<<<dim3(IDX_D / 128, BS / 128, 2), 256, 0, s_sel>>>(
        x, Wiq, iq, Wik, ik, BS, IDX_D, D_MODEL);
    topk8_kernel<<<BS / 8, 256, (8 * 256 + 8 * 2048 + 256) * 4, s_sel>>>(
        iq, ik, topk, mask);
    cudaEventRecord(ev_join, s_sel);

    // ---- smooth chain on the main (capture) stream ----
    split_a<<<(BS * D_MODEL + 255) / 256, 256>>>(x, x3, BS * D_MODEL);
    {
        dim3 blk(32, 8);
        split_bT<<<dim3(3 * D_MODEL / 32, D_MODEL / 32), blk>>>(Wqkv, wqkv3, D_MODEL, 3 * D_MODEL);
        split_bT<<<dim3(D_MODEL / 32, D_MODEL / 32), blk>>>(Wo, wo3, D_MODEL, D_MODEL);
    }
    mma_gemm<<<dim3(3 * D_MODEL / BNg, BS / BMg), 256>>>(x3, wqkv3, qkv, BS, 3 * D_MODEL, K3);
    rope_kernel<<<(BS * 1024 + 255) / 256, 256>>>(qkv, BS);
    prep_flash<<<(BS * 1024 + 255) / 256, 256>>>(qkv, q3, k3, vt3, BS);

    // ---- join: flash needs the mask ----
    cudaStreamWaitEvent(0, ev_join, 0);
    flash_mma2<<<dim3(S_LEN / 128, N_HEADS, Bn), 256, FSMEM>>>(q3, k3, vt3, mask, attn);

    // output projection
    split_a<<<(BS * D_MODEL + 255) / 256, 256>>>(attn, attn3, BS * D_MODEL);
    mma_gemm<<<dim3(D_MODEL / BNg, BS / BMg), 256>>>(attn3, wo3, (float*)d_out, BS, D_MODEL, K3);
}

// round 11
// speedup vs baseline: 2.7208x; 1.0808x over previous
#include <cuda_runtime.h>
#include <cuda_bf16.h>
#include <cstdint>
#include <math.h>

#define S_LEN   2048
#define D_MODEL 1024
#define N_HEADS 16
#define IDX_D   256
#define MAXB    2
#define BS_MAX  (MAXB * S_LEN)

typedef __nv_bfloat16 bf16;

// ---------------- scratch (static device globals; no allocation) ----------------
__device__ float    g_qkv [(size_t)BS_MAX * 3 * D_MODEL];
__device__ float    g_iq  [(size_t)BS_MAX * IDX_D];
__device__ float    g_ik  [(size_t)BS_MAX * IDX_D];
__device__ float    g_attn[(size_t)BS_MAX * D_MODEL];
__device__ unsigned g_mask[(size_t)BS_MAX * (S_LEN / 32)];

__device__ __align__(16) bf16 g_x3   [(size_t)BS_MAX * 3 * D_MODEL];
__device__ __align__(16) bf16 g_attn3[(size_t)BS_MAX * 3 * D_MODEL];
__device__ __align__(16) bf16 g_wqkv3[(size_t)(3 * D_MODEL) * 3 * D_MODEL];
__device__ __align__(16) bf16 g_wo3  [(size_t)D_MODEL * 3 * D_MODEL];

// flash operands (x3)
__device__ __align__(16) bf16 g_q3 [(size_t)MAXB * N_HEADS * S_LEN * 192];
__device__ __align__(16) bf16 g_k3 [(size_t)MAXB * N_HEADS * S_LEN * 192];
__device__ __align__(16) bf16 g_vt3[(size_t)MAXB * N_HEADS * 64 * 3 * S_LEN];

// ---------------- bf16x3 split conversions --------------------------------------
__global__ void split_a(const float* __restrict__ s, bf16* __restrict__ d, int n)
{
    int i = blockIdx.x * blockDim.x + threadIdx.x;
    if (i >= n) return;
    float v = s[i];
    bf16 h = __float2bfloat16(v);
    bf16 l = __float2bfloat16(v - __bfloat162float(h));
    d[3 * i] = h; d[3 * i + 1] = l; d[3 * i + 2] = h;
}

__global__ void split_bT(const float* __restrict__ W, bf16* __restrict__ out,
                         int K, int N)
{
    __shared__ float t[32][33];
    int n0 = blockIdx.x * 32, k0 = blockIdx.y * 32;
    int tx = threadIdx.x, ty = threadIdx.y;   // block (32,8)
    for (int i = ty; i < 32; i += 8)
        t[i][tx] = W[(size_t)(k0 + i) * N + n0 + tx];
    __syncthreads();
    for (int r = ty; r < 32; r += 8) {
        float v = t[tx][r];
        bf16 h = __float2bfloat16(v);
        bf16 l = __float2bfloat16(v - __bfloat162float(h));
        size_t o = (size_t)(n0 + r) * (3 * K) + 3 * (size_t)(k0 + tx);
        out[o] = h; out[o + 1] = h; out[o + 2] = l;
    }
}

// ---------------- tensor-core NT GEMM, 3-stage cp.async pipeline ----------------
// Shared tiles live in DYNAMIC smem (3 buffers = 61440 B > 48 KB static cap).
#define BMg 128
#define BNg 128
#define BKg 32
#define GEMM_SMEM (3 * (BMg + BNg) * 40 * 2)   // 61440 bytes

__device__ __forceinline__ void ldsm_x4(uint32_t* r, uint32_t a) {
    asm volatile("ldmatrix.sync.aligned.m8n8.x4.shared.b16 {%0,%1,%2,%3}, [%4];"
                 : "=r"(r[0]), "=r"(r[1]), "=r"(r[2]), "=r"(r[3]) : "r"(a));
}
__device__ __forceinline__ void ldsm_x2(uint32_t* r, uint32_t a) {
    asm volatile("ldmatrix.sync.aligned.m8n8.x2.shared.b16 {%0,%1}, [%2];"
                 : "=r"(r[0]), "=r"(r[1]) : "r"(a));
}
__device__ __forceinline__ void mma16816(float* c, const uint32_t* a, const uint32_t* b) {
    asm volatile("mma.sync.aligned.m16n8k16.row.col.f32.bf16.bf16.f32 "
                 "{%0,%1,%2,%3},{%4,%5,%6,%7},{%8,%9},{%0,%1,%2,%3};"
                 : "+f"(c[0]), "+f"(c[1]), "+f"(c[2]), "+f"(c[3])
                 : "r"(a[0]), "r"(a[1]), "r"(a[2]), "r"(a[3]), "r"(b[0]), "r"(b[1]));
}
#define CP16(sa, ga) asm volatile("cp.async.cg.shared.global [%0], [%1], 16;\n" :: "r"(sa), "l"(ga))
#define CPCOMMIT()   asm volatile("cp.async.commit_group;\n" ::: "memory")
#define CPWAIT0()    asm volatile("cp.async.wait_group 0;\n" ::: "memory")
#define CPWAIT1()    asm volatile("cp.async.wait_group 1;\n" ::: "memory")

__global__ __launch_bounds__(256) void mma_gemm(
    const bf16* __restrict__ A, const bf16* __restrict__ B, float* __restrict__ C,
    int M, int N, int K)
{
    extern __shared__ __align__(16) bf16 gsm[];
    const int bx = blockIdx.x, by = blockIdx.y;

    const int tid  = threadIdx.x;
    const int warp = tid >> 5, lane = tid & 31;
    const int wm = warp & 1, wn = warp >> 1;

    const uint32_t BUFA  = BMg * 40 * 2;           // 10240 B
    const uint32_t BUFAB = (BMg + BNg) * 40 * 2;   // 20480 B per stage
    const uint32_t sbase = (uint32_t)__cvta_generic_to_shared(gsm);
    const uint32_t sA = sbase;
    const uint32_t sB = sbase + BUFA;

    const int ldrow = tid >> 2;
    const int ldch  = (tid & 3) * 8;

    float acc[4][4][4];
#pragma unroll
    for (int i = 0; i < 4; i++)
#pragma unroll
        for (int j = 0; j < 4; j++)
#pragma unroll
            for (int t = 0; t < 4; t++) acc[i][j][t] = 0.f;

    const int KT = K / BKg;    // >= 2 for all our shapes

    // prefetch tiles 0 and 1
#pragma unroll
    for (int pf = 0; pf < 2; pf++) {
        int k0 = pf * BKg;
#pragma unroll
        for (int h = 0; h < 2; h++) {
            int row = ldrow + h * 64;
            CP16(sA + pf * BUFAB + (uint32_t)(row * 40 + ldch) * 2,
                 A + (size_t)(by * BMg + row) * K + k0 + ldch);
            CP16(sB + pf * BUFAB + (uint32_t)(row * 40 + ldch) * 2,
                 B + (size_t)(bx * BNg + row) * K + k0 + ldch);
        }
        CPCOMMIT();
    }
    CPWAIT1();                 // tile 0 resident (tile 1 may be in flight)
    __syncthreads();

    for (int kt = 0; kt < KT; kt++) {
        const uint32_t bo = (uint32_t)(kt % 3) * BUFAB;

#pragma unroll
        for (int ks = 0; ks < BKg; ks += 16) {
            uint32_t af[4][4], bfr[4][2];
            const int arow = wm * 64 + (lane & 15);
            const int acol = ks + ((lane >> 4) << 3);
#pragma unroll
            for (int mt = 0; mt < 4; mt++)
                ldsm_x4(af[mt], sA + bo +
                        (uint32_t)((arow + mt * 16) * 40 + acol) * 2);
            const int brow = wn * 32 + (lane & 7);
            const int bcol = ks + (((lane >> 3) & 1) << 3);
#pragma unroll
            for (int nt = 0; nt < 4; nt++)
                ldsm_x2(bfr[nt], sB + bo +
                        (uint32_t)((brow + nt * 8) * 40 + bcol) * 2);
#pragma unroll
            for (int mt = 0; mt < 4; mt++)
#pragma unroll
                for (int nt = 0; nt < 4; nt++)
                    mma16816(acc[mt][nt], af[mt], bfr[nt]);
        }

        __syncthreads();       // all warps done with this buffer
        if (kt + 2 < KT) {
            const uint32_t po = (uint32_t)((kt + 2) % 3) * BUFAB;
            const int k0 = (kt + 2) * BKg;
#pragma unroll
            for (int h = 0; h < 2; h++) {
                int row = ldrow + h * 64;
                CP16(sA + po + (uint32_t)(row * 40 + ldch) * 2,
                     A + (size_t)(by * BMg + row) * K + k0 + ldch);
                CP16(sB + po + (uint32_t)(row * 40 + ldch) * 2,
                     B + (size_t)(bx * BNg + row) * K + k0 + ldch);
            }
            CPCOMMIT();
        }
        if (kt + 1 < KT) {
            if (kt + 2 < KT) CPWAIT1(); else CPWAIT0();
            __syncthreads();   // tile kt+1 resident for everyone
        }
    }

#pragma unroll
    for (int mt = 0; mt < 4; mt++) {
#pragma unroll
        for (int nt = 0; nt < 4; nt++) {
            int row = by * BMg + wm * 64 + mt * 16 + (lane >> 2);
            int col = bx * BNg + wn * 32 + nt * 8 + (lane & 3) * 2;
            float2 v0 = make_float2(acc[mt][nt][0], acc[mt][nt][1]);
            float2 v1 = make_float2(acc[mt][nt][2], acc[mt][nt][3]);
            *(float2*)&C[(size_t)row * N + col]       = v0;
            *(float2*)&C[(size_t)(row + 8) * N + col] = v1;
        }
    }
}

// ---------------- fp32 SGEMM, dual-output (selection path, validated) -----------
__global__ __launch_bounds__(256) void sgemm_nn2(const float* __restrict__ A,
                                                 const float* __restrict__ B1,
                                                 float* __restrict__ C1,
                                                 const float* __restrict__ B2,
                                                 float* __restrict__ C2,
                                                 int M, int N, int K)
{
    const float* B = blockIdx.z ? B2 : B1;
    float*       C = blockIdx.z ? C2 : C1;

    __shared__ float As[2][8][128];
    __shared__ float Bs[2][8][128];

    const int tid = threadIdx.x;
    const int bx = blockIdx.x, by = blockIdx.y;
    const int tx = tid & 15, ty = tid >> 4;

    const int arow = tid >> 1, ak = (tid & 1) * 4;
    const int brow = tid >> 5, bcol = (tid & 31) * 4;

    const float* Ag = A + (size_t)(by * 128 + arow) * K + ak;
    const float* Bg = B + (size_t)brow * N + bx * 128 + bcol;

    float4 af = *(const float4*)Ag;
    float4 bf = *(const float4*)Bg;
    As[0][ak + 0][arow] = af.x;
    As[0][ak + 1][arow] = af.y;
    As[0][ak + 2][arow] = af.z;
    As[0][ak + 3][arow] = af.w;
    *(float4*)&Bs[0][brow][bcol] = bf;
    __syncthreads();

    float acc[8][8];
#pragma unroll
    for (int i = 0; i < 8; i++)
#pragma unroll
        for (int j = 0; j < 8; j++) acc[i][j] = 0.f;

    int buf = 0;
    for (int k0 = 8; k0 <= K; k0 += 8) {
        const bool next = (k0 < K);
        if (next) {
            af = *(const float4*)(Ag + k0);
            bf = *(const float4*)(Bg + (size_t)k0 * N);
        }
#pragma unroll
        for (int kk = 0; kk < 8; kk++) {
            float a[8], b[8];
            *(float4*)&a[0] = *(const float4*)&As[buf][kk][ty * 8];
            *(float4*)&a[4] = *(const float4*)&As[buf][kk][ty * 8 + 4];
            *(float4*)&b[0] = *(const float4*)&Bs[buf][kk][tx * 8];
            *(float4*)&b[4] = *(const float4*)&Bs[buf][kk][tx * 8 + 4];
#pragma unroll
            for (int i = 0; i < 8; i++)
#pragma unroll
                for (int j = 0; j < 8; j++)
                    acc[i][j] += a[i] * b[j];
        }
        if (next) {
            buf ^= 1;
            As[buf][ak + 0][arow] = af.x;
            As[buf][ak + 1][arow] = af.y;
            As[buf][ak + 2][arow] = af.z;
            As[buf][ak + 3][arow] = af.w;
            *(float4*)&Bs[buf][brow][bcol] = bf;
            __syncthreads();
        }
    }

#pragma unroll
    for (int i = 0; i < 8; i++) {
        float* Crow = C + (size_t)(by * 128 + ty * 8 + i) * N + bx * 128 + tx * 8;
        *(float4*)Crow       = make_float4(acc[i][0], acc[i][1], acc[i][2], acc[i][3]);
        *(float4*)(Crow + 4) = make_float4(acc[i][4], acc[i][5], acc[i][6], acc[i][7]);
    }
}

// ---------------- top-k: 8 rows/block, warp-parallel radix ----------------------
__global__ __launch_bounds__(256) void topk8_kernel(const float* __restrict__ iq,
                                                    const float* __restrict__ ik,
                                                    const int* __restrict__ topk_ptr,
                                                    unsigned* __restrict__ mask)
{
    extern __shared__ __align__(16) unsigned dsm[];
    float*    iqs  = (float*)dsm;             // 8 * 256 floats
    unsigned* keys = dsm + 8 * 256;           // 8 * 2048
    unsigned* hist = keys + 8 * 2048;         // 8 * 256
    __shared__ unsigned s_prefix[8];
    __shared__ int      s_kr[8];
    __shared__ unsigned s_thr[8];

    const int tid = threadIdx.x;
    const int gid = blockIdx.x;
    const int b = (gid * 8) >> 11;
    const int qbase = (gid * 8) & (S_LEN - 1);
    const int qmax = qbase + 7;

    for (int i = tid; i < 8 * IDX_D; i += 256) {
        int r = i >> 8, c = i & 255;
        iqs[i] = iq[(size_t)(b * S_LEN + qbase + r) * IDX_D + c];
    }
    __syncthreads();

    // scores for all 8 rows, one ik stream (identical dot expression)
    for (int k = tid; k < S_LEN; k += 256) {
        if (k <= qmax) {
            const float4* ikr = (const float4*)(ik + (size_t)(b * S_LEN + k) * IDX_D);
            float acc[8];
#pragma unroll
            for (int r = 0; r < 8; r++) acc[r] = 0.f;
#pragma unroll 4
            for (int i = 0; i < 64; i++) {
                float4 c = ikr[i];
#pragma unroll
                for (int r = 0; r < 8; r++) {
                    float4 a = ((const float4*)(iqs + r * 256))[i];
                    acc[r] += a.x * c.x + a.y * c.y + a.z * c.z + a.w * c.w;
                }
            }
#pragma unroll
            for (int r = 0; r < 8; r++) {
                unsigned key = 0u;
                if (k <= qbase + r) {
                    unsigned u = __float_as_uint(acc[r]);
                    key = (u & 0x80000000u) ? ~u : (u | 0x80000000u);
                }
                keys[r * S_LEN + k] = key;
            }
        } else {
#pragma unroll
            for (int r = 0; r < 8; r++) keys[r * S_LEN + k] = 0u;
        }
    }

    int topk = topk_ptr ? topk_ptr[0] : 512;
    if (topk > S_LEN) topk = S_LEN;

    const int row  = tid >> 5;     // warp per row
    const int lane = tid & 31;
    const bool active = (qbase + row + 1 > topk);
    if (lane == 0) { s_prefix[row] = 0u; s_kr[row] = topk; }
    __syncthreads();

    for (int pass = 0; pass < 4; pass++) {
        const int shift = 24 - pass * 8;
        for (int i = tid; i < 8 * 256; i += 256) hist[i] = 0u;
        __syncthreads();
        if (active) {
            const unsigned pref = s_prefix[row];
            const unsigned* kr = keys + row * S_LEN;
            for (int k = lane; k < S_LEN; k += 32) {
                unsigned key = kr[k];
                bool match = (pass == 0) || ((key >> (shift + 8)) == (pref >> (shift + 8)));
                if (match) atomicAdd(&hist[row * 256 + ((key >> shift) & 255u)], 1u);
            }
        }
        __syncthreads();
        if (active && lane == 0) {
            int kk = s_kr[row];
            unsigned p = s_prefix[row];
            const unsigned* hr = hist + row * 256;
            for (int d = 255; d >= 0; d--) {
                int c = (int)hr[d];
                if (kk <= c) { s_prefix[row] = p | ((unsigned)d << shift); break; }
                kk -= c;
            }
            s_kr[row] = kk;
        }
        __syncthreads();
    }
    if (lane == 0) s_thr[row] = active ? s_prefix[row] : 0u;
    __syncthreads();

    for (int w = tid; w < 8 * 64; w += 256) {
        int r = w >> 6, wi = w & 63;
        int q = qbase + r;
        unsigned thr = s_thr[r];
        const unsigned* kr = keys + r * S_LEN;
        unsigned word = 0u;
        int kb = wi * 32;
#pragma unroll
        for (int bit = 0; bit < 32; bit++) {
            int k = kb + bit;
            unsigned key = kr[k];
            if (k <= q && key >= thr && key != 0u) word |= (1u << bit);
        }
        mask[(size_t)(b * S_LEN + q) * 64 + wi] = word;
    }
}

// ---------------- fused rope + flash operand prep -------------------------------
__global__ void prep_flash_rope(const float* __restrict__ qkv,
                                bf16* __restrict__ q3, bf16* __restrict__ k3,
                                bf16* __restrict__ vt3, int BS)
{
    int idx = blockIdx.x * blockDim.x + threadIdx.x;   // BS * 16 * 32 pairs
    if (idx >= BS * 512) return;
    int i   = idx & 31;           // pair / frequency index
    int h   = (idx >> 5) & 15;
    int tok = idx >> 9;
    int b   = tok >> 11;
    int s   = tok & (S_LEN - 1);

    size_t base = (size_t)tok * 3072 + h * 64 + 2 * i;
    float q1 = qkv[base],        q2 = qkv[base + 1];
    float k1 = qkv[base + 1024], k2 = qkv[base + 1025];
    float v1 = qkv[base + 2048], v2 = qkv[base + 2049];

    float ex   = (float)(2 * i) * (1.0f / 64.0f);
    float freq = powf(10000.0f, -ex);
    float ang  = (float)s * freq;
    float sn, cs;
    sincosf(ang, &sn, &cs);

    float qa = q1 * cs - q2 * sn, qb = q1 * sn + q2 * cs;
    float ka = k1 * cs - k2 * sn, kb = k1 * sn + k2 * cs;

    size_t bh = (size_t)b * N_HEADS + h;
    {   // Q: A3 (h,l,h) for d = 2i, 2i+1
        size_t o = (bh * S_LEN + s) * 192 + 3 * (size_t)(2 * i);
        bf16 hh = __float2bfloat16(qa);
        bf16 ll = __float2bfloat16(qa - __bfloat162float(hh));
        q3[o] = hh; q3[o + 1] = ll; q3[o + 2] = hh;
        hh = __float2bfloat16(qb);
        ll = __float2bfloat16(qb - __bfloat162float(hh));
        q3[o + 3] = hh; q3[o + 4] = ll; q3[o + 5] = hh;
    }
    {   // K: B3 (h,h,l)
        size_t o = (bh * S_LEN + s) * 192 + 3 * (size_t)(2 * i);
        bf16 hh = __float2bfloat16(ka);
        bf16 ll = __float2bfloat16(ka - __bfloat162float(hh));
        k3[o] = hh; k3[o + 1] = hh; k3[o + 2] = ll;
        hh = __float2bfloat16(kb);
        ll = __float2bfloat16(kb - __bfloat162float(hh));
        k3[o + 3] = hh; k3[o + 4] = hh; k3[o + 5] = ll;
    }
    {   // V^T: rows = dim, cols = 3*key, B3 pattern; d = 2i and 2i+1
        bf16 hh = __float2bfloat16(v1);
        bf16 ll = __float2bfloat16(v1 - __bfloat162float(hh));
        size_t o = (bh * 64 + 2 * i) * (size_t)(3 * S_LEN) + 3 * (size_t)s;
        vt3[o] = hh; vt3[o + 1] = hh; vt3[o + 2] = ll;
        hh = __float2bfloat16(v2);
        ll = __float2bfloat16(v2 - __bfloat162float(hh));
        o += (size_t)(3 * S_LEN);
        vt3[o] = hh; vt3[o + 1] = hh; vt3[o + 2] = ll;
    }
}

// ---------------- tensor-core masked flash v2 (unchanged, validated) -------------
#define FSTR  200
#define FSTR2 400
#define OQ    0
#define OK0   (128 * FSTR)
#define OK1   (OK0 + 64 * FSTR)
#define OV0   (OK1 + 64 * FSTR)
#define OV1   (OV0 + 64 * FSTR)
#define OP    (OV1 + 64 * FSTR)
#define FSMEM ((OP + 128 * FSTR) * 2)   // 204800 bytes

__global__ __launch_bounds__(256) void flash_mma2(
    const bf16* __restrict__ q3, const bf16* __restrict__ k3,
    const bf16* __restrict__ vt3, const unsigned* __restrict__ mask,
    float* __restrict__ attn)
{
    extern __shared__ __align__(16) bf16 sm[];
    const int tid  = threadIdx.x;
    const int warp = tid >> 5, lane = tid & 31;
    const int qt = gridDim.x - 1 - blockIdx.x;
    const int h = blockIdx.y, b = blockIdx.z;

    const uint32_t sbase = (uint32_t)__cvta_generic_to_shared(sm);
    const uint32_t sQ = sbase + OQ * 2;
    const uint32_t sP = sbase + OP * 2;
    bf16* Psp = sm + OP;

    const size_t bh = (size_t)b * N_HEADS + h;
    const bf16* q3g  = q3  + (bh * S_LEN + (size_t)qt * 128) * 192;
    const bf16* k3g  = k3  + bh * S_LEN * 192;
    const bf16* vt3g = vt3 + bh * 64 * (size_t)(3 * S_LEN);

    for (int c = tid; c < 3072; c += 256) {
        int row = c / 24, k16 = c % 24;
        CP16(sQ + row * FSTR2 + k16 * 16, q3g + (size_t)row * 192 + k16 * 8);
    }
    CPCOMMIT();

    const int ktmax = 2 * qt + 1;

    for (int c = tid; c < 3072; c += 256) {
        if (c < 1536) {
            int row = c / 24, k16 = c % 24;
            CP16(sbase + OK0 * 2 + row * FSTR2 + k16 * 16,
                 k3g + (size_t)row * 192 + k16 * 8);
        } else {
            int cc = c - 1536;
            int drow = cc / 24, k16 = cc % 24;
            CP16(sbase + OV0 * 2 + drow * FSTR2 + k16 * 16,
                 vt3g + (size_t)drow * (3 * S_LEN) + k16 * 8);
        }
    }
    CPCOMMIT();

    float O[8][4];
#pragma unroll
    for (int i = 0; i < 8; i++)
#pragma unroll
        for (int j = 0; j < 4; j++) O[i][j] = 0.f;
    float m0 = -1e30f, m1 = -1e30f, l0 = 0.f, l1 = 0.f;

    const int r0 = warp * 16 + (lane >> 2);
    const int q0 = qt * 128 + r0, q1 = q0 + 8;
    const unsigned* mrow0 = mask + ((size_t)b * S_LEN + q0) * 64;
    const unsigned* mrow1 = mask + ((size_t)b * S_LEN + q1) * 64;

    const uint32_t aoff = (uint32_t)((warp * 16 + (lane & 15)) * FSTR2 + ((lane >> 4) << 3) * 2);
    const int browo = (lane & 7) + ((lane >> 4) << 3);
    const uint32_t bcol = (uint32_t)((((lane >> 3) & 1) << 3) * 2);

    for (int kt = 0; kt <= ktmax; kt++) {
        const int buf = kt & 1;
        if (kt < ktmax) {
            const uint32_t dK = sbase + (buf ? OK0 : OK1) * 2;
            const uint32_t dV = sbase + (buf ? OV0 : OV1) * 2;
            const size_t kro = (size_t)(kt + 1) * 64;
            for (int c = tid; c < 3072; c += 256) {
                if (c < 1536) {
                    int row = c / 24, k16 = c % 24;
                    CP16(dK + row * FSTR2 + k16 * 16,
                         k3g + (kro + row) * 192 + k16 * 8);
                } else {
                    int cc = c - 1536;
                    int drow = cc / 24, k16 = cc % 24;
                    CP16(dV + drow * FSTR2 + k16 * 16,
                         vt3g + (size_t)drow * (3 * S_LEN) + (kt + 1) * 192 + k16 * 8);
                }
            }
            CPCOMMIT();
            CPWAIT1();
        } else {
            CPWAIT0();
        }
        __syncthreads();

        const uint32_t sKb = sbase + (buf ? OK1 : OK0) * 2;
        const uint32_t sVb = sbase + (buf ? OV1 : OV0) * 2;

        float S_[8][4];
#pragma unroll
        for (int i = 0; i < 8; i++)
#pragma unroll
            for (int j = 0; j < 4; j++) S_[i][j] = 0.f;

#pragma unroll
        for (int ks = 0; ks < 12; ks++) {
            uint32_t a[4];
            ldsm_x4(a, sQ + aoff + ks * 32);
#pragma unroll
            for (int nt2 = 0; nt2 < 4; nt2++) {
                uint32_t bb[4];
                ldsm_x4(bb, sKb + (uint32_t)((nt2 * 16 + browo) * FSTR2) + bcol + ks * 32);
                mma16816(S_[nt2 * 2],     a, bb);
                mma16816(S_[nt2 * 2 + 1], a, bb + 2);
            }
        }

        const unsigned mw00 = mrow0[kt * 2], mw01 = mrow0[kt * 2 + 1];
        const unsigned mw10 = mrow1[kt * 2], mw11 = mrow1[kt * 2 + 1];
        float mx0 = -1e30f, mx1 = -1e30f;
#pragma unroll
        for (int nf = 0; nf < 8; nf++) {
            int c = nf * 8 + 2 * (lane & 3);
#pragma unroll
            for (int e = 0; e < 2; e++) {
                int cc = c + e;
                unsigned w0 = (cc < 32 ? mw00 : mw01) >> (cc & 31);
                unsigned w1 = (cc < 32 ? mw10 : mw11) >> (cc & 31);
                float v0 = (w0 & 1u) ? S_[nf][e] * 0.125f     : -1e30f;
                float v1 = (w1 & 1u) ? S_[nf][e + 2] * 0.125f : -1e30f;
                S_[nf][e] = v0; S_[nf][e + 2] = v1;
                mx0 = fmaxf(mx0, v0); mx1 = fmaxf(mx1, v1);
            }
        }
        mx0 = fmaxf(mx0, __shfl_xor_sync(0xffffffffu, mx0, 1));
        mx0 = fmaxf(mx0, __shfl_xor_sync(0xffffffffu, mx0, 2));
        mx1 = fmaxf(mx1, __shfl_xor_sync(0xffffffffu, mx1, 1));
        mx1 = fmaxf(mx1, __shfl_xor_sync(0xffffffffu, mx1, 2));
        float mn0 = fmaxf(m0, mx0), mn1 = fmaxf(m1, mx1);
        float c0 = __expf(m0 - mn0), c1 = __expf(m1 - mn1);
        float ls0 = 0.f, ls1 = 0.f;
#pragma unroll
        for (int nf = 0; nf < 8; nf++) {
#pragma unroll
            for (int e = 0; e < 2; e++) {
                float p0 = (S_[nf][e]     > -1e29f) ? __expf(S_[nf][e]     - mn0) : 0.f;
                float p1 = (S_[nf][e + 2] > -1e29f) ? __expf(S_[nf][e + 2] - mn1) : 0.f;
                S_[nf][e] = p0; S_[nf][e + 2] = p1;
                ls0 += p0; ls1 += p1;
            }
        }
        ls0 += __shfl_xor_sync(0xffffffffu, ls0, 1);
        ls0 += __shfl_xor_sync(0xffffffffu, ls0, 2);
        ls1 += __shfl_xor_sync(0xffffffffu, ls1, 1);
        ls1 += __shfl_xor_sync(0xffffffffu, ls1, 2);
        l0 = l0 * c0 + ls0; l1 = l1 * c1 + ls1;
        m0 = mn0; m1 = mn1;
#pragma unroll
        for (int nf = 0; nf < 8; nf++) {
            O[nf][0] *= c0; O[nf][1] *= c0;
            O[nf][2] *= c1; O[nf][3] *= c1;
        }

#pragma unroll
        for (int nf = 0; nf < 8; nf++) {
            int c = nf * 8 + 2 * (lane & 3);
#pragma unroll
            for (int e = 0; e < 2; e++) {
                float p = S_[nf][e];
                bf16 hh = __float2bfloat16(p);
                bf16 ll = __float2bfloat16(p - __bfloat162float(hh));
                int o = r0 * FSTR + 3 * (c + e);
                Psp[o] = hh; Psp[o + 1] = ll; Psp[o + 2] = hh;

                p = S_[nf][e + 2];
                hh = __float2bfloat16(p);
                ll = __float2bfloat16(p - __bfloat162float(hh));
                o = (r0 + 8) * FSTR + 3 * (c + e);
                Psp[o] = hh; Psp[o + 1] = ll; Psp[o + 2] = hh;
            }
        }
        __syncwarp();

#pragma unroll
        for (int ks = 0; ks < 12; ks++) {
            uint32_t a[4];
            ldsm_x4(a, sP + aoff + ks * 32);
#pragma unroll
            for (int nt2 = 0; nt2 < 4; nt2++) {
                uint32_t bb[4];
                ldsm_x4(bb, sVb + (uint32_t)((nt2 * 16 + browo) * FSTR2) + bcol + ks * 32);
                mma16816(O[nt2 * 2],     a, bb);
                mma16816(O[nt2 * 2 + 1], a, bb + 2);
            }
        }
        __syncthreads();
    }

    float inv0 = 1.0f / l0, inv1 = 1.0f / l1;
    float* out0 = attn + ((size_t)b * S_LEN + q0) * D_MODEL + h * 64;
    float* out1 = attn + ((size_t)b * S_LEN + q1) * D_MODEL + h * 64;
#pragma unroll
    for (int nf = 0; nf < 8; nf++) {
        int c = nf * 8 + 2 * (lane & 3);
        *(float2*)(out0 + c) = make_float2(O[nf][0] * inv0, O[nf][1] * inv0);
        *(float2*)(out1 + c) = make_float2(O[nf][2] * inv1, O[nf][3] * inv1);
    }
}

// ---------------- launcher with fork/join stream overlap -------------------------
extern "C" void kernel_launch(void* const* d_in, const int* in_sizes, int n_in,
                              void* d_out, int out_size)
{
    static cudaStream_t s_sel = nullptr;
    static cudaEvent_t  ev_fork = nullptr, ev_join = nullptr;
    if (!s_sel) {
        cudaStreamCreateWithFlags(&s_sel, cudaStreamNonBlocking);
        cudaEventCreateWithFlags(&ev_fork, cudaEventDisableTiming);
        cudaEventCreateWithFlags(&ev_join, cudaEventDisableTiming);
    }

    const float* x    = nullptr;
    const float* Wqkv = nullptr;
    const float* Wo   = nullptr;
    const float* Wiq  = nullptr;
    const float* Wik  = nullptr;
    const int*   topk = nullptr;
    for (int i = 0; i < n_in; i++) {
        int sz = in_sizes[i];
        if      (sz == D_MODEL * 3 * D_MODEL)       Wqkv = (const float*)d_in[i];
        else if (sz == D_MODEL * D_MODEL)           Wo   = (const float*)d_in[i];
        else if (sz == D_MODEL * IDX_D) { if (!Wiq) Wiq  = (const float*)d_in[i];
                                          else      Wik  = (const float*)d_in[i]; }
        else if (sz <= 4)                           topk = (const int*)d_in[i];
        else                                        x    = (const float*)d_in[i];
    }

    const int BS = out_size / D_MODEL;
    const int Bn = BS / S_LEN;

    float *qkv, *iq, *ik, *attn; unsigned* mask;
    bf16 *x3, *attn3, *wqkv3, *wo3, *q3, *k3, *vt3;
    cudaGetSymbolAddress((void**)&qkv,   g_qkv);
    cudaGetSymbolAddress((void**)&iq,    g_iq);
    cudaGetSymbolAddress((void**)&ik,    g_ik);
    cudaGetSymbolAddress((void**)&attn,  g_attn);
    cudaGetSymbolAddress((void**)&mask,  g_mask);
    cudaGetSymbolAddress((void**)&x3,    g_x3);
    cudaGetSymbolAddress((void**)&attn3, g_attn3);
    cudaGetSymbolAddress((void**)&wqkv3, g_wqkv3);
    cudaGetSymbolAddress((void**)&wo3,   g_wo3);
    cudaGetSymbolAddress((void**)&q3,    g_q3);
    cudaGetSymbolAddress((void**)&k3,    g_k3);
    cudaGetSymbolAddress((void**)&vt3,   g_vt3);

    const int K3 = 3 * D_MODEL;
    const int TOPK_SMEM = (8 * 256 + 8 * 2048 + 8 * 256) * 4;

    cudaFuncSetAttribute(mma_gemm, cudaFuncAttributeMaxDynamicSharedMemorySize, GEMM_SMEM);
    cudaFuncSetAttribute(topk8_kernel, cudaFuncAttributeMaxDynamicSharedMemorySize, TOPK_SMEM);
    cudaFuncSetAttribute(flash_mma2, cudaFuncAttributeMaxDynamicSharedMemorySize, FSMEM);

    // ---- fork: selection chain on s_sel ----
    cudaEventRecord(ev_fork, 0);
    cudaStreamWaitEvent(s_sel, ev_fork, 0);
    sgemm_nn2<<<dim3(IDX_D / 128, BS / 128, 2), 256, 0, s_sel>>>(
        x, Wiq, iq, Wik, ik, BS, IDX_D, D_MODEL);
    topk8_kernel<<<BS / 8, 256, TOPK_SMEM, s_sel>>>(iq, ik, topk, mask);
    cudaEventRecord(ev_join, s_sel);

    // ---- smooth chain on the main (capture) stream ----
    split_a<<<(BS * D_MODEL + 255) / 256, 256>>>(x, x3, BS * D_MODEL);
    {
        dim3 blk(32, 8);
        split_bT<<<dim3(3 * D_MODEL / 32, D_MODEL / 32), blk>>>(Wqkv, wqkv3, D_MODEL, 3 * D_MODEL);
        split_bT<<<dim3(D_MODEL / 32, D_MODEL / 32), blk>>>(Wo, wo3, D_MODEL, D_MODEL);
    }
    mma_gemm<<<dim3(3 * D_MODEL / BNg, BS / BMg), 256, GEMM_SMEM>>>(
        x3, wqkv3, qkv, BS, 3 * D_MODEL, K3);
    prep_flash_rope<<<(BS * 512 + 255) / 256, 256>>>(qkv, q3, k3, vt3, BS);

    // ---- join: flash needs the mask ----
    cudaStreamWaitEvent(0, ev_join, 0);
    flash_mma2<<<dim3(S_LEN / 128, N_HEADS, Bn), 256, FSMEM>>>(q3, k3, vt3, mask, attn);

    // output projection
    split_a<<<(BS * D_MODEL + 255) / 256, 256>>>(attn, attn3, BS * D_MODEL);
    mma_gemm<<<dim3(D_MODEL / BNg, BS / BMg), 256, GEMM_SMEM>>>(
        attn3, wo3, (float*)d_out, BS, D_MODEL, K3);
}

// round 12
// speedup vs baseline: 2.9998x; 1.1026x over previous
#include <cuda_runtime.h>
#include <cuda_bf16.h>
#include <cstdint>
#include <math.h>

#define S_LEN   2048
#define D_MODEL 1024
#define N_HEADS 16
#define IDX_D   256
#define MAXB    2
#define BS_MAX  (MAXB * S_LEN)

typedef __nv_bfloat16 bf16;

// ---------------- scratch (static device globals; no allocation) ----------------
__device__ float    g_qkv [(size_t)BS_MAX * 3 * D_MODEL];
__device__ float    g_iq  [(size_t)BS_MAX * IDX_D];
__device__ float    g_ik  [(size_t)BS_MAX * IDX_D];
__device__ float    g_attn[(size_t)BS_MAX * D_MODEL];
__device__ unsigned g_mask[(size_t)BS_MAX * (S_LEN / 32)];

__device__ __align__(16) bf16 g_x3   [(size_t)BS_MAX * 3 * D_MODEL];
__device__ __align__(16) bf16 g_attn3[(size_t)BS_MAX * 3 * D_MODEL];
__device__ __align__(16) bf16 g_wqkv3[(size_t)(3 * D_MODEL) * 3 * D_MODEL];
__device__ __align__(16) bf16 g_wo3  [(size_t)D_MODEL * 3 * D_MODEL];

// flash operands: h/l split pairs
__device__ __align__(16) bf16 g_qh [(size_t)MAXB * N_HEADS * S_LEN * 64];
__device__ __align__(16) bf16 g_ql [(size_t)MAXB * N_HEADS * S_LEN * 64];
__device__ __align__(16) bf16 g_kh [(size_t)MAXB * N_HEADS * S_LEN * 64];
__device__ __align__(16) bf16 g_kl [(size_t)MAXB * N_HEADS * S_LEN * 64];
__device__ __align__(16) bf16 g_vth[(size_t)MAXB * N_HEADS * 64 * S_LEN];
__device__ __align__(16) bf16 g_vtl[(size_t)MAXB * N_HEADS * 64 * S_LEN];

// ---------------- bf16x3 split conversions --------------------------------------
__global__ void split_a(const float* __restrict__ s, bf16* __restrict__ d, int n)
{
    int i = blockIdx.x * blockDim.x + threadIdx.x;
    if (i >= n) return;
    float v = s[i];
    bf16 h = __float2bfloat16(v);
    bf16 l = __float2bfloat16(v - __bfloat162float(h));
    d[3 * i] = h; d[3 * i + 1] = l; d[3 * i + 2] = h;
}

__global__ void split_bT(const float* __restrict__ W, bf16* __restrict__ out,
                         int K, int N)
{
    __shared__ float t[32][33];
    int n0 = blockIdx.x * 32, k0 = blockIdx.y * 32;
    int tx = threadIdx.x, ty = threadIdx.y;   // block (32,8)
    for (int i = ty; i < 32; i += 8)
        t[i][tx] = W[(size_t)(k0 + i) * N + n0 + tx];
    __syncthreads();
    for (int r = ty; r < 32; r += 8) {
        float v = t[tx][r];
        bf16 h = __float2bfloat16(v);
        bf16 l = __float2bfloat16(v - __bfloat162float(h));
        size_t o = (size_t)(n0 + r) * (3 * K) + 3 * (size_t)(k0 + tx);
        out[o] = h; out[o + 1] = h; out[o + 2] = l;
    }
}

// ---------------- tensor-core NT GEMM, 3-stage cp.async pipeline (validated) ----
#define BMg 128
#define BNg 128
#define BKg 32
#define GEMM_SMEM (3 * (BMg + BNg) * 40 * 2)   // 61440 bytes

__device__ __forceinline__ void ldsm_x4(uint32_t* r, uint32_t a) {
    asm volatile("ldmatrix.sync.aligned.m8n8.x4.shared.b16 {%0,%1,%2,%3}, [%4];"
                 : "=r"(r[0]), "=r"(r[1]), "=r"(r[2]), "=r"(r[3]) : "r"(a));
}
__device__ __forceinline__ void ldsm_x2(uint32_t* r, uint32_t a) {
    asm volatile("ldmatrix.sync.aligned.m8n8.x2.shared.b16 {%0,%1}, [%2];"
                 : "=r"(r[0]), "=r"(r[1]) : "r"(a));
}
__device__ __forceinline__ void mma16816(float* c, const uint32_t* a, const uint32_t* b) {
    asm volatile("mma.sync.aligned.m16n8k16.row.col.f32.bf16.bf16.f32 "
                 "{%0,%1,%2,%3},{%4,%5,%6,%7},{%8,%9},{%0,%1,%2,%3};"
                 : "+f"(c[0]), "+f"(c[1]), "+f"(c[2]), "+f"(c[3])
                 : "r"(a[0]), "r"(a[1]), "r"(a[2]), "r"(a[3]), "r"(b[0]), "r"(b[1]));
}
#define CP16(sa, ga) asm volatile("cp.async.cg.shared.global [%0], [%1], 16;\n" :: "r"(sa), "l"(ga))
#define CPCOMMIT()   asm volatile("cp.async.commit_group;\n" ::: "memory")
#define CPWAIT0()    asm volatile("cp.async.wait_group 0;\n" ::: "memory")
#define CPWAIT1()    asm volatile("cp.async.wait_group 1;\n" ::: "memory")

__global__ __launch_bounds__(256) void mma_gemm(
    const bf16* __restrict__ A, const bf16* __restrict__ B, float* __restrict__ C,
    int M, int N, int K)
{
    extern __shared__ __align__(16) bf16 gsm[];
    const int bx = blockIdx.x, by = blockIdx.y;

    const int tid  = threadIdx.x;
    const int warp = tid >> 5, lane = tid & 31;
    const int wm = warp & 1, wn = warp >> 1;

    const uint32_t BUFA  = BMg * 40 * 2;
    const uint32_t BUFAB = (BMg + BNg) * 40 * 2;
    const uint32_t sbase = (uint32_t)__cvta_generic_to_shared(gsm);
    const uint32_t sA = sbase;
    const uint32_t sB = sbase + BUFA;

    const int ldrow = tid >> 2;
    const int ldch  = (tid & 3) * 8;

    float acc[4][4][4];
#pragma unroll
    for (int i = 0; i < 4; i++)
#pragma unroll
        for (int j = 0; j < 4; j++)
#pragma unroll
            for (int t = 0; t < 4; t++) acc[i][j][t] = 0.f;

    const int KT = K / BKg;

#pragma unroll
    for (int pf = 0; pf < 2; pf++) {
        int k0 = pf * BKg;
#pragma unroll
        for (int h = 0; h < 2; h++) {
            int row = ldrow + h * 64;
            CP16(sA + pf * BUFAB + (uint32_t)(row * 40 + ldch) * 2,
                 A + (size_t)(by * BMg + row) * K + k0 + ldch);
            CP16(sB + pf * BUFAB + (uint32_t)(row * 40 + ldch) * 2,
                 B + (size_t)(bx * BNg + row) * K + k0 + ldch);
        }
        CPCOMMIT();
    }
    CPWAIT1();
    __syncthreads();

    for (int kt = 0; kt < KT; kt++) {
        const uint32_t bo = (uint32_t)(kt % 3) * BUFAB;

#pragma unroll
        for (int ks = 0; ks < BKg; ks += 16) {
            uint32_t af[4][4], bfr[4][2];
            const int arow = wm * 64 + (lane & 15);
            const int acol = ks + ((lane >> 4) << 3);
#pragma unroll
            for (int mt = 0; mt < 4; mt++)
                ldsm_x4(af[mt], sA + bo +
                        (uint32_t)((arow + mt * 16) * 40 + acol) * 2);
            const int brow = wn * 32 + (lane & 7);
            const int bcol = ks + (((lane >> 3) & 1) << 3);
#pragma unroll
            for (int nt = 0; nt < 4; nt++)
                ldsm_x2(bfr[nt], sB + bo +
                        (uint32_t)((brow + nt * 8) * 40 + bcol) * 2);
#pragma unroll
            for (int mt = 0; mt < 4; mt++)
#pragma unroll
                for (int nt = 0; nt < 4; nt++)
                    mma16816(acc[mt][nt], af[mt], bfr[nt]);
        }

        __syncthreads();
        if (kt + 2 < KT) {
            const uint32_t po = (uint32_t)((kt + 2) % 3) * BUFAB;
            const int k0 = (kt + 2) * BKg;
#pragma unroll
            for (int h = 0; h < 2; h++) {
                int row = ldrow + h * 64;
                CP16(sA + po + (uint32_t)(row * 40 + ldch) * 2,
                     A + (size_t)(by * BMg + row) * K + k0 + ldch);
                CP16(sB + po + (uint32_t)(row * 40 + ldch) * 2,
                     B + (size_t)(bx * BNg + row) * K + k0 + ldch);
            }
            CPCOMMIT();
        }
        if (kt + 1 < KT) {
            if (kt + 2 < KT) CPWAIT1(); else CPWAIT0();
            __syncthreads();
        }
    }

#pragma unroll
    for (int mt = 0; mt < 4; mt++) {
#pragma unroll
        for (int nt = 0; nt < 4; nt++) {
            int row = by * BMg + wm * 64 + mt * 16 + (lane >> 2);
            int col = bx * BNg + wn * 32 + nt * 8 + (lane & 3) * 2;
            float2 v0 = make_float2(acc[mt][nt][0], acc[mt][nt][1]);
            float2 v1 = make_float2(acc[mt][nt][2], acc[mt][nt][3]);
            *(float2*)&C[(size_t)row * N + col]       = v0;
            *(float2*)&C[(size_t)(row + 8) * N + col] = v1;
        }
    }
}

// ---------------- fp32 SGEMM, dual-output (selection path, validated) -----------
__global__ __launch_bounds__(256) void sgemm_nn2(const float* __restrict__ A,
                                                 const float* __restrict__ B1,
                                                 float* __restrict__ C1,
                                                 const float* __restrict__ B2,
                                                 float* __restrict__ C2,
                                                 int M, int N, int K)
{
    const float* B = blockIdx.z ? B2 : B1;
    float*       C = blockIdx.z ? C2 : C1;

    __shared__ float As[2][8][128];
    __shared__ float Bs[2][8][128];

    const int tid = threadIdx.x;
    const int bx = blockIdx.x, by = blockIdx.y;
    const int tx = tid & 15, ty = tid >> 4;

    const int arow = tid >> 1, ak = (tid & 1) * 4;
    const int brow = tid >> 5, bcol = (tid & 31) * 4;

    const float* Ag = A + (size_t)(by * 128 + arow) * K + ak;
    const float* Bg = B + (size_t)brow * N + bx * 128 + bcol;

    float4 af = *(const float4*)Ag;
    float4 bf = *(const float4*)Bg;
    As[0][ak + 0][arow] = af.x;
    As[0][ak + 1][arow] = af.y;
    As[0][ak + 2][arow] = af.z;
    As[0][ak + 3][arow] = af.w;
    *(float4*)&Bs[0][brow][bcol] = bf;
    __syncthreads();

    float acc[8][8];
#pragma unroll
    for (int i = 0; i < 8; i++)
#pragma unroll
        for (int j = 0; j < 8; j++) acc[i][j] = 0.f;

    int buf = 0;
    for (int k0 = 8; k0 <= K; k0 += 8) {
        const bool next = (k0 < K);
        if (next) {
            af = *(const float4*)(Ag + k0);
            bf = *(const float4*)(Bg + (size_t)k0 * N);
        }
#pragma unroll
        for (int kk = 0; kk < 8; kk++) {
            float a[8], b[8];
            *(float4*)&a[0] = *(const float4*)&As[buf][kk][ty * 8];
            *(float4*)&a[4] = *(const float4*)&As[buf][kk][ty * 8 + 4];
            *(float4*)&b[0] = *(const float4*)&Bs[buf][kk][tx * 8];
            *(float4*)&b[4] = *(const float4*)&Bs[buf][kk][tx * 8 + 4];
#pragma unroll
            for (int i = 0; i < 8; i++)
#pragma unroll
                for (int j = 0; j < 8; j++)
                    acc[i][j] += a[i] * b[j];
        }
        if (next) {
            buf ^= 1;
            As[buf][ak + 0][arow] = af.x;
            As[buf][ak + 1][arow] = af.y;
            As[buf][ak + 2][arow] = af.z;
            As[buf][ak + 3][arow] = af.w;
            *(float4*)&Bs[buf][brow][bcol] = bf;
            __syncthreads();
        }
    }

#pragma unroll
    for (int i = 0; i < 8; i++) {
        float* Crow = C + (size_t)(by * 128 + ty * 8 + i) * N + bx * 128 + tx * 8;
        *(float4*)Crow       = make_float4(acc[i][0], acc[i][1], acc[i][2], acc[i][3]);
        *(float4*)(Crow + 4) = make_float4(acc[i][4], acc[i][5], acc[i][6], acc[i][7]);
    }
}

// ---------------- top-k: 8 rows/block, warp-parallel radix (validated) ----------
__global__ __launch_bounds__(256) void topk8_kernel(const float* __restrict__ iq,
                                                    const float* __restrict__ ik,
                                                    const int* __restrict__ topk_ptr,
                                                    unsigned* __restrict__ mask)
{
    extern __shared__ __align__(16) unsigned dsm[];
    float*    iqs  = (float*)dsm;
    unsigned* keys = dsm + 8 * 256;
    unsigned* hist = keys + 8 * 2048;
    __shared__ unsigned s_prefix[8];
    __shared__ int      s_kr[8];
    __shared__ unsigned s_thr[8];

    const int tid = threadIdx.x;
    const int gid = blockIdx.x;
    const int b = (gid * 8) >> 11;
    const int qbase = (gid * 8) & (S_LEN - 1);
    const int qmax = qbase + 7;

    for (int i = tid; i < 8 * IDX_D; i += 256) {
        int r = i >> 8, c = i & 255;
        iqs[i] = iq[(size_t)(b * S_LEN + qbase + r) * IDX_D + c];
    }
    __syncthreads();

    for (int k = tid; k < S_LEN; k += 256) {
        if (k <= qmax) {
            const float4* ikr = (const float4*)(ik + (size_t)(b * S_LEN + k) * IDX_D);
            float acc[8];
#pragma unroll
            for (int r = 0; r < 8; r++) acc[r] = 0.f;
#pragma unroll 4
            for (int i = 0; i < 64; i++) {
                float4 c = ikr[i];
#pragma unroll
                for (int r = 0; r < 8; r++) {
                    float4 a = ((const float4*)(iqs + r * 256))[i];
                    acc[r] += a.x * c.x + a.y * c.y + a.z * c.z + a.w * c.w;
                }
            }
#pragma unroll
            for (int r = 0; r < 8; r++) {
                unsigned key = 0u;
                if (k <= qbase + r) {
                    unsigned u = __float_as_uint(acc[r]);
                    key = (u & 0x80000000u) ? ~u : (u | 0x80000000u);
                }
                keys[r * S_LEN + k] = key;
            }
        } else {
#pragma unroll
            for (int r = 0; r < 8; r++) keys[r * S_LEN + k] = 0u;
        }
    }

    int topk = topk_ptr ? topk_ptr[0] : 512;
    if (topk > S_LEN) topk = S_LEN;

    const int row  = tid >> 5;
    const int lane = tid & 31;
    const bool active = (qbase + row + 1 > topk);
    if (lane == 0) { s_prefix[row] = 0u; s_kr[row] = topk; }
    __syncthreads();

    for (int pass = 0; pass < 4; pass++) {
        const int shift = 24 - pass * 8;
        for (int i = tid; i < 8 * 256; i += 256) hist[i] = 0u;
        __syncthreads();
        if (active) {
            const unsigned pref = s_prefix[row];
            const unsigned* kr = keys + row * S_LEN;
            for (int k = lane; k < S_LEN; k += 32) {
                unsigned key = kr[k];
                bool match = (pass == 0) || ((key >> (shift + 8)) == (pref >> (shift + 8)));
                if (match) atomicAdd(&hist[row * 256 + ((key >> shift) & 255u)], 1u);
            }
        }
        __syncthreads();
        if (active && lane == 0) {
            int kk = s_kr[row];
            unsigned p = s_prefix[row];
            const unsigned* hr = hist + row * 256;
            for (int d = 255; d >= 0; d--) {
                int c = (int)hr[d];
                if (kk <= c) { s_prefix[row] = p | ((unsigned)d << shift); break; }
                kk -= c;
            }
            s_kr[row] = kk;
        }
        __syncthreads();
    }
    if (lane == 0) s_thr[row] = active ? s_prefix[row] : 0u;
    __syncthreads();

    for (int w = tid; w < 8 * 64; w += 256) {
        int r = w >> 6, wi = w & 63;
        int q = qbase + r;
        unsigned thr = s_thr[r];
        const unsigned* kr = keys + r * S_LEN;
        unsigned word = 0u;
        int kb = wi * 32;
#pragma unroll
        for (int bit = 0; bit < 32; bit++) {
            int k = kb + bit;
            unsigned key = kr[k];
            if (k <= q && key >= thr && key != 0u) word |= (1u << bit);
        }
        mask[(size_t)(b * S_LEN + q) * 64 + wi] = word;
    }
}

// ---------------- fused rope + h/l split flash operand prep ---------------------
__global__ void prep_flash_rope(const float* __restrict__ qkv,
                                bf16* __restrict__ qh, bf16* __restrict__ ql,
                                bf16* __restrict__ kh, bf16* __restrict__ kl,
                                bf16* __restrict__ vth, bf16* __restrict__ vtl,
                                int BS)
{
    int idx = blockIdx.x * blockDim.x + threadIdx.x;   // BS * 16 * 32 pairs
    if (idx >= BS * 512) return;
    int i   = idx & 31;
    int h   = (idx >> 5) & 15;
    int tok = idx >> 9;
    int b   = tok >> 11;
    int s   = tok & (S_LEN - 1);

    size_t base = (size_t)tok * 3072 + h * 64 + 2 * i;
    float q1 = qkv[base],        q2 = qkv[base + 1];
    float k1 = qkv[base + 1024], k2 = qkv[base + 1025];
    float v1 = qkv[base + 2048], v2 = qkv[base + 2049];

    float ex   = (float)(2 * i) * (1.0f / 64.0f);
    float freq = powf(10000.0f, -ex);
    float ang  = (float)s * freq;
    float sn, cs;
    sincosf(ang, &sn, &cs);

    float qa = q1 * cs - q2 * sn, qb = q1 * sn + q2 * cs;
    float ka = k1 * cs - k2 * sn, kb = k1 * sn + k2 * cs;

    size_t bh = (size_t)b * N_HEADS + h;
    size_t ro = (bh * S_LEN + s) * 64 + 2 * (size_t)i;
    {
        bf16 hh = __float2bfloat16(qa);
        qh[ro] = hh; ql[ro] = __float2bfloat16(qa - __bfloat162float(hh));
        hh = __float2bfloat16(qb);
        qh[ro + 1] = hh; ql[ro + 1] = __float2bfloat16(qb - __bfloat162float(hh));
    }
    {
        bf16 hh = __float2bfloat16(ka);
        kh[ro] = hh; kl[ro] = __float2bfloat16(ka - __bfloat162float(hh));
        hh = __float2bfloat16(kb);
        kh[ro + 1] = hh; kl[ro + 1] = __float2bfloat16(kb - __bfloat162float(hh));
    }
    {
        size_t vo = (bh * 64 + 2 * (size_t)i) * S_LEN + s;
        bf16 hh = __float2bfloat16(v1);
        vth[vo] = hh; vtl[vo] = __float2bfloat16(v1 - __bfloat162float(hh));
        hh = __float2bfloat16(v2);
        vth[vo + S_LEN] = hh; vtl[vo + S_LEN] = __float2bfloat16(v2 - __bfloat162float(hh));
    }
}

// ---------------- FA2-style tensor-core masked flash ----------------------------
// 128 q-rows x 1 head, 256 threads (8 warps, warp w owns rows 16w..16w+15).
// Q in registers (Qh/Ql frags), P in registers (accumulator->A-operand identity),
// K/V as h/l split tiles (64x64 each, stride 72 bf16). Double-buffered.
// QK = QhKh + QlKh + QhKl ; PV = PhVh + PlVh + PhVl (same terms as x3).
#define KSTR   72                 // bf16 per smem row (144 B; 36 = 4 mod 32: CF)
#define KSTRB  144
#define KTILE  (64 * KSTR)        // bf16 per 64-row tile (9216)
#define FSMEM3 (8 * KTILE * 2)    // 2 buffers x 4 tiles = 73728 bytes

__device__ __forceinline__ uint32_t pack_bf2(bf16 a, bf16 b) {
    return (uint32_t)__bfloat16_as_ushort(a) |
           ((uint32_t)__bfloat16_as_ushort(b) << 16);
}

__global__ __launch_bounds__(256) void flash_mma3(
    const bf16* __restrict__ qh, const bf16* __restrict__ ql,
    const bf16* __restrict__ kh, const bf16* __restrict__ kl,
    const bf16* __restrict__ vth, const bf16* __restrict__ vtl,
    const unsigned* __restrict__ mask, float* __restrict__ attn)
{
    extern __shared__ __align__(16) bf16 sm[];
    const int tid  = threadIdx.x;
    const int warp = tid >> 5, lane = tid & 31;
    const int qt = gridDim.x - 1 - blockIdx.x;   // largest-work-first
    const int h = blockIdx.y, b = blockIdx.z;

    const uint32_t sbase = (uint32_t)__cvta_generic_to_shared(sm);

    const size_t bh = (size_t)b * N_HEADS + h;
    const bf16* qhg  = qh  + (bh * S_LEN + (size_t)qt * 128) * 64;
    const bf16* qlg  = ql  + (bh * S_LEN + (size_t)qt * 128) * 64;
    const bf16* khg  = kh  + bh * S_LEN * 64;
    const bf16* klg  = kl  + bh * S_LEN * 64;
    const bf16* vthg = vth + bh * 64 * (size_t)S_LEN;
    const bf16* vtlg = vtl + bh * 64 * (size_t)S_LEN;

    // stage Q (h,l) into buffer-1 region (overwritten by K/V tile 1 later)
    const uint32_t QHS = sbase + (4 * KTILE) * 2;      // 128 rows x 144B
    const uint32_t QLS = sbase + (6 * KTILE) * 2;
    for (int c = tid; c < 2048; c += 256) {
        if (c < 1024) {
            int row = c >> 3, ch = c & 7;
            CP16(QHS + row * KSTRB + ch * 16, qhg + (size_t)row * 64 + ch * 8);
        } else {
            int cc = c - 1024;
            int row = cc >> 3, ch = cc & 7;
            CP16(QLS + row * KSTRB + ch * 16, qlg + (size_t)row * 64 + ch * 8);
        }
    }
    CPCOMMIT();

    // K/V tile 0 into buffer 0
    for (int c = tid; c < 2048; c += 256) {
        int q4 = c >> 9, idx = c & 511;
        int row = idx >> 3, ch = idx & 7;
        uint32_t dst = sbase + (uint32_t)q4 * (KTILE * 2) + row * KSTRB + ch * 16;
        const bf16* src;
        if      (q4 == 0) src = khg  + (size_t)row * 64 + ch * 8;
        else if (q4 == 1) src = klg  + (size_t)row * 64 + ch * 8;
        else if (q4 == 2) src = vthg + (size_t)row * S_LEN + ch * 8;
        else              src = vtlg + (size_t)row * S_LEN + ch * 8;
        CP16(dst, src);
    }
    CPCOMMIT();
    CPWAIT0();
    __syncthreads();

    // Q fragments to registers
    uint32_t aQh[4][4], aQl[4][4];
    const uint32_t qro = (uint32_t)((warp * 16 + (lane & 15)) * KSTRB + ((lane >> 4) << 3) * 2);
#pragma unroll
    for (int ks = 0; ks < 4; ks++) {
        ldsm_x4(aQh[ks], QHS + qro + ks * 32);
        ldsm_x4(aQl[ks], QLS + qro + ks * 32);
    }
    __syncthreads();   // all warps done reading Q before buf1 overwrite

    float O[8][4];
#pragma unroll
    for (int i = 0; i < 8; i++)
#pragma unroll
        for (int j = 0; j < 4; j++) O[i][j] = 0.f;
    float m0 = -1e30f, m1 = -1e30f, l0 = 0.f, l1 = 0.f;

    const int r0 = warp * 16 + (lane >> 2);
    const int q0 = qt * 128 + r0, q1 = q0 + 8;
    const unsigned* mrow0 = mask + ((size_t)b * S_LEN + q0) * 64;
    const unsigned* mrow1 = mask + ((size_t)b * S_LEN + q1) * 64;

    const int browo = (lane & 7) + ((lane >> 4) << 3);
    const uint32_t bcol = (uint32_t)((((lane >> 3) & 1) << 3) * 2);

    const int ktmax = 2 * qt + 1;

    for (int kt = 0; kt <= ktmax; kt++) {
        const int buf = kt & 1;
        if (kt < ktmax) {
            const uint32_t dbase = sbase + (uint32_t)(buf ^ 1) * (4 * KTILE * 2);
            const size_t kro = (size_t)(kt + 1) * 64;
            for (int c = tid; c < 2048; c += 256) {
                int q4 = c >> 9, idx = c & 511;
                int row = idx >> 3, ch = idx & 7;
                uint32_t dst = dbase + (uint32_t)q4 * (KTILE * 2) + row * KSTRB + ch * 16;
                const bf16* src;
                if      (q4 == 0) src = khg  + (kro + row) * 64 + ch * 8;
                else if (q4 == 1) src = klg  + (kro + row) * 64 + ch * 8;
                else if (q4 == 2) src = vthg + (size_t)row * S_LEN + kro + ch * 8;
                else              src = vtlg + (size_t)row * S_LEN + kro + ch * 8;
                CP16(dst, src);
            }
            CPCOMMIT();
            CPWAIT1();
        } else {
            CPWAIT0();
        }
        __syncthreads();

        const uint32_t tb  = sbase + (uint32_t)buf * (4 * KTILE * 2);
        const uint32_t sKh = tb;
        const uint32_t sKl = tb + KTILE * 2;
        const uint32_t sVh = tb + 2 * KTILE * 2;
        const uint32_t sVl = tb + 3 * KTILE * 2;

        // S = QhKh + QlKh + QhKl
        float S_[8][4];
#pragma unroll
        for (int i = 0; i < 8; i++)
#pragma unroll
            for (int j = 0; j < 4; j++) S_[i][j] = 0.f;

#pragma unroll
        for (int ks = 0; ks < 4; ks++) {
#pragma unroll
            for (int nt2 = 0; nt2 < 4; nt2++) {
                const uint32_t ro = (uint32_t)((nt2 * 16 + browo) * KSTRB) + bcol + ks * 32;
                uint32_t bb[4];
                ldsm_x4(bb, sKh + ro);
                mma16816(S_[nt2 * 2],     aQh[ks], bb);
                mma16816(S_[nt2 * 2 + 1], aQh[ks], bb + 2);
                mma16816(S_[nt2 * 2],     aQl[ks], bb);
                mma16816(S_[nt2 * 2 + 1], aQl[ks], bb + 2);
                ldsm_x4(bb, sKl + ro);
                mma16816(S_[nt2 * 2],     aQh[ks], bb);
                mma16816(S_[nt2 * 2 + 1], aQh[ks], bb + 2);
            }
        }

        // mask + online softmax (identical structure to validated kernel)
        const unsigned mw00 = mrow0[kt * 2], mw01 = mrow0[kt * 2 + 1];
        const unsigned mw10 = mrow1[kt * 2], mw11 = mrow1[kt * 2 + 1];
        float mx0 = -1e30f, mx1 = -1e30f;
#pragma unroll
        for (int nf = 0; nf < 8; nf++) {
            int c = nf * 8 + 2 * (lane & 3);
#pragma unroll
            for (int e = 0; e < 2; e++) {
                int cc = c + e;
                unsigned w0 = (cc < 32 ? mw00 : mw01) >> (cc & 31);
                unsigned w1 = (cc < 32 ? mw10 : mw11) >> (cc & 31);
                float v0 = (w0 & 1u) ? S_[nf][e] * 0.125f     : -1e30f;
                float v1 = (w1 & 1u) ? S_[nf][e + 2] * 0.125f : -1e30f;
                S_[nf][e] = v0; S_[nf][e + 2] = v1;
                mx0 = fmaxf(mx0, v0); mx1 = fmaxf(mx1, v1);
            }
        }
        mx0 = fmaxf(mx0, __shfl_xor_sync(0xffffffffu, mx0, 1));
        mx0 = fmaxf(mx0, __shfl_xor_sync(0xffffffffu, mx0, 2));
        mx1 = fmaxf(mx1, __shfl_xor_sync(0xffffffffu, mx1, 1));
        mx1 = fmaxf(mx1, __shfl_xor_sync(0xffffffffu, mx1, 2));
        float mn0 = fmaxf(m0, mx0), mn1 = fmaxf(m1, mx1);
        float c0 = __expf(m0 - mn0), c1 = __expf(m1 - mn1);
        float ls0 = 0.f, ls1 = 0.f;
#pragma unroll
        for (int nf = 0; nf < 8; nf++) {
#pragma unroll
            for (int e = 0; e < 2; e++) {
                float p0 = (S_[nf][e]     > -1e29f) ? __expf(S_[nf][e]     - mn0) : 0.f;
                float p1 = (S_[nf][e + 2] > -1e29f) ? __expf(S_[nf][e + 2] - mn1) : 0.f;
                S_[nf][e] = p0; S_[nf][e + 2] = p1;
                ls0 += p0; ls1 += p1;
            }
        }
        ls0 += __shfl_xor_sync(0xffffffffu, ls0, 1);
        ls0 += __shfl_xor_sync(0xffffffffu, ls0, 2);
        ls1 += __shfl_xor_sync(0xffffffffu, ls1, 1);
        ls1 += __shfl_xor_sync(0xffffffffu, ls1, 2);
        l0 = l0 * c0 + ls0; l1 = l1 * c1 + ls1;
        m0 = mn0; m1 = mn1;
#pragma unroll
        for (int nf = 0; nf < 8; nf++) {
            O[nf][0] *= c0; O[nf][1] *= c0;
            O[nf][2] *= c1; O[nf][3] *= c1;
        }

        // P fragments in registers (accumulator layout == A-operand layout)
        uint32_t aPh[4][4], aPl[4][4];
#pragma unroll
        for (int ks = 0; ks < 4; ks++) {
#pragma unroll
            for (int half = 0; half < 2; half++) {
                const float* Sf = S_[2 * ks + half];
                bf16 h0 = __float2bfloat16(Sf[0]);
                bf16 l0b = __float2bfloat16(Sf[0] - __bfloat162float(h0));
                bf16 h1 = __float2bfloat16(Sf[1]);
                bf16 l1b = __float2bfloat16(Sf[1] - __bfloat162float(h1));
                bf16 h2 = __float2bfloat16(Sf[2]);
                bf16 l2b = __float2bfloat16(Sf[2] - __bfloat162float(h2));
                bf16 h3 = __float2bfloat16(Sf[3]);
                bf16 l3b = __float2bfloat16(Sf[3] - __bfloat162float(h3));
                aPh[ks][half * 2]     = pack_bf2(h0, h1);
                aPh[ks][half * 2 + 1] = pack_bf2(h2, h3);
                aPl[ks][half * 2]     = pack_bf2(l0b, l1b);
                aPl[ks][half * 2 + 1] = pack_bf2(l2b, l3b);
            }
        }

        // O += PhVh + PlVh + PhVl
#pragma unroll
        for (int ks = 0; ks < 4; ks++) {
#pragma unroll
            for (int nt2 = 0; nt2 < 4; nt2++) {
                const uint32_t ro = (uint32_t)((nt2 * 16 + browo) * KSTRB) + bcol + ks * 32;
                uint32_t bb[4];
                ldsm_x4(bb, sVh + ro);
                mma16816(O[nt2 * 2],     aPh[ks], bb);
                mma16816(O[nt2 * 2 + 1], aPh[ks], bb + 2);
                mma16816(O[nt2 * 2],     aPl[ks], bb);
                mma16816(O[nt2 * 2 + 1], aPl[ks], bb + 2);
                ldsm_x4(bb, sVl + ro);
                mma16816(O[nt2 * 2],     aPh[ks], bb);
                mma16816(O[nt2 * 2 + 1], aPh[ks], bb + 2);
            }
        }
        __syncthreads();   // all warps done with this buffer before next prefetch
    }

    float inv0 = 1.0f / l0, inv1 = 1.0f / l1;
    float* out0 = attn + ((size_t)b * S_LEN + q0) * D_MODEL + h * 64;
    float* out1 = attn + ((size_t)b * S_LEN + q1) * D_MODEL + h * 64;
#pragma unroll
    for (int nf = 0; nf < 8; nf++) {
        int c = nf * 8 + 2 * (lane & 3);
        *(float2*)(out0 + c) = make_float2(O[nf][0] * inv0, O[nf][1] * inv0);
        *(float2*)(out1 + c) = make_float2(O[nf][2] * inv1, O[nf][3] * inv1);
    }
}

// ---------------- launcher with fork/join stream overlap -------------------------
extern "C" void kernel_launch(void* const* d_in, const int* in_sizes, int n_in,
                              void* d_out, int out_size)
{
    static cudaStream_t s_sel = nullptr;
    static cudaEvent_t  ev_fork = nullptr, ev_join = nullptr;
    if (!s_sel) {
        cudaStreamCreateWithFlags(&s_sel, cudaStreamNonBlocking);
        cudaEventCreateWithFlags(&ev_fork, cudaEventDisableTiming);
        cudaEventCreateWithFlags(&ev_join, cudaEventDisableTiming);
    }

    const float* x    = nullptr;
    const float* Wqkv = nullptr;
    const float* Wo   = nullptr;
    const float* Wiq  = nullptr;
    const float* Wik  = nullptr;
    const int*   topk = nullptr;
    for (int i = 0; i < n_in; i++) {
        int sz = in_sizes[i];
        if      (sz == D_MODEL * 3 * D_MODEL)       Wqkv = (const float*)d_in[i];
        else if (sz == D_MODEL * D_MODEL)           Wo   = (const float*)d_in[i];
        else if (sz == D_MODEL * IDX_D) { if (!Wiq) Wiq  = (const float*)d_in[i];
                                          else      Wik  = (const float*)d_in[i]; }
        else if (sz <= 4)                           topk = (const int*)d_in[i];
        else                                        x    = (const float*)d_in[i];
    }

    const int BS = out_size / D_MODEL;
    const int Bn = BS / S_LEN;

    float *qkv, *iq, *ik, *attn; unsigned* mask;
    bf16 *x3, *attn3, *wqkv3, *wo3, *qh, *ql, *kh, *kl, *vth, *vtl;
    cudaGetSymbolAddress((void**)&qkv,   g_qkv);
    cudaGetSymbolAddress((void**)&iq,    g_iq);
    cudaGetSymbolAddress((void**)&ik,    g_ik);
    cudaGetSymbolAddress((void**)&attn,  g_attn);
    cudaGetSymbolAddress((void**)&mask,  g_mask);
    cudaGetSymbolAddress((void**)&x3,    g_x3);
    cudaGetSymbolAddress((void**)&attn3, g_attn3);
    cudaGetSymbolAddress((void**)&wqkv3, g_wqkv3);
    cudaGetSymbolAddress((void**)&wo3,   g_wo3);
    cudaGetSymbolAddress((void**)&qh,    g_qh);
    cudaGetSymbolAddress((void**)&ql,    g_ql);
    cudaGetSymbolAddress((void**)&kh,    g_kh);
    cudaGetSymbolAddress((void**)&kl,    g_kl);
    cudaGetSymbolAddress((void**)&vth,   g_vth);
    cudaGetSymbolAddress((void**)&vtl,   g_vtl);

    const int K3 = 3 * D_MODEL;
    const int TOPK_SMEM = (8 * 256 + 8 * 2048 + 8 * 256) * 4;

    cudaFuncSetAttribute(mma_gemm, cudaFuncAttributeMaxDynamicSharedMemorySize, GEMM_SMEM);
    cudaFuncSetAttribute(topk8_kernel, cudaFuncAttributeMaxDynamicSharedMemorySize, TOPK_SMEM);
    cudaFuncSetAttribute(flash_mma3, cudaFuncAttributeMaxDynamicSharedMemorySize, FSMEM3);

    // ---- fork: selection chain on s_sel ----
    cudaEventRecord(ev_fork, 0);
    cudaStreamWaitEvent(s_sel, ev_fork, 0);
    sgemm_nn2<<<dim3(IDX_D / 128, BS / 128, 2), 256, 0, s_sel>>>(
        x, Wiq, iq, Wik, ik, BS, IDX_D, D_MODEL);
    topk8_kernel<<<BS / 8, 256, TOPK_SMEM, s_sel>>>(iq, ik, topk, mask);
    cudaEventRecord(ev_join, s_sel);

    // ---- smooth chain on the main (capture) stream ----
    split_a<<<(BS * D_MODEL + 255) / 256, 256>>>(x, x3, BS * D_MODEL);
    {
        dim3 blk(32, 8);
        split_bT<<<dim3(3 * D_MODEL / 32, D_MODEL / 32), blk>>>(Wqkv, wqkv3, D_MODEL, 3 * D_MODEL);
        split_bT<<<dim3(D_MODEL / 32, D_MODEL / 32), blk>>>(Wo, wo3, D_MODEL, D_MODEL);
    }
    mma_gemm<<<dim3(3 * D_MODEL / BNg, BS / BMg), 256, GEMM_SMEM>>>(
        x3, wqkv3, qkv, BS, 3 * D_MODEL, K3);
    prep_flash_rope<<<(BS * 512 + 255) / 256, 256>>>(qkv, qh, ql, kh, kl, vth, vtl, BS);

    // ---- join: flash needs the mask ----
    cudaStreamWaitEvent(0, ev_join, 0);
    flash_mma3<<<dim3(S_LEN / 128, N_HEADS, Bn), 256, FSMEM3>>>(
        qh, ql, kh, kl, vth, vtl, mask, attn);

    // output projection
    split_a<<<(BS * D_MODEL + 255) / 256, 256>>>(attn, attn3, BS * D_MODEL);
    mma_gemm<<<dim3(D_MODEL / BNg, BS / BMg), 256, GEMM_SMEM>>>(
        attn3, wo3, (float*)d_out, BS, D_MODEL, K3);
}